// round 1
// baseline (speedup 1.0000x reference)
#include <cuda_runtime.h>
#include <math.h>

#define Bn  128
#define Ln  577
#define Dn  768
#define NPn 1024
#define EPSF 1e-8f

// ---------------- device scratch (allocation-free rule: __device__ globals) ----
__device__ float g_S[(size_t)Bn * Ln * NPn];   // raw dots, later overwritten by softmax probs
__device__ float g_inv[Bn * Ln];               // 1 / max(rownorm, eps)
__device__ float g_qn[NPn];                    // ||np_n||
__device__ float g_num[Bn * NPn];              // q . wctx
__device__ float g_wn2[Bn * NPn];              // ||wctx||^2 accumulators
__device__ float g_ct[Bn * Bn];                // image-text logits (raw dot)
__device__ float g_npc[Bn * NPn];              // image-np logits (raw dot)
__device__ float g_acc;                        // total loss accumulator
__device__ int   g_idx64;                      // 1 if indices buffer is int64

__device__ __forceinline__ float lk(float x) { return x >= 0.f ? x : 0.1f * x; }
__device__ __forceinline__ float logsig(float x) {
    return fminf(x, 0.f) - log1pf(expf(-fabsf(x)));
}

// ---------------- init: zero accumulators, detect index dtype -----------------
__global__ void k_init(const int* __restrict__ idxr) {
    int gid = blockIdx.x * 256 + threadIdx.x;
    if (gid < Bn * NPn) g_wn2[gid] = 0.f;
    if (gid == 0) {
        g_acc = 0.f;
        int any = 0;
        // safe in both layouts: int32 buffer has 1024 words, int64 has 2048.
        for (int i = 1; i < 1024; i += 2) any |= idxr[i];
        g_idx64 = (any == 0) ? 1 : 0;
    }
}

__device__ __forceinline__ int get_idx(const int* __restrict__ r, int n) {
    return g_idx64 ? r[2 * n] : r[n];
}

// ---------------- ||q_n|| ------------------------------------------------------
__global__ void k_qnorm(const float* __restrict__ npf) {
    int n = blockIdx.x;
    float s = 0.f;
    for (int d = threadIdx.x; d < Dn; d += 256) {
        float v = npf[(size_t)n * Dn + d];
        s += v * v;
    }
    __shared__ float sh[256];
    sh[threadIdx.x] = s; __syncthreads();
    for (int o = 128; o > 0; o >>= 1) {
        if (threadIdx.x < o) sh[threadIdx.x] += sh[threadIdx.x + o];
        __syncthreads();
    }
    if (threadIdx.x == 0) g_qn[n] = sqrtf(sh[0]);
}

// ---------------- generic NT GEMM: C[m,n] = sum_k A[m,k]*B[n,k] ----------------
// BM=BN=128, BK=16, 256 threads, 8x8 per thread. dst: 0=g_ct 1=g_npc 2=g_S
__global__ __launch_bounds__(256) void k_gemm_nt(
    const float* __restrict__ A, const float* __restrict__ Bm,
    int M, int N, int K, size_t sA, size_t sC, int dst)
{
    float* C = (dst == 0) ? g_ct : (dst == 1) ? g_npc : g_S;
    int bz = blockIdx.z;
    A += (size_t)bz * sA;
    C += (size_t)bz * sC;

    __shared__ float As[16][132];
    __shared__ float Bs[16][132];
    const int tid = threadIdx.x;
    const int tx = tid & 15, ty = tid >> 4;
    const int m0 = blockIdx.y * 128, n0 = blockIdx.x * 128;

    float acc[8][8];
#pragma unroll
    for (int r = 0; r < 8; r++)
#pragma unroll
        for (int c = 0; c < 8; c++) acc[r][c] = 0.f;

    for (int k0 = 0; k0 < K; k0 += 16) {
#pragma unroll
        for (int i = 0; i < 8; i++) {
            int e = tid + i * 256;
            int mm = e >> 4, kk = e & 15;
            int gm = m0 + mm;
            As[kk][mm] = (gm < M) ? A[(size_t)gm * K + k0 + kk] : 0.f;
        }
#pragma unroll
        for (int i = 0; i < 8; i++) {
            int e = tid + i * 256;
            int nn = e >> 4, kk = e & 15;
            int gn = n0 + nn;
            Bs[kk][nn] = (gn < N) ? Bm[(size_t)gn * K + k0 + kk] : 0.f;
        }
        __syncthreads();
#pragma unroll
        for (int k = 0; k < 16; k++) {
            float4 a0 = *(const float4*)&As[k][ty * 8];
            float4 a1 = *(const float4*)&As[k][ty * 8 + 4];
            float4 b0 = *(const float4*)&Bs[k][tx * 8];
            float4 b1 = *(const float4*)&Bs[k][tx * 8 + 4];
            float av[8] = {a0.x, a0.y, a0.z, a0.w, a1.x, a1.y, a1.z, a1.w};
            float bv[8] = {b0.x, b0.y, b0.z, b0.w, b1.x, b1.y, b1.z, b1.w};
#pragma unroll
            for (int r = 0; r < 8; r++)
#pragma unroll
                for (int c = 0; c < 8; c++) acc[r][c] += av[r] * bv[c];
        }
        __syncthreads();
    }
#pragma unroll
    for (int r = 0; r < 8; r++) {
        int gm = m0 + ty * 8 + r;
        if (gm >= M) continue;
#pragma unroll
        for (int c = 0; c < 8; c++) {
            int gn = n0 + tx * 8 + c;
            if (gn < N) C[(size_t)gm * N + gn] = acc[r][c];
        }
    }
}

// ---------------- per-(b,l) L2 norm over n -------------------------------------
__global__ void k_rownorm() {
    size_t row = blockIdx.x;                       // 0 .. B*L-1
    const float4* p = (const float4*)(g_S + row * NPn);
    float4 v = p[threadIdx.x];                     // 256 * 4 = 1024
    float a = lk(v.x), b = lk(v.y), c = lk(v.z), d = lk(v.w);
    float s = a * a + b * b + c * c + d * d;
    __shared__ float sh[256];
    sh[threadIdx.x] = s; __syncthreads();
    for (int o = 128; o > 0; o >>= 1) {
        if (threadIdx.x < o) sh[threadIdx.x] += sh[threadIdx.x + o];
        __syncthreads();
    }
    if (threadIdx.x == 0) g_inv[row] = 1.f / fmaxf(sqrtf(sh[0]), EPSF);
}

// ---------------- per-(b,n) softmax over l; P overwrites S; num = p . raw ------
__global__ void k_softmax() {
    int b = blockIdx.y;
    int n = blockIdx.x * 256 + threadIdx.x;
    __shared__ float sinv[Ln];
    for (int j = threadIdx.x; j < Ln; j += 256) sinv[j] = g_inv[b * Ln + j];
    __syncthreads();

    size_t base = (size_t)b * Ln * NPn + n;
    float m = -3.4e38f, s = 0.f;
    for (int l = 0; l < Ln; l++) {
        float raw = g_S[base + (size_t)l * NPn];
        float v = lk(raw) * sinv[l] * 4.0f;
        if (v > m) { s = s * expf(m - v) + 1.f; m = v; }
        else       { s += expf(v - m); }
    }
    float inv_s = 1.f / s;
    float num = 0.f;
    for (int l = 0; l < Ln; l++) {
        size_t idx = base + (size_t)l * NPn;
        float raw = g_S[idx];
        float v = lk(raw) * sinv[l] * 4.0f;
        float pl = expf(v - m) * inv_s;
        g_S[idx] = pl;
        num += pl * raw;
    }
    g_num[(size_t)b * NPn + n] = num;
}

// ---------------- GEMM2 (TN): wctx = P^T-layout @ tokens; fused ||wctx||^2 -----
// A: P stored [L][NP] (K-major).  B: tokens [L][D] (K-major).  M=NP, N=D, K=L
__global__ __launch_bounds__(256) void k_gemm2(const float* __restrict__ T) {
    int b = blockIdx.z;
    const float* P  = g_S + (size_t)b * Ln * NPn;
    const float* Tb = T   + (size_t)b * Ln * Dn;
    const int m0 = blockIdx.y * 128;   // NP tile
    const int n0 = blockIdx.x * 128;   // D tile

    __shared__ float As[16][132];
    __shared__ float Bs[16][132];
    const int tid = threadIdx.x;
    const int tx = tid & 15, ty = tid >> 4;

    float acc[8][8];
#pragma unroll
    for (int r = 0; r < 8; r++)
#pragma unroll
        for (int c = 0; c < 8; c++) acc[r][c] = 0.f;

    for (int k0 = 0; k0 < Ln; k0 += 16) {
#pragma unroll
        for (int i = 0; i < 8; i++) {
            int e = tid + i * 256;
            int kk = e >> 7, mm = e & 127;
            int gk = k0 + kk;
            As[kk][mm] = (gk < Ln) ? P[(size_t)gk * NPn + m0 + mm] : 0.f;
            Bs[kk][mm] = (gk < Ln) ? Tb[(size_t)gk * Dn + n0 + mm] : 0.f;
        }
        __syncthreads();
#pragma unroll
        for (int k = 0; k < 16; k++) {
            float4 a0 = *(const float4*)&As[k][ty * 8];
            float4 a1 = *(const float4*)&As[k][ty * 8 + 4];
            float4 b0 = *(const float4*)&Bs[k][tx * 8];
            float4 b1 = *(const float4*)&Bs[k][tx * 8 + 4];
            float av[8] = {a0.x, a0.y, a0.z, a0.w, a1.x, a1.y, a1.z, a1.w};
            float bv[8] = {b0.x, b0.y, b0.z, b0.w, b1.x, b1.y, b1.z, b1.w};
#pragma unroll
            for (int r = 0; r < 8; r++)
#pragma unroll
                for (int c = 0; c < 8; c++) acc[r][c] += av[r] * bv[c];
        }
        __syncthreads();
    }
    // fused epilogue: sum of squares over D for each NP row
    float rs[8];
#pragma unroll
    for (int r = 0; r < 8; r++) {
        rs[r] = 0.f;
#pragma unroll
        for (int c = 0; c < 8; c++) rs[r] += acc[r][c] * acc[r][c];
    }
#pragma unroll
    for (int off = 8; off > 0; off >>= 1)
#pragma unroll
        for (int r = 0; r < 8; r++)
            rs[r] += __shfl_xor_sync(0xffffffffu, rs[r], off);
    if (tx == 0) {
#pragma unroll
        for (int r = 0; r < 8; r++)
            atomicAdd(&g_wn2[(size_t)b * NPn + m0 + ty * 8 + r], rs[r]);
    }
}

// ---------------- loss reductions ----------------------------------------------
__device__ __forceinline__ void block_acc(float t, float w) {
    __shared__ float sh[256];
    sh[threadIdx.x] = t; __syncthreads();
    for (int o = 128; o > 0; o >>= 1) {
        if (threadIdx.x < o) sh[threadIdx.x] += sh[threadIdx.x + o];
        __syncthreads();
    }
    if (threadIdx.x == 0) atomicAdd(&g_acc, sh[0] * w);
}

__global__ void k_loss_ct(const float* sc, const float* bi) {
    int gid = blockIdx.x * 256 + threadIdx.x;      // 16384
    float t = 0.f;
    if (gid < Bn * Bn) {
        int i = gid >> 7, j = gid & 127;
        float lg = g_ct[gid] * sc[0] + bi[0];
        float lab = (i == j) ? 1.f : -1.f;
        t = -logsig(lab * lg);
    }
    block_acc(t, 1.0f / Bn);
}

__global__ void k_loss_npc(const float* sc, const float* bi, const int* __restrict__ idxr) {
    int gid = blockIdx.x * 256 + threadIdx.x;      // 131072
    float t = 0.f;
    if (gid < Bn * NPn) {
        int b = gid >> 10, n = gid & 1023;
        float lab = (get_idx(idxr, n) == b) ? 1.f : -1.f;
        float lg = g_npc[gid] * sc[0] + bi[0];
        t = -logsig(lab * lg);
    }
    block_acc(t, 1.0f / NPn);
}

__global__ void k_loss_xac(const float* sc, const float* bi, const int* __restrict__ idxr) {
    int gid = blockIdx.x * 256 + threadIdx.x;      // 131072
    float t = 0.f;
    if (gid < Bn * NPn) {
        int b = gid >> 10, n = gid & 1023;
        float wn = sqrtf(g_wn2[gid]);
        float den = fmaxf(g_qn[n] * wn, EPSF);
        float sim = g_num[gid] / den;
        float lg = sim * sc[0] + bi[0];
        float lab = (get_idx(idxr, n) == b) ? 1.f : -1.f;
        t = -logsig(lab * lg);
    }
    block_acc(t, 0.01f / NPn);
}

__global__ void k_final(float* out) { out[0] = g_acc; }

// ---------------- launch ---------------------------------------------------------
extern "C" void kernel_launch(void* const* d_in, const int* in_sizes, int n_in,
                              void* d_out, int out_size) {
    const float* img = (const float*)d_in[0];
    const float* txt = (const float*)d_in[1];
    const float* sc  = (const float*)d_in[2];
    const float* bi  = (const float*)d_in[3];
    const float* npf = (const float*)d_in[4];
    const int*   idx = (const int*)d_in[5];
    const float* tok = (const float*)d_in[6];
    float* out = (float*)d_out;

    k_init<<<512, 256>>>(idx);
    k_qnorm<<<NPn, 256>>>(npf);

    // contrastive logits: [128,128] = img @ txt^T
    k_gemm_nt<<<dim3(1, 1, 1), 256>>>(img, txt, Bn, Bn, Dn, 0, 0, 0);
    // npc logits: [128,1024] = img @ npf^T
    k_gemm_nt<<<dim3(8, 1, 1), 256>>>(img, npf, Bn, NPn, Dn, 0, 0, 1);
    // S[b,l,n] = tokens[b] @ npf^T  (batched over b)
    k_gemm_nt<<<dim3(8, 5, Bn), 256>>>(tok, npf, Ln, NPn, Dn,
                                       (size_t)Ln * Dn, (size_t)Ln * NPn, 2);

    k_rownorm<<<Bn * Ln, 256>>>();
    k_softmax<<<dim3(NPn / 256, Bn), 256>>>();
    k_gemm2<<<dim3(Dn / 128, NPn / 128, Bn), 256>>>(tok);

    k_loss_ct<<<64, 256>>>(sc, bi);
    k_loss_npc<<<512, 256>>>(sc, bi, idx);
    k_loss_xac<<<512, 256>>>(sc, bi, idx);
    k_final<<<1, 1>>>(out);
}

// round 3
// speedup vs baseline: 4.7143x; 4.7143x over previous
#include <cuda_runtime.h>
#include <cuda_bf16.h>
#include <math.h>
#include <stdint.h>

#define Bn  128
#define Ln  577
#define LP  640
#define Dn  768
#define NPn 1024
#define EPSF 1e-8f
#define SMEM_DYN 65536

// ---------------- device scratch ----------------
__device__ float         g_S  [(size_t)Bn*Ln*NPn];
__device__ __nv_bfloat16 g_P  [(size_t)Bn*Ln*NPn];
__device__ __nv_bfloat16 g_Pt [(size_t)Bn*NPn*LP];
__device__ __nv_bfloat16 g_Tt [(size_t)Bn*Dn*LP];
__device__ __nv_bfloat16 g_tok[(size_t)Bn*Ln*Dn];
__device__ __nv_bfloat16 g_npf[NPn*Dn];
__device__ __nv_bfloat16 g_img[Bn*Dn];
__device__ __nv_bfloat16 g_txt[Bn*Dn];
__device__ float g_norm2[Bn*Ln];
__device__ float g_inv  [Bn*Ln];
__device__ float g_qn   [NPn];
__device__ float g_num  [Bn*NPn];
__device__ float g_wn2  [Bn*NPn];
__device__ float g_ct   [Bn*Bn];
__device__ float g_npc  [Bn*NPn];
__device__ float g_acc;
__device__ int   g_idx64;

__device__ __forceinline__ float lk(float x) { return x >= 0.f ? x : 0.1f * x; }
__device__ __forceinline__ float logsig(float x) {
    return fminf(x, 0.f) - log1pf(expf(-fabsf(x)));
}
__device__ __forceinline__ uint32_t s2u(const void* p) {
    uint32_t a;
    asm("{ .reg .u64 t; cvta.to.shared.u64 t, %1; cvt.u32.u64 %0, t; }" : "=r"(a) : "l"(p));
    return a;
}

// ---------------- cp.async tile loader: 128 rows x 64 bf16, SW128 swizzle -----
__device__ __forceinline__ void cpa_tile(uint32_t dst, const __nv_bfloat16* __restrict__ src,
                                         int row0, int row_lim, size_t stride, int k0, int tid) {
#pragma unroll
    for (int i = 0; i < 4; i++) {
        int e = tid + (i << 8);
        int r = e >> 3, c = e & 7;
        int gr = row0 + r;
        int sz = 16;
        if (gr >= row_lim) { gr = row_lim - 1; sz = 0; }
        const void* gp = (const void*)(src + (size_t)gr * stride + k0 + (c << 3));
        uint32_t off = (uint32_t)((r << 7) + (c << 4));
        off ^= (off >> 3) & 0x70;
        asm volatile("cp.async.cg.shared.global [%0], [%1], 16, %2;"
                     :: "r"(dst + off), "l"(gp), "r"(sz) : "memory");
    }
}
#define CPA_COMMIT() asm volatile("cp.async.commit_group;" ::: "memory")
#define CPA_WAIT()   asm volatile("cp.async.wait_group 0;" ::: "memory")

// ---------------- warp MMA over one 128x128x64 SMEM chunk ----------------------
__device__ __forceinline__ void mma_compute(uint32_t aBase, uint32_t bBase,
                                            int lane, int warpM, int warpN,
                                            float (&acc)[4][4][4]) {
#pragma unroll
    for (int ks = 0; ks < 4; ks++) {
        uint32_t a[4][4];
#pragma unroll
        for (int mb = 0; mb < 4; mb++) {
            int row = warpM * 64 + mb * 16 + (lane & 15);
            uint32_t byte = (uint32_t)(ks * 32 + ((lane >> 4) << 4));
            uint32_t off = (uint32_t)(row << 7) + byte;
            off ^= (off >> 3) & 0x70;
            asm volatile("ldmatrix.sync.aligned.m8n8.x4.shared.b16 {%0,%1,%2,%3}, [%4];"
                         : "=r"(a[mb][0]), "=r"(a[mb][1]), "=r"(a[mb][2]), "=r"(a[mb][3])
                         : "r"(aBase + off));
        }
        uint32_t b[4][2];
#pragma unroll
        for (int nb2 = 0; nb2 < 2; nb2++) {
            int row = warpN * 32 + nb2 * 16 + (lane & 7) + ((lane >> 4) << 3);
            uint32_t byte = (uint32_t)(ks * 32 + ((lane & 8) ? 16 : 0));
            uint32_t off = (uint32_t)(row << 7) + byte;
            off ^= (off >> 3) & 0x70;
            uint32_t r0, r1, r2, r3;
            asm volatile("ldmatrix.sync.aligned.m8n8.x4.shared.b16 {%0,%1,%2,%3}, [%4];"
                         : "=r"(r0), "=r"(r1), "=r"(r2), "=r"(r3)
                         : "r"(bBase + off));
            b[nb2 * 2][0] = r0; b[nb2 * 2][1] = r1;
            b[nb2 * 2 + 1][0] = r2; b[nb2 * 2 + 1][1] = r3;
        }
#pragma unroll
        for (int mb = 0; mb < 4; mb++)
#pragma unroll
            for (int nb = 0; nb < 4; nb++)
                asm volatile(
                    "mma.sync.aligned.m16n8k16.row.col.f32.bf16.bf16.f32 "
                    "{%0,%1,%2,%3},{%4,%5,%6,%7},{%8,%9},{%0,%1,%2,%3};"
                    : "+f"(acc[mb][nb][0]), "+f"(acc[mb][nb][1]),
                      "+f"(acc[mb][nb][2]), "+f"(acc[mb][nb][3])
                    : "r"(a[mb][0]), "r"(a[mb][1]), "r"(a[mb][2]), "r"(a[mb][3]),
                      "r"(b[nb][0]), "r"(b[nb][1]));
    }
}

// ---------------- shared mainloop ------------------------------------------------
__device__ __forceinline__ void mma_mainloop(uint32_t su,
    const __nv_bfloat16* A, int arow0, int alim, size_t astr,
    const __nv_bfloat16* Bp, int brow0, int blim, size_t bstr,
    int nK, int tid, int lane, int warpM, int warpN, float (&acc)[4][4][4]) {
    cpa_tile(su,         A,  arow0, alim, astr, 0, tid);
    cpa_tile(su + 16384, Bp, brow0, blim, bstr, 0, tid);
    CPA_COMMIT();
    CPA_WAIT();
    __syncthreads();
    for (int it = 0; it < nK; ++it) {
        uint32_t base = su + (uint32_t)((it & 1) * 32768);
        if (it + 1 < nK) {
            uint32_t nbase = su + (uint32_t)(((it + 1) & 1) * 32768);
            cpa_tile(nbase,         A,  arow0, alim, astr, (it + 1) * 64, tid);
            cpa_tile(nbase + 16384, Bp, brow0, blim, bstr, (it + 1) * 64, tid);
            CPA_COMMIT();
        }
        mma_compute(base, base + 16384, lane, warpM, warpN, acc);
        CPA_WAIT();
        __syncthreads();
    }
}

// ---------------- GEMM1: S = tok @ npf^T (+ npc, ct on z=128 slice) ------------
__global__ __launch_bounds__(256, 1) void k_mma1() {
    extern __shared__ char smem[];
    uint32_t su = s2u(smem);
    int tid = threadIdx.x, lane = tid & 31, wid = tid >> 5;
    int warpM = wid & 1, warpN = wid >> 1;
    int bx = blockIdx.x, by = blockIdx.y, bz = blockIdx.z;

    const __nv_bfloat16 *A, *Bp;
    float* Cout; size_t cstr; int M, m0, n0; bool isS;
    if (bz < Bn) {
        A = g_tok + (size_t)bz * Ln * Dn;
        Bp = g_npf + (size_t)bx * 128 * Dn;
        Cout = g_S + (size_t)bz * Ln * NPn; cstr = NPn;
        M = Ln; m0 = by * 128; n0 = bx * 128; isS = true;
    } else if (by == 0) {
        A = g_img; Bp = g_npf + (size_t)bx * 128 * Dn;
        Cout = g_npc; cstr = NPn; M = Bn; m0 = 0; n0 = bx * 128; isS = false;
    } else if (by == 1 && bx == 0) {
        A = g_img; Bp = g_txt;
        Cout = g_ct; cstr = Bn; M = Bn; m0 = 0; n0 = 0; isS = false;
    } else return;

    float acc[4][4][4];
#pragma unroll
    for (int i = 0; i < 4; i++)
#pragma unroll
        for (int j = 0; j < 4; j++)
#pragma unroll
            for (int k = 0; k < 4; k++) acc[i][j][k] = 0.f;

    mma_mainloop(su, A, m0, M, (size_t)Dn, Bp, 0, 128, (size_t)Dn,
                 12, tid, lane, warpM, warpN, acc);

#pragma unroll
    for (int mb = 0; mb < 4; mb++) {
#pragma unroll
        for (int h = 0; h < 2; h++) {
            int gr = m0 + warpM * 64 + mb * 16 + (lane >> 2) + h * 8;
            float ps = 0.f;
            if (gr < M) {
#pragma unroll
                for (int nb = 0; nb < 4; nb++) {
                    float x = acc[mb][nb][h * 2], y = acc[mb][nb][h * 2 + 1];
                    if (isS) {
                        float lx = lk(x), ly = lk(y);
                        ps += lx * lx + ly * ly;
                    }
                    float2 v; v.x = x; v.y = y;
                    *(float2*)(Cout + (size_t)gr * cstr + n0 + warpN * 32 + nb * 8 + (lane & 3) * 2) = v;
                }
            }
            if (isS) {
                ps += __shfl_xor_sync(0xffffffffu, ps, 1);
                ps += __shfl_xor_sync(0xffffffffu, ps, 2);
                if ((lane & 3) == 0 && gr < M)
                    atomicAdd(&g_norm2[(size_t)bz * Ln + gr], ps);
            }
        }
    }
}

// ---------------- GEMM2: wn2 += rowsum( (P_t @ T_t^T)^2 ), wctx never stored ---
__global__ __launch_bounds__(256, 1) void k_mma2() {
    extern __shared__ char smem[];
    uint32_t su = s2u(smem);
    int tid = threadIdx.x, lane = tid & 31, wid = tid >> 5;
    int warpM = wid & 1, warpN = wid >> 1;
    int bx = blockIdx.x, by = blockIdx.y, bz = blockIdx.z;

    const __nv_bfloat16* A  = g_Pt + (size_t)bz * NPn * LP;
    const __nv_bfloat16* Bp = g_Tt + (size_t)bz * Dn * LP;
    int m0 = by * 128, n0 = bx * 128;

    float acc[4][4][4];
#pragma unroll
    for (int i = 0; i < 4; i++)
#pragma unroll
        for (int j = 0; j < 4; j++)
#pragma unroll
            for (int k = 0; k < 4; k++) acc[i][j][k] = 0.f;

    mma_mainloop(su, A, m0, NPn, (size_t)LP, Bp, n0, Dn, (size_t)LP,
                 10, tid, lane, warpM, warpN, acc);
    (void)n0;

#pragma unroll
    for (int mb = 0; mb < 4; mb++) {
#pragma unroll
        for (int h = 0; h < 2; h++) {
            int gr = m0 + warpM * 64 + mb * 16 + (lane >> 2) + h * 8;
            float s = 0.f;
#pragma unroll
            for (int nb = 0; nb < 4; nb++) {
                float x = acc[mb][nb][h * 2], y = acc[mb][nb][h * 2 + 1];
                s += x * x + y * y;
            }
            s += __shfl_xor_sync(0xffffffffu, s, 1);
            s += __shfl_xor_sync(0xffffffffu, s, 2);
            if ((lane & 3) == 0)
                atomicAdd(&g_wn2[(size_t)bz * NPn + gr], s);
        }
    }
}

// ---------------- init / conversions / transposes ------------------------------
__global__ void k_init(const int* __restrict__ idxr) {
    int gid = blockIdx.x * 256 + threadIdx.x;
    if (gid < Bn * NPn) g_wn2[gid] = 0.f;
    if (gid < Bn * Ln)  g_norm2[gid] = 0.f;
    if (gid == 0) {
        g_acc = 0.f;
        int any = 0;
        for (int i = 1; i < 1024; i += 2) any |= idxr[i];
        g_idx64 = (any == 0) ? 1 : 0;
    }
}
__device__ __forceinline__ int get_idx(const int* __restrict__ r, int n) {
    return g_idx64 ? r[2 * n] : r[n];
}

__global__ void k_cvt_small(const float* __restrict__ npf, const float* __restrict__ img,
                            const float* __restrict__ txt) {
    int i = (blockIdx.x * 256 + threadIdx.x) * 4;
    const float* src; __nv_bfloat16* dst; int off;
    if (i < NPn * Dn)                    { src = npf; dst = g_npf; off = i; }
    else if (i < NPn * Dn + Bn * Dn)     { src = img; dst = g_img; off = i - NPn * Dn; }
    else if (i < NPn * Dn + 2 * Bn * Dn) { src = txt; dst = g_txt; off = i - NPn * Dn - Bn * Dn; }
    else return;
    float4 v = *(const float4*)(src + off);
    *(__nv_bfloat162*)(dst + off)     = __floats2bfloat162_rn(v.x, v.y);
    *(__nv_bfloat162*)(dst + off + 2) = __floats2bfloat162_rn(v.z, v.w);
}

__global__ void k_cvt_tok(const float* __restrict__ tok) {
    size_t i = ((size_t)blockIdx.x * 256 + threadIdx.x) * 4;
    float4 v = *(const float4*)(tok + i);
    *(__nv_bfloat162*)(g_tok + i)     = __floats2bfloat162_rn(v.x, v.y);
    *(__nv_bfloat162*)(g_tok + i + 2) = __floats2bfloat162_rn(v.z, v.w);
}

__global__ void k_ttok(const float* __restrict__ tok) {
    __shared__ float t[32][33];
    int bz = blockIdx.z;
    int d = blockIdx.x * 32 + threadIdx.x;
    int l = blockIdx.y * 32 + threadIdx.y;
    t[threadIdx.y][threadIdx.x] = (l < Ln) ? tok[(size_t)bz * Ln * Dn + (size_t)l * Dn + d] : 0.f;
    __syncthreads();
    int dd = blockIdx.x * 32 + threadIdx.y;
    int ll = blockIdx.y * 32 + threadIdx.x;
    g_Tt[(size_t)bz * Dn * LP + (size_t)dd * LP + ll] = __float2bfloat16(t[threadIdx.x][threadIdx.y]);
}

__global__ void k_tP() {
    __shared__ __nv_bfloat16 t[32][34];
    int bz = blockIdx.z;
    int n = blockIdx.x * 32 + threadIdx.x;
    int l = blockIdx.y * 32 + threadIdx.y;
    t[threadIdx.y][threadIdx.x] = (l < Ln)
        ? g_P[(size_t)bz * Ln * NPn + (size_t)l * NPn + n] : __float2bfloat16(0.f);
    __syncthreads();
    int nn = blockIdx.x * 32 + threadIdx.y;
    int ll = blockIdx.y * 32 + threadIdx.x;
    g_Pt[(size_t)bz * NPn * LP + (size_t)nn * LP + ll] = t[threadIdx.x][threadIdx.y];
}

__global__ void k_qnorm(const float* __restrict__ npf) {
    int n = blockIdx.x;
    float s = 0.f;
    for (int d = threadIdx.x; d < Dn; d += 256) {
        float v = npf[(size_t)n * Dn + d];
        s += v * v;
    }
    __shared__ float sh[256];
    sh[threadIdx.x] = s; __syncthreads();
    for (int o = 128; o > 0; o >>= 1) {
        if (threadIdx.x < o) sh[threadIdx.x] += sh[threadIdx.x + o];
        __syncthreads();
    }
    if (threadIdx.x == 0) g_qn[n] = sqrtf(sh[0]);
}

__global__ void k_inv() {
    int i = blockIdx.x * 256 + threadIdx.x;
    if (i < Bn * Ln) g_inv[i] = 1.f / fmaxf(sqrtf(g_norm2[i]), EPSF);
}

// ---------------- softmax over l; writes P (bf16) and num -----------------------
__global__ void k_softmax() {
    int b = blockIdx.y;
    int n = blockIdx.x * 256 + threadIdx.x;
    __shared__ float sinv[Ln];
    for (int j = threadIdx.x; j < Ln; j += 256) sinv[j] = g_inv[b * Ln + j];
    __syncthreads();

    size_t base = (size_t)b * Ln * NPn + n;
    float m = -3.4e38f, s = 0.f;
    for (int l = 0; l < Ln; l++) {
        float raw = g_S[base + (size_t)l * NPn];
        float v = lk(raw) * sinv[l] * 4.0f;
        if (v > m) { s = s * expf(m - v) + 1.f; m = v; }
        else       { s += expf(v - m); }
    }
    float inv_s = 1.f / s;
    float num = 0.f;
    for (int l = 0; l < Ln; l++) {
        size_t idx = base + (size_t)l * NPn;
        float raw = g_S[idx];
        float v = lk(raw) * sinv[l] * 4.0f;
        float pl = expf(v - m) * inv_s;
        g_P[idx] = __float2bfloat16(pl);
        num += pl * raw;
    }
    g_num[(size_t)b * NPn + n] = num;
}

// ---------------- loss reductions ----------------------------------------------
__device__ __forceinline__ void block_acc(float t, float w) {
    __shared__ float sh[256];
    sh[threadIdx.x] = t; __syncthreads();
    for (int o = 128; o > 0; o >>= 1) {
        if (threadIdx.x < o) sh[threadIdx.x] += sh[threadIdx.x + o];
        __syncthreads();
    }
    if (threadIdx.x == 0) atomicAdd(&g_acc, sh[0] * w);
}

__global__ void k_loss_ct(const float* sc, const float* bi) {
    int gid = blockIdx.x * 256 + threadIdx.x;
    float t = 0.f;
    if (gid < Bn * Bn) {
        int i = gid >> 7, j = gid & 127;
        float lg = g_ct[gid] * sc[0] + bi[0];
        float lab = (i == j) ? 1.f : -1.f;
        t = -logsig(lab * lg);
    }
    block_acc(t, 1.0f / Bn);
}

__global__ void k_loss_npc(const float* sc, const float* bi, const int* __restrict__ idxr) {
    int gid = blockIdx.x * 256 + threadIdx.x;
    float t = 0.f;
    if (gid < Bn * NPn) {
        int b = gid >> 10, n = gid & 1023;
        float lab = (get_idx(idxr, n) == b) ? 1.f : -1.f;
        float lg = g_npc[gid] * sc[0] + bi[0];
        t = -logsig(lab * lg);
    }
    block_acc(t, 1.0f / NPn);
}

__global__ void k_loss_xac(const float* sc, const float* bi, const int* __restrict__ idxr) {
    int gid = blockIdx.x * 256 + threadIdx.x;
    float t = 0.f;
    if (gid < Bn * NPn) {
        int b = gid >> 10, n = gid & 1023;
        float wn = sqrtf(g_wn2[gid]);
        float den = fmaxf(g_qn[n] * wn, EPSF);
        float sim = g_num[gid] / den;
        float lg = sim * sc[0] + bi[0];
        float lab = (get_idx(idxr, n) == b) ? 1.f : -1.f;
        t = -logsig(lab * lg);
    }
    block_acc(t, 0.01f / NPn);
}

__global__ void k_final(float* out) { out[0] = g_acc; }

// ---------------- launch ---------------------------------------------------------
extern "C" void kernel_launch(void* const* d_in, const int* in_sizes, int n_in,
                              void* d_out, int out_size) {
    const float* img = (const float*)d_in[0];
    const float* txt = (const float*)d_in[1];
    const float* sc  = (const float*)d_in[2];
    const float* bi  = (const float*)d_in[3];
    const float* npf = (const float*)d_in[4];
    const int*   idx = (const int*)d_in[5];
    const float* tok = (const float*)d_in[6];
    float* out = (float*)d_out;

    cudaFuncSetAttribute(k_mma1, cudaFuncAttributeMaxDynamicSharedMemorySize, SMEM_DYN);
    cudaFuncSetAttribute(k_mma2, cudaFuncAttributeMaxDynamicSharedMemorySize, SMEM_DYN);

    k_init<<<512, 256>>>(idx);
    k_cvt_small<<<960, 256>>>(npf, img, txt);
    k_cvt_tok<<<55392, 256>>>(tok);
    k_qnorm<<<NPn, 256>>>(npf);
    k_ttok<<<dim3(24, 20, 128), dim3(32, 32)>>>(tok);

    k_mma1<<<dim3(8, 5, 129), 256, SMEM_DYN>>>();
    k_inv<<<289, 256>>>();
    k_softmax<<<dim3(4, 128), 256>>>();
    k_tP<<<dim3(32, 20, 128), dim3(32, 32)>>>();
    k_mma2<<<dim3(6, 8, 128), 256, SMEM_DYN>>>();

    k_loss_ct<<<64, 256>>>(sc, bi);
    k_loss_npc<<<512, 256>>>(sc, bi, idx);
    k_loss_xac<<<512, 256>>>(sc, bi, idx);
    k_final<<<1, 1>>>(out);
}

// round 4
// speedup vs baseline: 6.8905x; 1.4616x over previous
#include <cuda_runtime.h>
#include <cuda_bf16.h>
#include <cuda_fp16.h>
#include <math.h>
#include <stdint.h>

#define Bn  128
#define Ln  577
#define LP  640
#define Dn  768
#define NPn 1024
#define EPSF 1e-8f
#define SMEM_DYN 65536

// ---------------- device scratch ----------------
__device__ __nv_bfloat16 g_S  [(size_t)Bn*Ln*NPn];   // y = leaky(S) bf16
__device__ __half        g_Pt [(size_t)Bn*NPn*LP];   // e, transposed [n][l], fp16
__device__ __half        g_Tt [(size_t)Bn*Dn*LP];    // tokens transposed [d][l], fp16
__device__ __nv_bfloat16 g_tok[(size_t)Bn*Ln*Dn];
__device__ __nv_bfloat16 g_npf[NPn*Dn];
__device__ __nv_bfloat16 g_img[Bn*Dn];
__device__ __nv_bfloat16 g_txt[Bn*Dn];
__device__ float    g_norm2[Bn*Ln];
__device__ uint32_t g_cl  [Bn*Ln];     // packed fp16x2 scale c = inv*4*log2e*1024
__device__ float    g_qn  [NPn];
__device__ float    g_num [Bn*NPn];    // q . w_hat
__device__ float    g_wn2 [Bn*NPn];    // ||w_hat||^2
__device__ float    g_ct  [Bn*Bn];
__device__ float    g_npc [Bn*NPn];
__device__ float    g_acc;
__device__ int      g_idx64;

__device__ __forceinline__ float lk(float x) { return x >= 0.f ? x : 0.1f * x; }
__device__ __forceinline__ float logsig(float x) {
    return fminf(x, 0.f) - log1pf(expf(-fabsf(x)));
}
__device__ __forceinline__ uint32_t s2u(const void* p) {
    uint32_t a;
    asm("{ .reg .u64 t; cvta.to.shared.u64 t, %1; cvt.u32.u64 %0, t; }" : "=r"(a) : "l"(p));
    return a;
}

// ---------------- cp.async tile loader: 128 rows x 64 elems(2B), SW128 --------
__device__ __forceinline__ void cpa_tile(uint32_t dst, const __nv_bfloat16* __restrict__ src,
                                         int row0, int row_lim, size_t stride, int k0, int tid) {
#pragma unroll
    for (int i = 0; i < 4; i++) {
        int e = tid + (i << 8);
        int r = e >> 3, c = e & 7;
        int gr = row0 + r;
        int sz = 16;
        if (gr >= row_lim) { gr = row_lim - 1; sz = 0; }
        const void* gp = (const void*)(src + (size_t)gr * stride + k0 + (c << 3));
        uint32_t off = (uint32_t)((r << 7) + (c << 4));
        off ^= (off >> 3) & 0x70;
        asm volatile("cp.async.cg.shared.global [%0], [%1], 16, %2;"
                     :: "r"(dst + off), "l"(gp), "r"(sz) : "memory");
    }
}
#define CPA_COMMIT() asm volatile("cp.async.commit_group;" ::: "memory")
#define CPA_WAIT()   asm volatile("cp.async.wait_group 0;" ::: "memory")

// ---------------- warp MMA over one 128x128x64 SMEM chunk ----------------------
template<bool F16>
__device__ __forceinline__ void mma_compute(uint32_t aBase, uint32_t bBase,
                                            int lane, int warpM, int warpN,
                                            float (&acc)[4][4][4]) {
#pragma unroll
    for (int ks = 0; ks < 4; ks++) {
        uint32_t a[4][4];
#pragma unroll
        for (int mb = 0; mb < 4; mb++) {
            int row = warpM * 64 + mb * 16 + (lane & 15);
            uint32_t byte = (uint32_t)(ks * 32 + ((lane >> 4) << 4));
            uint32_t off = (uint32_t)(row << 7) + byte;
            off ^= (off >> 3) & 0x70;
            asm volatile("ldmatrix.sync.aligned.m8n8.x4.shared.b16 {%0,%1,%2,%3}, [%4];"
                         : "=r"(a[mb][0]), "=r"(a[mb][1]), "=r"(a[mb][2]), "=r"(a[mb][3])
                         : "r"(aBase + off));
        }
        uint32_t b[4][2];
#pragma unroll
        for (int nb2 = 0; nb2 < 2; nb2++) {
            int row = warpN * 32 + nb2 * 16 + (lane & 7) + ((lane >> 4) << 3);
            uint32_t byte = (uint32_t)(ks * 32 + ((lane & 8) ? 16 : 0));
            uint32_t off = (uint32_t)(row << 7) + byte;
            off ^= (off >> 3) & 0x70;
            uint32_t r0, r1, r2, r3;
            asm volatile("ldmatrix.sync.aligned.m8n8.x4.shared.b16 {%0,%1,%2,%3}, [%4];"
                         : "=r"(r0), "=r"(r1), "=r"(r2), "=r"(r3)
                         : "r"(bBase + off));
            b[nb2 * 2][0] = r0; b[nb2 * 2][1] = r1;
            b[nb2 * 2 + 1][0] = r2; b[nb2 * 2 + 1][1] = r3;
        }
#pragma unroll
        for (int mb = 0; mb < 4; mb++)
#pragma unroll
            for (int nb = 0; nb < 4; nb++) {
                if (F16)
                    asm volatile(
                        "mma.sync.aligned.m16n8k16.row.col.f32.f16.f16.f32 "
                        "{%0,%1,%2,%3},{%4,%5,%6,%7},{%8,%9},{%0,%1,%2,%3};"
                        : "+f"(acc[mb][nb][0]), "+f"(acc[mb][nb][1]),
                          "+f"(acc[mb][nb][2]), "+f"(acc[mb][nb][3])
                        : "r"(a[mb][0]), "r"(a[mb][1]), "r"(a[mb][2]), "r"(a[mb][3]),
                          "r"(b[nb][0]), "r"(b[nb][1]));
                else
                    asm volatile(
                        "mma.sync.aligned.m16n8k16.row.col.f32.bf16.bf16.f32 "
                        "{%0,%1,%2,%3},{%4,%5,%6,%7},{%8,%9},{%0,%1,%2,%3};"
                        : "+f"(acc[mb][nb][0]), "+f"(acc[mb][nb][1]),
                          "+f"(acc[mb][nb][2]), "+f"(acc[mb][nb][3])
                        : "r"(a[mb][0]), "r"(a[mb][1]), "r"(a[mb][2]), "r"(a[mb][3]),
                          "r"(b[nb][0]), "r"(b[nb][1]));
            }
    }
}

// ---------------- shared mainloop ------------------------------------------------
template<bool F16>
__device__ __forceinline__ void mma_mainloop(uint32_t su,
    const __nv_bfloat16* A, int arow0, int alim, size_t astr,
    const __nv_bfloat16* Bp, int brow0, int blim, size_t bstr,
    int nK, int tid, int lane, int warpM, int warpN, float (&acc)[4][4][4]) {
    cpa_tile(su,         A,  arow0, alim, astr, 0, tid);
    cpa_tile(su + 16384, Bp, brow0, blim, bstr, 0, tid);
    CPA_COMMIT();
    CPA_WAIT();
    __syncthreads();
    for (int it = 0; it < nK; ++it) {
        uint32_t base = su + (uint32_t)((it & 1) * 32768);
        if (it + 1 < nK) {
            uint32_t nbase = su + (uint32_t)(((it + 1) & 1) * 32768);
            cpa_tile(nbase,         A,  arow0, alim, astr, (it + 1) * 64, tid);
            cpa_tile(nbase + 16384, Bp, brow0, blim, bstr, (it + 1) * 64, tid);
            CPA_COMMIT();
        }
        mma_compute<F16>(base, base + 16384, lane, warpM, warpN, acc);
        CPA_WAIT();
        __syncthreads();
    }
}

// ---------------- GEMM1: y = lk(tok @ npf^T) (+ npc, ct on z=128 slice) --------
__global__ __launch_bounds__(256, 1) void k_mma1() {
    extern __shared__ char smem[];
    uint32_t su = s2u(smem);
    int tid = threadIdx.x, lane = tid & 31, wid = tid >> 5;
    int warpM = wid & 1, warpN = wid >> 1;
    int bx = blockIdx.x, by = blockIdx.y, bz = blockIdx.z;

    const __nv_bfloat16 *A, *Bp;
    float* CoutF = 0; __nv_bfloat16* CoutB = 0;
    size_t cstr; int M, m0, n0; bool isS;
    if (bz < Bn) {
        A = g_tok + (size_t)bz * Ln * Dn;
        Bp = g_npf + (size_t)bx * 128 * Dn;
        CoutB = g_S + (size_t)bz * Ln * NPn; cstr = NPn;
        M = Ln; m0 = by * 128; n0 = bx * 128; isS = true;
    } else if (by == 0) {
        A = g_img; Bp = g_npf + (size_t)bx * 128 * Dn;
        CoutF = g_npc; cstr = NPn; M = Bn; m0 = 0; n0 = bx * 128; isS = false;
    } else if (by == 1 && bx == 0) {
        A = g_img; Bp = g_txt;
        CoutF = g_ct; cstr = Bn; M = Bn; m0 = 0; n0 = 0; isS = false;
    } else return;

    float acc[4][4][4];
#pragma unroll
    for (int i = 0; i < 4; i++)
#pragma unroll
        for (int j = 0; j < 4; j++)
#pragma unroll
            for (int k = 0; k < 4; k++) acc[i][j][k] = 0.f;

    mma_mainloop<false>(su, A, m0, M, (size_t)Dn, Bp, 0, 128, (size_t)Dn,
                        12, tid, lane, warpM, warpN, acc);

#pragma unroll
    for (int mb = 0; mb < 4; mb++) {
#pragma unroll
        for (int h = 0; h < 2; h++) {
            int gr = m0 + warpM * 64 + mb * 16 + (lane >> 2) + h * 8;
            if (isS) {
                float ps = 0.f;
                if (gr < M) {
#pragma unroll
                    for (int nb = 0; nb < 4; nb++) {
                        float lx = lk(acc[mb][nb][h * 2]);
                        float ly = lk(acc[mb][nb][h * 2 + 1]);
                        ps += lx * lx + ly * ly;
                        uint32_t pk;
                        asm("cvt.rn.bf16x2.f32 %0, %1, %2;" : "=r"(pk) : "f"(ly), "f"(lx));
                        *(uint32_t*)(CoutB + (size_t)gr * cstr +
                                     n0 + warpN * 32 + nb * 8 + (lane & 3) * 2) = pk;
                    }
                }
                ps += __shfl_xor_sync(0xffffffffu, ps, 1);
                ps += __shfl_xor_sync(0xffffffffu, ps, 2);
                if ((lane & 3) == 0 && gr < M)
                    atomicAdd(&g_norm2[(size_t)bz * Ln + gr], ps);
            } else if (gr < M) {
#pragma unroll
                for (int nb = 0; nb < 4; nb++) {
                    float2 v;
                    v.x = acc[mb][nb][h * 2]; v.y = acc[mb][nb][h * 2 + 1];
                    *(float2*)(CoutF + (size_t)gr * cstr +
                               n0 + warpN * 32 + nb * 8 + (lane & 3) * 2) = v;
                }
            }
        }
    }
}

// ---------------- GEMM2: w_hat = e @ tok; epilogue: wn2 += ||.||^2, num += q.w --
__global__ __launch_bounds__(256, 1) void k_mma2() {
    extern __shared__ char smem[];
    uint32_t su = s2u(smem);
    int tid = threadIdx.x, lane = tid & 31, wid = tid >> 5;
    int warpM = wid & 1, warpN = wid >> 1;
    int bx = blockIdx.x, by = blockIdx.y, bz = blockIdx.z;

    const __nv_bfloat16* A  = (const __nv_bfloat16*)(g_Pt + (size_t)bz * NPn * LP);
    const __nv_bfloat16* Bp = (const __nv_bfloat16*)(g_Tt + (size_t)bz * Dn * LP);
    int m0 = by * 128, n0 = bx * 128;

    float acc[4][4][4];
#pragma unroll
    for (int i = 0; i < 4; i++)
#pragma unroll
        for (int j = 0; j < 4; j++)
#pragma unroll
            for (int k = 0; k < 4; k++) acc[i][j][k] = 0.f;

    mma_mainloop<true>(su, A, m0, NPn, (size_t)LP, Bp, n0, Dn, (size_t)LP,
                       10, tid, lane, warpM, warpN, acc);

#pragma unroll
    for (int mb = 0; mb < 4; mb++) {
#pragma unroll
        for (int h = 0; h < 2; h++) {
            int gr = m0 + warpM * 64 + mb * 16 + (lane >> 2) + h * 8;
            float s = 0.f, nump = 0.f;
#pragma unroll
            for (int nb = 0; nb < 4; nb++) {
                float x = acc[mb][nb][h * 2], y = acc[mb][nb][h * 2 + 1];
                s += x * x + y * y;
                int dcol = n0 + warpN * 32 + nb * 8 + (lane & 3) * 2;
                __nv_bfloat162 q = *(const __nv_bfloat162*)(g_npf + (size_t)gr * Dn + dcol);
                nump += __bfloat162float(q.x) * x + __bfloat162float(q.y) * y;
            }
            s    += __shfl_xor_sync(0xffffffffu, s, 1);
            s    += __shfl_xor_sync(0xffffffffu, s, 2);
            nump += __shfl_xor_sync(0xffffffffu, nump, 1);
            nump += __shfl_xor_sync(0xffffffffu, nump, 2);
            if ((lane & 3) == 0) {
                atomicAdd(&g_wn2[(size_t)bz * NPn + gr], s);
                atomicAdd(&g_num[(size_t)bz * NPn + gr], nump);
            }
        }
    }
}

// ---------------- e-pass: e = 2^(y*c) via fp16 Schraudolph; transposed out ------
__global__ __launch_bounds__(256) void k_epass() {
    int bz = blockIdx.z, l0 = blockIdx.y * 64, n0 = blockIdx.x * 256;
    __shared__ __half st[256][66];
    __shared__ uint32_t sc[64];
    int tid = threadIdx.x;
    if (tid < 64) {
        int l = l0 + tid;
        sc[tid] = (l < Ln) ? g_cl[bz * Ln + l] : 0u;
    }
    __syncthreads();
    const uint16_t* Sb = (const uint16_t*)g_S + (size_t)bz * Ln * NPn;
#pragma unroll
    for (int i = 0; i < 16; i++) {
        int j = tid + i * 256;
        int row = j >> 6, cu = j & 63;
        int l = l0 + row;
        uint32_t r0 = 0u, r1 = 0u;
        if (l < Ln) {
            uint2 v = *(const uint2*)(Sb + (size_t)l * NPn + n0 + cu * 4);
            uint32_t c2 = sc[row], hh;
            float f0 = __uint_as_float(v.x << 16);
            float f1 = __uint_as_float(v.x & 0xFFFF0000u);
            asm("cvt.rn.f16x2.f32 %0, %1, %2;" : "=r"(hh) : "f"(f1), "f"(f0));
            asm("fma.rn.f16x2 %0, %1, %2, %3;" : "=r"(r0)
                : "r"(hh), "r"(c2), "r"(0x73807380u));
            float f2 = __uint_as_float(v.y << 16);
            float f3 = __uint_as_float(v.y & 0xFFFF0000u);
            asm("cvt.rn.f16x2.f32 %0, %1, %2;" : "=r"(hh) : "f"(f3), "f"(f2));
            asm("fma.rn.f16x2 %0, %1, %2, %3;" : "=r"(r1)
                : "r"(hh), "r"(c2), "r"(0x73807380u));
        }
        int nl = cu * 4;
        __half2 a = *(__half2*)&r0, b = *(__half2*)&r1;
        st[nl + 0][row] = a.x; st[nl + 1][row] = a.y;
        st[nl + 2][row] = b.x; st[nl + 3][row] = b.y;
    }
    __syncthreads();
    int wid = tid >> 5, lane = tid & 31;
    __half* Pt = g_Pt + (size_t)bz * NPn * LP;
    for (int r = wid; r < 256; r += 8) {
        __half2 h2 = *(__half2*)&st[r][2 * lane];
        *(__half2*)(Pt + (size_t)(n0 + r) * LP + l0 + 2 * lane) = h2;
    }
}

// ---------------- init / conversions / transposes ------------------------------
__global__ void k_init(const int* __restrict__ idxr) {
    int gid = blockIdx.x * 256 + threadIdx.x;
    if (gid < Bn * NPn) { g_wn2[gid] = 0.f; g_num[gid] = 0.f; }
    if (gid < Bn * Ln)  g_norm2[gid] = 0.f;
    if (gid == 0) {
        g_acc = 0.f;
        int any = 0;
        for (int i = 1; i < 1024; i += 2) any |= idxr[i];
        g_idx64 = (any == 0) ? 1 : 0;
    }
}
__device__ __forceinline__ int get_idx(const int* __restrict__ r, int n) {
    return g_idx64 ? r[2 * n] : r[n];
}

__global__ void k_cvt_small(const float* __restrict__ npf, const float* __restrict__ img,
                            const float* __restrict__ txt) {
    int i = (blockIdx.x * 256 + threadIdx.x) * 4;
    const float* src; __nv_bfloat16* dst; int off;
    if (i < NPn * Dn)                    { src = npf; dst = g_npf; off = i; }
    else if (i < NPn * Dn + Bn * Dn)     { src = img; dst = g_img; off = i - NPn * Dn; }
    else if (i < NPn * Dn + 2 * Bn * Dn) { src = txt; dst = g_txt; off = i - NPn * Dn - Bn * Dn; }
    else return;
    float4 v = *(const float4*)(src + off);
    *(__nv_bfloat162*)(dst + off)     = __floats2bfloat162_rn(v.x, v.y);
    *(__nv_bfloat162*)(dst + off + 2) = __floats2bfloat162_rn(v.z, v.w);
}

__global__ void k_cvt_tok(const float* __restrict__ tok) {
    size_t i = ((size_t)blockIdx.x * 256 + threadIdx.x) * 4;
    float4 v = *(const float4*)(tok + i);
    *(__nv_bfloat162*)(g_tok + i)     = __floats2bfloat162_rn(v.x, v.y);
    *(__nv_bfloat162*)(g_tok + i + 2) = __floats2bfloat162_rn(v.z, v.w);
}

__global__ void k_ttok() {
    __shared__ float t[32][33];
    int bz = blockIdx.z;
    int d = blockIdx.x * 32 + threadIdx.x;
    int l = blockIdx.y * 32 + threadIdx.y;
    t[threadIdx.y][threadIdx.x] = (l < Ln)
        ? __bfloat162float(g_tok[(size_t)bz * Ln * Dn + (size_t)l * Dn + d]) : 0.f;
    __syncthreads();
    int dd = blockIdx.x * 32 + threadIdx.y;
    int ll = blockIdx.y * 32 + threadIdx.x;
    g_Tt[(size_t)bz * Dn * LP + (size_t)dd * LP + ll] = __float2half(t[threadIdx.x][threadIdx.y]);
}

__global__ void k_qnorm(const float* __restrict__ npf) {
    int n = blockIdx.x;
    float s = 0.f;
    for (int d = threadIdx.x; d < Dn; d += 256) {
        float v = npf[(size_t)n * Dn + d];
        s += v * v;
    }
    __shared__ float sh[256];
    sh[threadIdx.x] = s; __syncthreads();
    for (int o = 128; o > 0; o >>= 1) {
        if (threadIdx.x < o) sh[threadIdx.x] += sh[threadIdx.x + o];
        __syncthreads();
    }
    if (threadIdx.x == 0) g_qn[n] = sqrtf(sh[0]);
}

__global__ void k_inv() {
    int i = blockIdx.x * 256 + threadIdx.x;
    if (i < Bn * Ln) {
        float inv = 1.f / fmaxf(sqrtf(g_norm2[i]), EPSF);
        float cf = fminf(inv * 5909.2788f, 60000.f);   // 4*log2(e)*1024
        uint32_t b = (uint32_t)__half_as_ushort(__float2half_rn(cf));
        g_cl[i] = b | (b << 16);
    }
}

// ---------------- loss reductions ----------------------------------------------
__device__ __forceinline__ void block_acc(float t, float w) {
    __shared__ float sh[256];
    sh[threadIdx.x] = t; __syncthreads();
    for (int o = 128; o > 0; o >>= 1) {
        if (threadIdx.x < o) sh[threadIdx.x] += sh[threadIdx.x + o];
        __syncthreads();
    }
    if (threadIdx.x == 0) atomicAdd(&g_acc, sh[0] * w);
}

__global__ void k_loss_ct(const float* sc, const float* bi) {
    int gid = blockIdx.x * 256 + threadIdx.x;
    float t = 0.f;
    if (gid < Bn * Bn) {
        int i = gid >> 7, j = gid & 127;
        float lg = g_ct[gid] * sc[0] + bi[0];
        float lab = (i == j) ? 1.f : -1.f;
        t = -logsig(lab * lg);
    }
    block_acc(t, 1.0f / Bn);
}

__global__ void k_loss_npc(const float* sc, const float* bi, const int* __restrict__ idxr) {
    int gid = blockIdx.x * 256 + threadIdx.x;
    float t = 0.f;
    if (gid < Bn * NPn) {
        int b = gid >> 10, n = gid & 1023;
        float lab = (get_idx(idxr, n) == b) ? 1.f : -1.f;
        float lg = g_npc[gid] * sc[0] + bi[0];
        t = -logsig(lab * lg);
    }
    block_acc(t, 1.0f / NPn);
}

__global__ void k_loss_xac(const float* sc, const float* bi, const int* __restrict__ idxr) {
    int gid = blockIdx.x * 256 + threadIdx.x;
    float t = 0.f;
    if (gid < Bn * NPn) {
        int b = gid >> 10, n = gid & 1023;
        float wn = sqrtf(g_wn2[gid]);
        float den = fmaxf(g_qn[n] * wn, EPSF);
        float sim = g_num[gid] / den;
        float lg = sim * sc[0] + bi[0];
        float lab = (get_idx(idxr, n) == b) ? 1.f : -1.f;
        t = -logsig(lab * lg);
    }
    block_acc(t, 0.01f / NPn);
}

__global__ void k_final(float* out) { out[0] = g_acc; }

// ---------------- launch ---------------------------------------------------------
extern "C" void kernel_launch(void* const* d_in, const int* in_sizes, int n_in,
                              void* d_out, int out_size) {
    const float* img = (const float*)d_in[0];
    const float* txt = (const float*)d_in[1];
    const float* sc  = (const float*)d_in[2];
    const float* bi  = (const float*)d_in[3];
    const float* npf = (const float*)d_in[4];
    const int*   idx = (const int*)d_in[5];
    const float* tok = (const float*)d_in[6];
    float* out = (float*)d_out;

    cudaFuncSetAttribute(k_mma1, cudaFuncAttributeMaxDynamicSharedMemorySize, SMEM_DYN);
    cudaFuncSetAttribute(k_mma2, cudaFuncAttributeMaxDynamicSharedMemorySize, SMEM_DYN);

    k_init<<<512, 256>>>(idx);
    k_cvt_small<<<960, 256>>>(npf, img, txt);
    k_cvt_tok<<<55392, 256>>>(tok);
    k_qnorm<<<NPn, 256>>>(npf);
    k_ttok<<<dim3(24, 20, 128), dim3(32, 32)>>>();

    k_mma1<<<dim3(8, 5, 129), 256, SMEM_DYN>>>();
    k_inv<<<289, 256>>>();
    k_epass<<<dim3(4, 10, 128), 256>>>();
    k_mma2<<<dim3(6, 8, 128), 256, SMEM_DYN>>>();

    k_loss_ct<<<64, 256>>>(sc, bi);
    k_loss_npc<<<512, 256>>>(sc, bi, idx);
    k_loss_xac<<<512, 256>>>(sc, bi, idx);
    k_final<<<1, 1>>>(out);
}

// round 5
// speedup vs baseline: 8.4661x; 1.2287x over previous
#include <cuda_runtime.h>
#include <cuda_bf16.h>
#include <cuda_fp16.h>
#include <math.h>
#include <stdint.h>

#define Bn  128
#define Ln  577
#define LP  640
#define Dn  768
#define NPn 1024
#define EPSF 1e-8f
#define STAGE_B 49152
#define SMEM_DYN (3 * STAGE_B)

// ---------------- device scratch ----------------
__device__ __half        g_Yt [(size_t)Bn*NPn*LP];   // y = leaky(S), [b][n][l] fp16
__device__ __half        g_Pt [(size_t)Bn*NPn*LP];   // e, [b][n][l] fp16
__device__ __half        g_Tt [(size_t)Bn*Dn*LP];    // tokens transposed [b][d][l] fp16
__device__ __nv_bfloat16 g_tok[(size_t)Bn*Ln*Dn];
__device__ __nv_bfloat16 g_npf[NPn*Dn];
__device__ __nv_bfloat16 g_img[Bn*Dn];
__device__ __nv_bfloat16 g_txt[Bn*Dn];
__device__ float  g_norm2[Bn*Ln];
__device__ __half g_ch [Bn*LP];     // per-(b,l) scale c (fp16), pad=0
__device__ __half g_ca [LP];        // per-l addend: 15360.0 valid, 0 pad
__device__ float  g_qn  [NPn];
__device__ float  g_num [Bn*NPn];
__device__ float  g_wn2 [Bn*NPn];
__device__ float  g_ct  [Bn*Bn];
__device__ float  g_npc [Bn*NPn];
__device__ float  g_acc;
__device__ int    g_idx64;

__device__ __forceinline__ float lk(float x) { return x >= 0.f ? x : 0.1f * x; }
__device__ __forceinline__ float logsig(float x) {
    return fminf(x, 0.f) - log1pf(expf(-fabsf(x)));
}
__device__ __forceinline__ uint32_t s2u(const void* p) {
    uint32_t a;
    asm("{ .reg .u64 t; cvta.to.shared.u64 t, %1; cvt.u32.u64 %0, t; }" : "=r"(a) : "l"(p));
    return a;
}

// ---------------- cp.async tile loader: ROWS x 64 elems(2B), SW128 ------------
template<int ROWS>
__device__ __forceinline__ void cpa_tile(uint32_t dst, const __nv_bfloat16* __restrict__ src,
                                         int row0, int row_lim, size_t stride, int k0, int tid) {
#pragma unroll
    for (int i = 0; i < ROWS / 32; i++) {
        int e = tid + (i << 8);
        int r = e >> 3, c = e & 7;
        int gr = row0 + r;
        int sz = 16;
        if (gr >= row_lim) { gr = row_lim - 1; sz = 0; }
        const void* gp = (const void*)(src + (size_t)gr * stride + k0 + (c << 3));
        uint32_t off = (uint32_t)((r << 7) + (c << 4));
        off ^= (off >> 3) & 0x70;
        asm volatile("cp.async.cg.shared.global [%0], [%1], 16, %2;"
                     :: "r"(dst + off), "l"(gp), "r"(sz) : "memory");
    }
}
#define CPA_COMMIT() asm volatile("cp.async.commit_group;" ::: "memory")

// ---------------- warp MMA over one 128x256x64 SMEM chunk ----------------------
template<bool F16>
__device__ __forceinline__ void mma_compute(uint32_t aBase, uint32_t bBase,
                                            int lane, int warpM, int warpN,
                                            float (&acc)[4][8][4]) {
#pragma unroll
    for (int ks = 0; ks < 4; ks++) {
        uint32_t a[4][4];
#pragma unroll
        for (int mb = 0; mb < 4; mb++) {
            int row = warpM * 64 + mb * 16 + (lane & 15);
            uint32_t byte = (uint32_t)(ks * 32 + ((lane >> 4) << 4));
            uint32_t off = (uint32_t)(row << 7) + byte;
            off ^= (off >> 3) & 0x70;
            asm volatile("ldmatrix.sync.aligned.m8n8.x4.shared.b16 {%0,%1,%2,%3}, [%4];"
                         : "=r"(a[mb][0]), "=r"(a[mb][1]), "=r"(a[mb][2]), "=r"(a[mb][3])
                         : "r"(aBase + off));
        }
        uint32_t b[8][2];
#pragma unroll
        for (int g = 0; g < 4; g++) {
            int row = warpN * 64 + g * 16 + (lane & 7) + ((lane >> 4) << 3);
            uint32_t byte = (uint32_t)(ks * 32 + ((lane & 8) ? 16 : 0));
            uint32_t off = (uint32_t)(row << 7) + byte;
            off ^= (off >> 3) & 0x70;
            uint32_t r0, r1, r2, r3;
            asm volatile("ldmatrix.sync.aligned.m8n8.x4.shared.b16 {%0,%1,%2,%3}, [%4];"
                         : "=r"(r0), "=r"(r1), "=r"(r2), "=r"(r3)
                         : "r"(bBase + off));
            b[g * 2][0] = r0; b[g * 2][1] = r1;
            b[g * 2 + 1][0] = r2; b[g * 2 + 1][1] = r3;
        }
#pragma unroll
        for (int mb = 0; mb < 4; mb++)
#pragma unroll
            for (int nb = 0; nb < 8; nb++) {
                if (F16)
                    asm volatile(
                        "mma.sync.aligned.m16n8k16.row.col.f32.f16.f16.f32 "
                        "{%0,%1,%2,%3},{%4,%5,%6,%7},{%8,%9},{%0,%1,%2,%3};"
                        : "+f"(acc[mb][nb][0]), "+f"(acc[mb][nb][1]),
                          "+f"(acc[mb][nb][2]), "+f"(acc[mb][nb][3])
                        : "r"(a[mb][0]), "r"(a[mb][1]), "r"(a[mb][2]), "r"(a[mb][3]),
                          "r"(b[nb][0]), "r"(b[nb][1]));
                else
                    asm volatile(
                        "mma.sync.aligned.m16n8k16.row.col.f32.bf16.bf16.f32 "
                        "{%0,%1,%2,%3},{%4,%5,%6,%7},{%8,%9},{%0,%1,%2,%3};"
                        : "+f"(acc[mb][nb][0]), "+f"(acc[mb][nb][1]),
                          "+f"(acc[mb][nb][2]), "+f"(acc[mb][nb][3])
                        : "r"(a[mb][0]), "r"(a[mb][1]), "r"(a[mb][2]), "r"(a[mb][3]),
                          "r"(b[nb][0]), "r"(b[nb][1]));
            }
    }
}

// ---------------- 3-stage pipelined mainloop -----------------------------------
template<bool F16>
__device__ __forceinline__ void mma_mainloop(uint32_t su,
    const __nv_bfloat16* A, int arow0, int alim, size_t astr,
    const __nv_bfloat16* Bp, int brow0, int blim, size_t bstr,
    int nK, int tid, int lane, int warpM, int warpN, float (&acc)[4][8][4]) {
    cpa_tile<128>(su,         A,  arow0, alim, astr, 0, tid);
    cpa_tile<256>(su + 16384, Bp, brow0, blim, bstr, 0, tid);
    CPA_COMMIT();
    cpa_tile<128>(su + STAGE_B,         A,  arow0, alim, astr, 64, tid);
    cpa_tile<256>(su + STAGE_B + 16384, Bp, brow0, blim, bstr, 64, tid);
    CPA_COMMIT();
    for (int it = 0; it < nK; ++it) {
        if (it < nK - 1) asm volatile("cp.async.wait_group 1;" ::: "memory");
        else             asm volatile("cp.async.wait_group 0;" ::: "memory");
        __syncthreads();
        if (it + 2 < nK) {
            uint32_t nb = su + (uint32_t)(((it + 2) % 3) * STAGE_B);
            cpa_tile<128>(nb,         A,  arow0, alim, astr, (it + 2) * 64, tid);
            cpa_tile<256>(nb + 16384, Bp, brow0, blim, bstr, (it + 2) * 64, tid);
            CPA_COMMIT();
        }
        uint32_t base = su + (uint32_t)((it % 3) * STAGE_B);
        mma_compute<F16>(base, base + 16384, lane, warpM, warpN, acc);
    }
    __syncthreads();
}

// ---------------- GEMM1: y = lk(tok @ npf^T), transposed out (+ npc/ct) --------
__global__ __launch_bounds__(256, 1) void k_mma1() {
    extern __shared__ char smem[];
    uint32_t su = s2u(smem);
    int tid = threadIdx.x, lane = tid & 31, wid = tid >> 5;
    int warpM = wid & 1, warpN = wid >> 1;
    int bx = blockIdx.x, by = blockIdx.y, bz = blockIdx.z;

    const __nv_bfloat16 *A, *Bp;
    float* CoutF = 0;
    size_t cstr = 0; int M, m0, n0, Nlim = 0, blim; bool isS;
    if (bz < Bn) {
        A = g_tok + (size_t)bz * Ln * Dn;
        Bp = g_npf + (size_t)bx * 256 * Dn;
        M = Ln; m0 = by * 128; n0 = bx * 256; blim = 256; isS = true;
    } else if (by == 0) {
        A = g_img; Bp = g_npf + (size_t)bx * 256 * Dn;
        CoutF = g_npc; cstr = NPn; M = Bn; m0 = 0; n0 = bx * 256;
        Nlim = NPn; blim = 256; isS = false;
    } else if (by == 1 && bx == 0) {
        A = g_img; Bp = g_txt;
        CoutF = g_ct; cstr = Bn; M = Bn; m0 = 0; n0 = 0;
        Nlim = Bn; blim = 128; isS = false;
    } else return;

    float acc[4][8][4];
#pragma unroll
    for (int i = 0; i < 4; i++)
#pragma unroll
        for (int j = 0; j < 8; j++)
#pragma unroll
            for (int k = 0; k < 4; k++) acc[i][j][k] = 0.f;

    mma_mainloop<false>(su, A, m0, M, (size_t)Dn, Bp, 0, blim, (size_t)Dn,
                        12, tid, lane, warpM, warpN, acc);

    if (isS) {
        __half* st = (__half*)smem;   // [256][132]
#pragma unroll
        for (int mb = 0; mb < 4; mb++) {
#pragma unroll
            for (int h = 0; h < 2; h++) {
                int ml = warpM * 64 + mb * 16 + (lane >> 2) + h * 8;
                int gr = m0 + ml;
                float ps = 0.f;
#pragma unroll
                for (int nb = 0; nb < 8; nb++) {
                    float lx = lk(acc[mb][nb][h * 2]);
                    float ly = lk(acc[mb][nb][h * 2 + 1]);
                    ps += lx * lx + ly * ly;
                    int nl = warpN * 64 + nb * 8 + (lane & 3) * 2;
                    st[nl * 132 + ml]       = __float2half_rn(lx);
                    st[(nl + 1) * 132 + ml] = __float2half_rn(ly);
                }
                ps += __shfl_xor_sync(0xffffffffu, ps, 1);
                ps += __shfl_xor_sync(0xffffffffu, ps, 2);
                if ((lane & 3) == 0 && gr < M)
                    atomicAdd(&g_norm2[(size_t)bz * Ln + gr], ps);
            }
        }
        __syncthreads();
        int valid = M - m0; if (valid > 128) valid = 128;
#pragma unroll 4
        for (int c = tid; c < 256 * 32; c += 256) {
            int r = c >> 5, ch = c & 31;
            int l = ch * 4;
            __half* dst = g_Yt + ((size_t)bz * NPn + n0 + r) * LP + m0 + l;
            const __half* srcp = st + r * 132 + l;
            if (l + 4 <= valid) {
                *(uint2*)dst = *(const uint2*)srcp;
            } else {
                for (int j = 0; j < 4; j++)
                    if (l + j < valid) dst[j] = srcp[j];
            }
        }
    } else {
#pragma unroll
        for (int mb = 0; mb < 4; mb++) {
#pragma unroll
            for (int h = 0; h < 2; h++) {
                int gr = m0 + warpM * 64 + mb * 16 + (lane >> 2) + h * 8;
                if (gr >= M) continue;
#pragma unroll
                for (int nb = 0; nb < 8; nb++) {
                    int gn = n0 + warpN * 64 + nb * 8 + (lane & 3) * 2;
                    if (gn < Nlim) {
                        float2 v;
                        v.x = acc[mb][nb][h * 2]; v.y = acc[mb][nb][h * 2 + 1];
                        *(float2*)(CoutF + (size_t)gr * cstr + gn) = v;
                    }
                }
            }
        }
    }
}

// ---------------- GEMM2: w_hat = e @ tok; fused ||w||^2 and q.w ----------------
__global__ __launch_bounds__(256, 1) void k_mma2() {
    extern __shared__ char smem[];
    uint32_t su = s2u(smem);
    int tid = threadIdx.x, lane = tid & 31, wid = tid >> 5;
    int warpM = wid & 1, warpN = wid >> 1;
    int bx = blockIdx.x, by = blockIdx.y, bz = blockIdx.z;

    const __nv_bfloat16* A  = (const __nv_bfloat16*)(g_Pt + (size_t)bz * NPn * LP);
    const __nv_bfloat16* Bp = (const __nv_bfloat16*)(g_Tt + (size_t)bz * Dn * LP);
    int m0 = by * 128, n0 = bx * 256;

    float acc[4][8][4];
#pragma unroll
    for (int i = 0; i < 4; i++)
#pragma unroll
        for (int j = 0; j < 8; j++)
#pragma unroll
            for (int k = 0; k < 4; k++) acc[i][j][k] = 0.f;

    mma_mainloop<true>(su, A, m0, NPn, (size_t)LP, Bp, n0, Dn, (size_t)LP,
                       10, tid, lane, warpM, warpN, acc);

#pragma unroll
    for (int mb = 0; mb < 4; mb++) {
#pragma unroll
        for (int h = 0; h < 2; h++) {
            int gr = m0 + warpM * 64 + mb * 16 + (lane >> 2) + h * 8;
            float s = 0.f, nump = 0.f;
#pragma unroll
            for (int nb = 0; nb < 8; nb++) {
                float x = acc[mb][nb][h * 2], y = acc[mb][nb][h * 2 + 1];
                s += x * x + y * y;
                int dcol = n0 + warpN * 64 + nb * 8 + (lane & 3) * 2;
                __nv_bfloat162 q = *(const __nv_bfloat162*)(g_npf + (size_t)gr * Dn + dcol);
                nump += __bfloat162float(q.x) * x + __bfloat162float(q.y) * y;
            }
            s    += __shfl_xor_sync(0xffffffffu, s, 1);
            s    += __shfl_xor_sync(0xffffffffu, s, 2);
            nump += __shfl_xor_sync(0xffffffffu, nump, 1);
            nump += __shfl_xor_sync(0xffffffffu, nump, 2);
            if ((lane & 3) == 0) {
                atomicAdd(&g_wn2[(size_t)bz * NPn + gr], s);
                atomicAdd(&g_num[(size_t)bz * NPn + gr], nump);
            }
        }
    }
}

// ---------------- e-pass: e = schraudolph(y * c + a), streaming ------------------
__global__ __launch_bounds__(256) void k_epass() {
    int b = blockIdx.y;
    int flat = blockIdx.x * 256 + threadIdx.x;   // 0 .. 1024*80-1
    int n = flat / 80, lc = flat % 80;
    size_t off = ((size_t)b * NPn + n) * LP + lc * 8;
    uint4 y = *(const uint4*)(g_Yt + off);
    uint4 c = *(const uint4*)(g_ch + (size_t)b * LP + lc * 8);
    uint4 a = *(const uint4*)(g_ca + lc * 8);
    uint4 r;
    asm("fma.rn.f16x2 %0,%1,%2,%3;" : "=r"(r.x) : "r"(y.x), "r"(c.x), "r"(a.x));
    asm("fma.rn.f16x2 %0,%1,%2,%3;" : "=r"(r.y) : "r"(y.y), "r"(c.y), "r"(a.y));
    asm("fma.rn.f16x2 %0,%1,%2,%3;" : "=r"(r.z) : "r"(y.z), "r"(c.z), "r"(a.z));
    asm("fma.rn.f16x2 %0,%1,%2,%3;" : "=r"(r.w) : "r"(y.w), "r"(c.w), "r"(a.w));
    *(uint4*)(g_Pt + off) = r;
}

// ---------------- init / conversions / transposes ------------------------------
__global__ void k_init(const int* __restrict__ idxr) {
    int gid = blockIdx.x * 256 + threadIdx.x;
    if (gid < Bn * NPn) { g_wn2[gid] = 0.f; g_num[gid] = 0.f; }
    if (gid < Bn * Ln)  g_norm2[gid] = 0.f;
    if (gid < LP) g_ca[gid] = __ushort_as_half(gid < Ln ? (unsigned short)0x7380 : (unsigned short)0);
    if (gid == 0) {
        g_acc = 0.f;
        int any = 0;
        for (int i = 1; i < 1024; i += 2) any |= idxr[i];
        g_idx64 = (any == 0) ? 1 : 0;
    }
}
__device__ __forceinline__ int get_idx(const int* __restrict__ r, int n) {
    return g_idx64 ? r[2 * n] : r[n];
}

__global__ void k_cvt_small(const float* __restrict__ npf, const float* __restrict__ img,
                            const float* __restrict__ txt) {
    int i = (blockIdx.x * 256 + threadIdx.x) * 4;
    const float* src; __nv_bfloat16* dst; int off;
    if (i < NPn * Dn)                    { src = npf; dst = g_npf; off = i; }
    else if (i < NPn * Dn + Bn * Dn)     { src = img; dst = g_img; off = i - NPn * Dn; }
    else if (i < NPn * Dn + 2 * Bn * Dn) { src = txt; dst = g_txt; off = i - NPn * Dn - Bn * Dn; }
    else return;
    float4 v = *(const float4*)(src + off);
    *(__nv_bfloat162*)(dst + off)     = __floats2bfloat162_rn(v.x, v.y);
    *(__nv_bfloat162*)(dst + off + 2) = __floats2bfloat162_rn(v.z, v.w);
}

__global__ void k_cvt_tok(const float* __restrict__ tok) {
    size_t i = ((size_t)blockIdx.x * 256 + threadIdx.x) * 4;
    float4 v = *(const float4*)(tok + i);
    *(__nv_bfloat162*)(g_tok + i)     = __floats2bfloat162_rn(v.x, v.y);
    *(__nv_bfloat162*)(g_tok + i + 2) = __floats2bfloat162_rn(v.z, v.w);
}

__global__ void k_ttok() {
    __shared__ float t[32][33];
    int bz = blockIdx.z;
    int d = blockIdx.x * 32 + threadIdx.x;
    int l = blockIdx.y * 32 + threadIdx.y;
    t[threadIdx.y][threadIdx.x] = (l < Ln)
        ? __bfloat162float(g_tok[(size_t)bz * Ln * Dn + (size_t)l * Dn + d]) : 0.f;
    __syncthreads();
    int dd = blockIdx.x * 32 + threadIdx.y;
    int ll = blockIdx.y * 32 + threadIdx.x;
    g_Tt[(size_t)bz * Dn * LP + (size_t)dd * LP + ll] = __float2half(t[threadIdx.x][threadIdx.y]);
}

__global__ void k_qnorm(const float* __restrict__ npf) {
    int n = blockIdx.x;
    float s = 0.f;
    for (int d = threadIdx.x; d < Dn; d += 256) {
        float v = npf[(size_t)n * Dn + d];
        s += v * v;
    }
    __shared__ float sh[256];
    sh[threadIdx.x] = s; __syncthreads();
    for (int o = 128; o > 0; o >>= 1) {
        if (threadIdx.x < o) sh[threadIdx.x] += sh[threadIdx.x + o];
        __syncthreads();
    }
    if (threadIdx.x == 0) g_qn[n] = sqrtf(sh[0]);
}

__global__ void k_inv() {
    int i = blockIdx.x * 256 + threadIdx.x;
    if (i < Bn * Ln) {
        int b = i / Ln, l = i - b * Ln;
        float inv = 1.f / fmaxf(sqrtf(g_norm2[i]), EPSF);
        float cf = fminf(inv * 5909.2788f, 60000.f);   // 4*log2(e)*1024
        g_ch[b * LP + l] = __float2half_rn(cf);
    }
}

// ---------------- loss reductions ----------------------------------------------
__device__ __forceinline__ void block_acc(float t, float w) {
    __shared__ float sh[256];
    sh[threadIdx.x] = t; __syncthreads();
    for (int o = 128; o > 0; o >>= 1) {
        if (threadIdx.x < o) sh[threadIdx.x] += sh[threadIdx.x + o];
        __syncthreads();
    }
    if (threadIdx.x == 0) atomicAdd(&g_acc, sh[0] * w);
}

__global__ void k_loss_ct(const float* sc, const float* bi) {
    int gid = blockIdx.x * 256 + threadIdx.x;
    float t = 0.f;
    if (gid < Bn * Bn) {
        int i = gid >> 7, j = gid & 127;
        float lg = g_ct[gid] * sc[0] + bi[0];
        float lab = (i == j) ? 1.f : -1.f;
        t = -logsig(lab * lg);
    }
    block_acc(t, 1.0f / Bn);
}

__global__ void k_loss_npc(const float* sc, const float* bi, const int* __restrict__ idxr) {
    int gid = blockIdx.x * 256 + threadIdx.x;
    float t = 0.f;
    if (gid < Bn * NPn) {
        int b = gid >> 10, n = gid & 1023;
        float lab = (get_idx(idxr, n) == b) ? 1.f : -1.f;
        float lg = g_npc[gid] * sc[0] + bi[0];
        t = -logsig(lab * lg);
    }
    block_acc(t, 1.0f / NPn);
}

__global__ void k_loss_xac(const float* sc, const float* bi, const int* __restrict__ idxr) {
    int gid = blockIdx.x * 256 + threadIdx.x;
    float t = 0.f;
    if (gid < Bn * NPn) {
        int b = gid >> 10, n = gid & 1023;
        float wn = sqrtf(g_wn2[gid]);
        float den = fmaxf(g_qn[n] * wn, EPSF);
        float sim = g_num[gid] / den;
        float lg = sim * sc[0] + bi[0];
        float lab = (get_idx(idxr, n) == b) ? 1.f : -1.f;
        t = -logsig(lab * lg);
    }
    block_acc(t, 0.01f / NPn);
}

__global__ void k_final(float* out) { out[0] = g_acc; }

// ---------------- launch ---------------------------------------------------------
extern "C" void kernel_launch(void* const* d_in, const int* in_sizes, int n_in,
                              void* d_out, int out_size) {
    const float* img = (const float*)d_in[0];
    const float* txt = (const float*)d_in[1];
    const float* sc  = (const float*)d_in[2];
    const float* bi  = (const float*)d_in[3];
    const float* npf = (const float*)d_in[4];
    const int*   idx = (const int*)d_in[5];
    const float* tok = (const float*)d_in[6];
    float* out = (float*)d_out;

    cudaFuncSetAttribute(k_mma1, cudaFuncAttributeMaxDynamicSharedMemorySize, SMEM_DYN);
    cudaFuncSetAttribute(k_mma2, cudaFuncAttributeMaxDynamicSharedMemorySize, SMEM_DYN);

    k_init<<<512, 256>>>(idx);
    k_cvt_small<<<960, 256>>>(npf, img, txt);
    k_cvt_tok<<<55392, 256>>>(tok);
    k_qnorm<<<NPn, 256>>>(npf);
    k_ttok<<<dim3(24, 20, 128), dim3(32, 32)>>>();

    k_mma1<<<dim3(4, 5, 129), 256, SMEM_DYN>>>();
    k_inv<<<289, 256>>>();
    k_epass<<<dim3(320, 128), 256>>>();
    k_mma2<<<dim3(3, 8, 128), 256, SMEM_DYN>>>();

    k_loss_ct<<<64, 256>>>(sc, bi);
    k_loss_npc<<<512, 256>>>(sc, bi, idx);
    k_loss_xac<<<512, 256>>>(sc, bi, idx);
    k_final<<<1, 1>>>(out);
}

// round 6
// speedup vs baseline: 9.0076x; 1.0640x over previous
#include <cuda_runtime.h>
#include <cuda_fp16.h>
#include <math.h>
#include <stdint.h>

#define Bn  128
#define Ln  577
#define LP  640
#define Dn  768
#define NPn 1024
#define EPSF 1e-8f
#define STAGE_B 49152
#define SMEM_DYN (3 * STAGE_B)

// ---------------- device scratch ----------------
__device__ __half g_Yt [(size_t)Bn*NPn*LP];   // y = leaky(S), [b][n][l]
__device__ __half g_Pt [(size_t)Bn*NPn*LP];   // e (unnormalized), [b][n][l]
__device__ __half g_Tt [(size_t)Bn*Dn*LP];    // tokens transposed [b][d][l]
__device__ __half g_tok[(size_t)Bn*Ln*Dn];
__device__ __half g_npf[NPn*Dn];
__device__ __half g_img[Bn*Dn];
__device__ __half g_txt[Bn*Dn];
__device__ float  g_norm2[Bn*Ln];
__device__ __half g_ch [Bn*LP];     // per-(b,l) scale c, pad=0
__device__ __half g_ca [LP];        // addend 15360.0 valid l, 0 pad
__device__ float  g_qn  [NPn];
__device__ float  g_num [Bn*NPn];   // sum e*raw  (exact f32, from epass)
__device__ float  g_wn2 [Bn*NPn];   // ||w_hat||^2
__device__ float  g_ct  [Bn*Bn];
__device__ float  g_npc [Bn*NPn];
__device__ float  g_acc;
__device__ int    g_idx64;

__device__ __forceinline__ float lk(float x) { return x >= 0.f ? x : 0.1f * x; }
__device__ __forceinline__ float logsig(float x) {
    return fminf(x, 0.f) - log1pf(expf(-fabsf(x)));
}
__device__ __forceinline__ uint32_t s2u(const void* p) {
    uint32_t a;
    asm("{ .reg .u64 t; cvta.to.shared.u64 t, %1; cvt.u32.u64 %0, t; }" : "=r"(a) : "l"(p));
    return a;
}

// ---------------- cp.async tile loader: ROWS x 64 halfs, SW128 ----------------
template<int ROWS>
__device__ __forceinline__ void cpa_tile(uint32_t dst, const __half* __restrict__ src,
                                         int row0, int row_lim, size_t stride, int k0, int tid) {
#pragma unroll
    for (int i = 0; i < ROWS / 32; i++) {
        int e = tid + (i << 8);
        int r = e >> 3, c = e & 7;
        int gr = row0 + r;
        int sz = 16;
        if (gr >= row_lim) { gr = row_lim - 1; sz = 0; }
        const void* gp = (const void*)(src + (size_t)gr * stride + k0 + (c << 3));
        uint32_t off = (uint32_t)((r << 7) + (c << 4));
        off ^= (off >> 3) & 0x70;
        asm volatile("cp.async.cg.shared.global [%0], [%1], 16, %2;"
                     :: "r"(dst + off), "l"(gp), "r"(sz) : "memory");
    }
}
#define CPA_COMMIT() asm volatile("cp.async.commit_group;" ::: "memory")

// ---------------- warp MMA (f16 acc) over one 128x256x64 SMEM chunk ------------
__device__ __forceinline__ void mma_compute(uint32_t aBase, uint32_t bBase,
                                            int lane, int warpM, int warpN,
                                            uint32_t (&acc)[4][8][2]) {
#pragma unroll
    for (int ks = 0; ks < 4; ks++) {
        uint32_t a[4][4];
#pragma unroll
        for (int mb = 0; mb < 4; mb++) {
            int row = warpM * 64 + mb * 16 + (lane & 15);
            uint32_t byte = (uint32_t)(ks * 32 + ((lane >> 4) << 4));
            uint32_t off = (uint32_t)(row << 7) + byte;
            off ^= (off >> 3) & 0x70;
            asm volatile("ldmatrix.sync.aligned.m8n8.x4.shared.b16 {%0,%1,%2,%3}, [%4];"
                         : "=r"(a[mb][0]), "=r"(a[mb][1]), "=r"(a[mb][2]), "=r"(a[mb][3])
                         : "r"(aBase + off));
        }
        uint32_t b[8][2];
#pragma unroll
        for (int g = 0; g < 4; g++) {
            int row = warpN * 64 + g * 16 + (lane & 7) + ((lane >> 4) << 3);
            uint32_t byte = (uint32_t)(ks * 32 + ((lane & 8) ? 16 : 0));
            uint32_t off = (uint32_t)(row << 7) + byte;
            off ^= (off >> 3) & 0x70;
            uint32_t r0, r1, r2, r3;
            asm volatile("ldmatrix.sync.aligned.m8n8.x4.shared.b16 {%0,%1,%2,%3}, [%4];"
                         : "=r"(r0), "=r"(r1), "=r"(r2), "=r"(r3)
                         : "r"(bBase + off));
            b[g * 2][0] = r0; b[g * 2][1] = r1;
            b[g * 2 + 1][0] = r2; b[g * 2 + 1][1] = r3;
        }
#pragma unroll
        for (int mb = 0; mb < 4; mb++)
#pragma unroll
            for (int nb = 0; nb < 8; nb++)
                asm volatile(
                    "mma.sync.aligned.m16n8k16.row.col.f16.f16.f16.f16 "
                    "{%0,%1},{%2,%3,%4,%5},{%6,%7},{%0,%1};"
                    : "+r"(acc[mb][nb][0]), "+r"(acc[mb][nb][1])
                    : "r"(a[mb][0]), "r"(a[mb][1]), "r"(a[mb][2]), "r"(a[mb][3]),
                      "r"(b[nb][0]), "r"(b[nb][1]));
    }
}

// ---------------- 3-stage pipelined mainloop -----------------------------------
__device__ __forceinline__ void mma_mainloop(uint32_t su,
    const __half* A, int arow0, int alim, size_t astr,
    const __half* Bp, int brow0, int blim, size_t bstr,
    int nK, int tid, int lane, int warpM, int warpN, uint32_t (&acc)[4][8][2]) {
    cpa_tile<128>(su,         A,  arow0, alim, astr, 0, tid);
    cpa_tile<256>(su + 16384, Bp, brow0, blim, bstr, 0, tid);
    CPA_COMMIT();
    cpa_tile<128>(su + STAGE_B,         A,  arow0, alim, astr, 64, tid);
    cpa_tile<256>(su + STAGE_B + 16384, Bp, brow0, blim, bstr, 64, tid);
    CPA_COMMIT();
    for (int it = 0; it < nK; ++it) {
        if (it < nK - 1) asm volatile("cp.async.wait_group 1;" ::: "memory");
        else             asm volatile("cp.async.wait_group 0;" ::: "memory");
        __syncthreads();
        if (it + 2 < nK) {
            uint32_t nb = su + (uint32_t)(((it + 2) % 3) * STAGE_B);
            cpa_tile<128>(nb,         A,  arow0, alim, astr, (it + 2) * 64, tid);
            cpa_tile<256>(nb + 16384, Bp, brow0, blim, bstr, (it + 2) * 64, tid);
            CPA_COMMIT();
        }
        uint32_t base = su + (uint32_t)((it % 3) * STAGE_B);
        mma_compute(base, base + 16384, lane, warpM, warpN, acc);
    }
    __syncthreads();
}

// ---------------- GEMM1: y = lk(tok @ npf^T), transposed out (+ npc/ct) --------
__global__ __launch_bounds__(256, 1) void k_mma1() {
    extern __shared__ char smem[];
    uint32_t su = s2u(smem);
    int tid = threadIdx.x, lane = tid & 31, wid = tid >> 5;
    int warpM = wid & 1, warpN = wid >> 1;
    int bx = blockIdx.x, by = blockIdx.y, bz = blockIdx.z;

    const __half *A, *Bp;
    float* CoutF = 0;
    size_t cstr = 0; int M, m0, n0, Nlim = 0, blim; bool isS;
    if (bz < Bn) {
        A = g_tok + (size_t)bz * Ln * Dn;
        Bp = g_npf + (size_t)bx * 256 * Dn;
        M = Ln; m0 = by * 128; n0 = bx * 256; blim = 256; isS = true;
    } else if (by == 0) {
        A = g_img; Bp = g_npf + (size_t)bx * 256 * Dn;
        CoutF = g_npc; cstr = NPn; M = Bn; m0 = 0; n0 = bx * 256;
        Nlim = NPn; blim = 256; isS = false;
    } else if (by == 1 && bx == 0) {
        A = g_img; Bp = g_txt;
        CoutF = g_ct; cstr = Bn; M = Bn; m0 = 0; n0 = 0;
        Nlim = Bn; blim = 128; isS = false;
    } else return;

    uint32_t acc[4][8][2];
#pragma unroll
    for (int i = 0; i < 4; i++)
#pragma unroll
        for (int j = 0; j < 8; j++) { acc[i][j][0] = 0u; acc[i][j][1] = 0u; }

    mma_mainloop(su, A, m0, M, (size_t)Dn, Bp, 0, blim, (size_t)Dn,
                 12, tid, lane, warpM, warpN, acc);

    if (isS) {
        __half* st = (__half*)smem;   // [256][132]
#pragma unroll
        for (int mb = 0; mb < 4; mb++) {
#pragma unroll
            for (int h = 0; h < 2; h++) {
                int ml = warpM * 64 + mb * 16 + (lane >> 2) + h * 8;
                int gr = m0 + ml;
                float ps = 0.f;
#pragma unroll
                for (int nb = 0; nb < 8; nb++) {
                    __half2 hv = *(__half2*)&acc[mb][nb][h];
                    float lx = lk(__half2float(hv.x));
                    float ly = lk(__half2float(hv.y));
                    ps += lx * lx + ly * ly;
                    int nl = warpN * 64 + nb * 8 + (lane & 3) * 2;
                    st[nl * 132 + ml]       = __float2half_rn(lx);
                    st[(nl + 1) * 132 + ml] = __float2half_rn(ly);
                }
                ps += __shfl_xor_sync(0xffffffffu, ps, 1);
                ps += __shfl_xor_sync(0xffffffffu, ps, 2);
                if ((lane & 3) == 0 && gr < M)
                    atomicAdd(&g_norm2[(size_t)bz * Ln + gr], ps);
            }
        }
        __syncthreads();
        int valid = M - m0; if (valid > 128) valid = 128;
#pragma unroll 4
        for (int c = tid; c < 256 * 32; c += 256) {
            int r = c >> 5, ch = c & 31;
            int l = ch * 4;
            __half* dst = g_Yt + ((size_t)bz * NPn + n0 + r) * LP + m0 + l;
            const __half* srcp = st + r * 132 + l;
            if (l + 4 <= valid) {
                *(uint2*)dst = *(const uint2*)srcp;
            } else {
                for (int j = 0; j < 4; j++)
                    if (l + j < valid) dst[j] = srcp[j];
            }
        }
    } else {
#pragma unroll
        for (int mb = 0; mb < 4; mb++) {
#pragma unroll
            for (int h = 0; h < 2; h++) {
                int gr = m0 + warpM * 64 + mb * 16 + (lane >> 2) + h * 8;
                if (gr >= M) continue;
#pragma unroll
                for (int nb = 0; nb < 8; nb++) {
                    int gn = n0 + warpN * 64 + nb * 8 + (lane & 3) * 2;
                    if (gn < Nlim) {
                        __half2 hv = *(__half2*)&acc[mb][nb][h];
                        float2 v;
                        v.x = __half2float(hv.x); v.y = __half2float(hv.y);
                        *(float2*)(CoutF + (size_t)gr * cstr + gn) = v;
                    }
                }
            }
        }
    }
}

// ---------------- GEMM2: w_hat = e @ tok; fused ||w_hat||^2 --------------------
__global__ __launch_bounds__(256, 1) void k_mma2() {
    extern __shared__ char smem[];
    uint32_t su = s2u(smem);
    int tid = threadIdx.x, lane = tid & 31, wid = tid >> 5;
    int warpM = wid & 1, warpN = wid >> 1;
    int bx = blockIdx.x, by = blockIdx.y, bz = blockIdx.z;

    const __half* A  = g_Pt + (size_t)bz * NPn * LP;
    const __half* Bp = g_Tt + (size_t)bz * Dn * LP;
    int m0 = by * 128, n0 = bx * 256;

    uint32_t acc[4][8][2];
#pragma unroll
    for (int i = 0; i < 4; i++)
#pragma unroll
        for (int j = 0; j < 8; j++) { acc[i][j][0] = 0u; acc[i][j][1] = 0u; }

    mma_mainloop(su, A, m0, NPn, (size_t)LP, Bp, n0, Dn, (size_t)LP,
                 10, tid, lane, warpM, warpN, acc);

#pragma unroll
    for (int mb = 0; mb < 4; mb++) {
#pragma unroll
        for (int h = 0; h < 2; h++) {
            int gr = m0 + warpM * 64 + mb * 16 + (lane >> 2) + h * 8;
            float s = 0.f;
#pragma unroll
            for (int nb = 0; nb < 8; nb++) {
                __half2 hv = *(__half2*)&acc[mb][nb][h];
                float x = __half2float(hv.x), y = __half2float(hv.y);
                s += x * x + y * y;
            }
            s += __shfl_xor_sync(0xffffffffu, s, 1);
            s += __shfl_xor_sync(0xffffffffu, s, 2);
            if ((lane & 3) == 0)
                atomicAdd(&g_wn2[(size_t)bz * NPn + gr], s);
        }
    }
}

// ---------------- e-pass: warp per (b,n) row; e = schraudolph; num = sum e*raw --
__global__ __launch_bounds__(256) void k_epass() {
    int warp = (blockIdx.x << 3) + (threadIdx.x >> 5);   // 0 .. 131071
    int lane = threadIdx.x & 31;
    int b = warp >> 10, n = warp & 1023;
    const uint2* Y  = (const uint2*)(g_Yt + ((size_t)b * NPn + n) * LP);
    uint2*       P  = (uint2*)(g_Pt + ((size_t)b * NPn + n) * LP);
    const uint2* C  = (const uint2*)(g_ch + (size_t)b * LP);
    const uint2* A2 = (const uint2*)g_ca;
    float num = 0.f;
#pragma unroll
    for (int k = 0; k < 5; k++) {
        int idx = lane + (k << 5);
        uint2 y = Y[idx], c = C[idx], a = A2[idx], r;
        asm("fma.rn.f16x2 %0,%1,%2,%3;" : "=r"(r.x) : "r"(y.x), "r"(c.x), "r"(a.x));
        asm("fma.rn.f16x2 %0,%1,%2,%3;" : "=r"(r.y) : "r"(y.y), "r"(c.y), "r"(a.y));
        P[idx] = r;
        __half2 yv0 = *(__half2*)&y.x, yv1 = *(__half2*)&y.y;
        __half2 ev0 = *(__half2*)&r.x, ev1 = *(__half2*)&r.y;
        float y0 = __half2float(yv0.x), y1 = __half2float(yv0.y);
        float y2 = __half2float(yv1.x), y3 = __half2float(yv1.y);
        float r0 = (y0 < 0.f) ? 10.f * y0 : y0;
        float r1 = (y1 < 0.f) ? 10.f * y1 : y1;
        float r2 = (y2 < 0.f) ? 10.f * y2 : y2;
        float r3 = (y3 < 0.f) ? 10.f * y3 : y3;
        num += __half2float(ev0.x) * r0 + __half2float(ev0.y) * r1
             + __half2float(ev1.x) * r2 + __half2float(ev1.y) * r3;
    }
#pragma unroll
    for (int o = 16; o > 0; o >>= 1)
        num += __shfl_xor_sync(0xffffffffu, num, o);
    if (lane == 0) g_num[(size_t)b * NPn + n] = num;
}

// ---------------- init ----------------------------------------------------------
__global__ void k_init(const int* __restrict__ idxr) {
    int gid = blockIdx.x * 256 + threadIdx.x;
    if (gid < Bn * NPn) g_wn2[gid] = 0.f;
    if (gid < Bn * Ln)  g_norm2[gid] = 0.f;
    if (gid < LP) g_ca[gid] = __ushort_as_half(gid < Ln ? (unsigned short)0x7380
                                                        : (unsigned short)0);
    if (gid == 0) {
        g_acc = 0.f;
        int any = 0;
        for (int i = 1; i < 1024; i += 2) any |= idxr[i];
        g_idx64 = (any == 0) ? 1 : 0;
    }
}
__device__ __forceinline__ int get_idx(const int* __restrict__ r, int n) {
    return g_idx64 ? r[2 * n] : r[n];
}

// ---------------- convert npf (+ fused q-norm) ----------------------------------
__global__ __launch_bounds__(256) void k_cvt_np(const float* __restrict__ npf) {
    int n = blockIdx.x, t = threadIdx.x;
    const float* src = npf + (size_t)n * Dn;
    __half* dst = g_npf + (size_t)n * Dn;
    float s = 0.f;
#pragma unroll
    for (int i = 0; i < 3; i++) {
        float v = src[t + i * 256];
        dst[t + i * 256] = __float2half(v);
        s += v * v;
    }
    __shared__ float sh[256];
    sh[t] = s; __syncthreads();
    for (int o = 128; o > 0; o >>= 1) {
        if (t < o) sh[t] += sh[t + o];
        __syncthreads();
    }
    if (t == 0) g_qn[n] = sqrtf(sh[0]);
}

// ---------------- convert img/txt -----------------------------------------------
__global__ void k_cvt_it(const float* __restrict__ img, const float* __restrict__ txt) {
    int i = (blockIdx.x * 256 + threadIdx.x) * 4;
    const float* src; __half* dst; int off;
    if (i < Bn * Dn)          { src = img; dst = g_img; off = i; }
    else if (i < 2 * Bn * Dn) { src = txt; dst = g_txt; off = i - Bn * Dn; }
    else return;
    float4 v = *(const float4*)(src + off);
    dst[off] = __float2half(v.x); dst[off + 1] = __float2half(v.y);
    dst[off + 2] = __float2half(v.z); dst[off + 3] = __float2half(v.w);
}

// ---------------- fused convert + transpose of tokens ---------------------------
__global__ void k_ttk(const float* __restrict__ tok) {
    __shared__ float t[32][33];
    int bz = blockIdx.z;
    int d = blockIdx.x * 32 + threadIdx.x;
    int l = blockIdx.y * 32 + threadIdx.y;
    float v = (l < Ln) ? tok[(size_t)bz * Ln * Dn + (size_t)l * Dn + d] : 0.f;
    t[threadIdx.y][threadIdx.x] = v;
    if (l < Ln) g_tok[(size_t)bz * Ln * Dn + (size_t)l * Dn + d] = __float2half(v);
    __syncthreads();
    int dd = blockIdx.x * 32 + threadIdx.y;
    int ll = blockIdx.y * 32 + threadIdx.x;
    g_Tt[(size_t)bz * Dn * LP + (size_t)dd * LP + ll] = __float2half(t[threadIdx.x][threadIdx.y]);
}

// ---------------- inv norm -> fp16 scale ----------------------------------------
__global__ void k_inv() {
    int i = blockIdx.x * 256 + threadIdx.x;
    if (i < Bn * Ln) {
        int b = i / Ln, l = i - b * Ln;
        float inv = 1.f / fmaxf(sqrtf(g_norm2[i]), EPSF);
        float cf = fminf(inv * 5909.2788f, 60000.f);   // 4*log2(e)*1024
        g_ch[b * LP + l] = __float2half_rn(cf);
    }
}

// ---------------- merged loss reduction -----------------------------------------
__global__ void k_loss(const float* sc, const float* bi, const int* __restrict__ idxr) {
    int gid = blockIdx.x * 256 + threadIdx.x;
    float t = 0.f;
    if (gid < Bn * Bn) {
        int i = gid >> 7, j = gid & 127;
        float lg = g_ct[gid] * sc[0] + bi[0];
        float lab = (i == j) ? 1.f : -1.f;
        t = -logsig(lab * lg) * (1.0f / Bn);
    } else if (gid < Bn * Bn + Bn * NPn) {
        int g2 = gid - Bn * Bn;
        int b = g2 >> 10, n = g2 & 1023;
        float lab = (get_idx(idxr, n) == b) ? 1.f : -1.f;
        float lg = g_npc[g2] * sc[0] + bi[0];
        t = -logsig(lab * lg) * (1.0f / NPn);
    } else if (gid < Bn * Bn + 2 * Bn * NPn) {
        int g2 = gid - Bn * Bn - Bn * NPn;
        int b = g2 >> 10, n = g2 & 1023;
        float wn = sqrtf(g_wn2[g2]);
        float den = fmaxf(g_qn[n] * wn, EPSF);
        float sim = g_num[g2] / den;
        float lg = sim * sc[0] + bi[0];
        float lab = (get_idx(idxr, n) == b) ? 1.f : -1.f;
        t = -logsig(lab * lg) * (0.01f / NPn);
    }
    __shared__ float sh[256];
    sh[threadIdx.x] = t; __syncthreads();
    for (int o = 128; o > 0; o >>= 1) {
        if (threadIdx.x < o) sh[threadIdx.x] += sh[threadIdx.x + o];
        __syncthreads();
    }
    if (threadIdx.x == 0) atomicAdd(&g_acc, sh[0]);
}

__global__ void k_final(float* out) { out[0] = g_acc; }

// ---------------- launch ---------------------------------------------------------
extern "C" void kernel_launch(void* const* d_in, const int* in_sizes, int n_in,
                              void* d_out, int out_size) {
    const float* img = (const float*)d_in[0];
    const float* txt = (const float*)d_in[1];
    const float* sc  = (const float*)d_in[2];
    const float* bi  = (const float*)d_in[3];
    const float* npf = (const float*)d_in[4];
    const int*   idx = (const int*)d_in[5];
    const float* tok = (const float*)d_in[6];
    float* out = (float*)d_out;

    cudaFuncSetAttribute(k_mma1, cudaFuncAttributeMaxDynamicSharedMemorySize, SMEM_DYN);
    cudaFuncSetAttribute(k_mma2, cudaFuncAttributeMaxDynamicSharedMemorySize, SMEM_DYN);

    k_init<<<512, 256>>>(idx);
    k_cvt_np<<<NPn, 256>>>(npf);
    k_cvt_it<<<192, 256>>>(img, txt);
    k_ttk<<<dim3(24, 20, 128), dim3(32, 32)>>>(tok);

    k_mma1<<<dim3(4, 5, 129), 256, SMEM_DYN>>>();
    k_inv<<<289, 256>>>();
    k_epass<<<16384, 256>>>();
    k_mma2<<<dim3(3, 8, 128), 256, SMEM_DYN>>>();

    k_loss<<<1088, 256>>>(sc, bi, idx);
    k_final<<<1, 1>>>(out);
}

// round 7
// speedup vs baseline: 11.6164x; 1.2896x over previous
#include <cuda_runtime.h>
#include <cuda_fp16.h>
#include <math.h>
#include <stdint.h>

#define Bn  128
#define Ln  577
#define LP  640
#define Dn  768
#define NPn 1024
#define EPSF 1e-8f
#define STAGE_B 49152
#define SMEM_DYN (3 * STAGE_B)

// ---------------- device scratch ----------------
__device__ __half g_Yt [(size_t)Bn*NPn*LP];   // y = leaky(S), [b][n][l]
__device__ __half g_Pt [(size_t)Bn*NPn*LP];   // e (unnormalized), [b][n][l]
__device__ __half g_tok[(size_t)Bn*Ln*Dn];    // tokens fp16, [b][l][d]
__device__ __half g_npf[NPn*Dn];
__device__ __half g_img[Bn*Dn];
__device__ __half g_txt[Bn*Dn];
__device__ float  g_norm2[Bn*Ln];
__device__ __half g_ch [Bn*LP];     // per-(b,l) scale c, pad=0
__device__ __half g_ca [LP];        // addend 15360.0 valid l, 0 pad
__device__ float  g_qn  [NPn];
__device__ float  g_num [Bn*NPn];   // sum e*raw
__device__ float  g_wn2 [Bn*NPn];   // ||w_hat||^2
__device__ float  g_ct  [Bn*Bn];
__device__ float  g_npc [Bn*NPn];
__device__ float  g_acc;
__device__ int    g_idx64;

__device__ __forceinline__ float lk(float x) { return x >= 0.f ? x : 0.1f * x; }
__device__ __forceinline__ float logsig(float x) {
    return fminf(x, 0.f) - log1pf(expf(-fabsf(x)));
}
__device__ __forceinline__ uint32_t s2u(const void* p) {
    uint32_t a;
    asm("{ .reg .u64 t; cvta.to.shared.u64 t, %1; cvt.u32.u64 %0, t; }" : "=r"(a) : "l"(p));
    return a;
}

// -------- cp.async K-major tile: ROWS x 64 halfs, SW128 swizzle ---------------
template<int ROWS>
__device__ __forceinline__ void cpa_tile(uint32_t dst, const __half* __restrict__ src,
                                         int row0, int row_lim, size_t stride, int k0, int tid) {
#pragma unroll
    for (int i = 0; i < ROWS / 32; i++) {
        int e = tid + (i << 8);
        int r = e >> 3, c = e & 7;
        int gr = row0 + r;
        int sz = 16;
        if (gr >= row_lim) { gr = row_lim - 1; sz = 0; }
        const void* gp = (const void*)(src + (size_t)gr * stride + k0 + (c << 3));
        uint32_t off = (uint32_t)((r << 7) + (c << 4));
        off ^= (off >> 3) & 0x70;
        asm volatile("cp.async.cg.shared.global [%0], [%1], 16, %2;"
                     :: "r"(dst + off), "l"(gp), "r"(sz) : "memory");
    }
}
// -------- cp.async MN-major tile: 64 rows(l) x 256 halfs(d), per-row XOR ------
__device__ __forceinline__ void cpa_tile_tr(uint32_t dst, const __half* __restrict__ src,
                                            int row0, int row_lim, size_t stride, int tid) {
#pragma unroll
    for (int i = 0; i < 8; i++) {
        int e = tid + (i << 8);
        int r = e >> 5, c = e & 31;
        int gr = row0 + r;
        int sz = 16;
        if (gr >= row_lim) { gr = row_lim - 1; sz = 0; }
        const void* gp = (const void*)(src + (size_t)gr * stride + (c << 3));
        uint32_t phys = (uint32_t)(r << 9) + ((uint32_t)(c << 4) ^ ((uint32_t)(r & 7) << 4));
        asm volatile("cp.async.cg.shared.global [%0], [%1], 16, %2;"
                     :: "r"(dst + phys), "l"(gp), "r"(sz) : "memory");
    }
}
#define CPA_COMMIT() asm volatile("cp.async.commit_group;" ::: "memory")

// ---------------- warp MMA (f16 acc) over one 128x256x64 SMEM chunk ------------
template<bool TRANSB>
__device__ __forceinline__ void mma_compute(uint32_t aBase, uint32_t bBase,
                                            int lane, int warpM, int warpN,
                                            uint32_t (&acc)[4][8][2]) {
#pragma unroll
    for (int ks = 0; ks < 4; ks++) {
        uint32_t a[4][4];
#pragma unroll
        for (int mb = 0; mb < 4; mb++) {
            int row = warpM * 64 + mb * 16 + (lane & 15);
            uint32_t byte = (uint32_t)(ks * 32 + ((lane >> 4) << 4));
            uint32_t off = (uint32_t)(row << 7) + byte;
            off ^= (off >> 3) & 0x70;
            asm volatile("ldmatrix.sync.aligned.m8n8.x4.shared.b16 {%0,%1,%2,%3}, [%4];"
                         : "=r"(a[mb][0]), "=r"(a[mb][1]), "=r"(a[mb][2]), "=r"(a[mb][3])
                         : "r"(aBase + off));
        }
        uint32_t b[8][2];
        if (!TRANSB) {
#pragma unroll
            for (int g = 0; g < 4; g++) {
                int row = warpN * 64 + g * 16 + (lane & 7) + ((lane >> 4) << 3);
                uint32_t byte = (uint32_t)(ks * 32 + ((lane & 8) ? 16 : 0));
                uint32_t off = (uint32_t)(row << 7) + byte;
                off ^= (off >> 3) & 0x70;
                uint32_t r0, r1, r2, r3;
                asm volatile("ldmatrix.sync.aligned.m8n8.x4.shared.b16 {%0,%1,%2,%3}, [%4];"
                             : "=r"(r0), "=r"(r1), "=r"(r2), "=r"(r3)
                             : "r"(bBase + off));
                b[g * 2][0] = r0; b[g * 2][1] = r1;
                b[g * 2 + 1][0] = r2; b[g * 2 + 1][1] = r3;
            }
        } else {
#pragma unroll
            for (int g = 0; g < 4; g++) {
                int row = ks * 16 + (lane & 15);                       // l row
                uint32_t bir = (uint32_t)(warpN * 128 + g * 32 + ((lane >> 4) << 4));
                uint32_t phys = (uint32_t)(row << 9) + (bir ^ ((uint32_t)(row & 7) << 4));
                uint32_t r0, r1, r2, r3;
                asm volatile("ldmatrix.sync.aligned.m8n8.x4.trans.shared.b16 {%0,%1,%2,%3}, [%4];"
                             : "=r"(r0), "=r"(r1), "=r"(r2), "=r"(r3)
                             : "r"(bBase + phys));
                b[g * 2][0] = r0; b[g * 2][1] = r1;
                b[g * 2 + 1][0] = r2; b[g * 2 + 1][1] = r3;
            }
        }
#pragma unroll
        for (int mb = 0; mb < 4; mb++)
#pragma unroll
            for (int nb = 0; nb < 8; nb++)
                asm volatile(
                    "mma.sync.aligned.m16n8k16.row.col.f16.f16.f16.f16 "
                    "{%0,%1},{%2,%3,%4,%5},{%6,%7},{%0,%1};"
                    : "+r"(acc[mb][nb][0]), "+r"(acc[mb][nb][1])
                    : "r"(a[mb][0]), "r"(a[mb][1]), "r"(a[mb][2]), "r"(a[mb][3]),
                      "r"(b[nb][0]), "r"(b[nb][1]));
    }
}

// ---------------- 3-stage pipelined mainloop -----------------------------------
// TRANSB=false: B = K-major rows [n][k], brow0 fixed, K advances columns.
// TRANSB=true:  B = MN-major rows [l][d] (src pre-offset to d0), K advances rows.
template<bool TRANSB>
__device__ __forceinline__ void mma_mainloop(uint32_t su,
    const __half* A, int arow0, int alim, size_t astr,
    const __half* Bp, int brow0, int blim, size_t bstr,
    int nK, int tid, int lane, int warpM, int warpN, uint32_t (&acc)[4][8][2]) {
#pragma unroll 1
    for (int pre = 0; pre < 2; pre++) {
        uint32_t st = su + (uint32_t)(pre * STAGE_B);
        cpa_tile<128>(st, A, arow0, alim, astr, pre * 64, tid);
        if (!TRANSB) cpa_tile<256>(st + 16384, Bp, brow0, blim, bstr, pre * 64, tid);
        else         cpa_tile_tr (st + 16384, Bp, pre * 64, blim, bstr, tid);
        CPA_COMMIT();
    }
    for (int it = 0; it < nK; ++it) {
        if (it < nK - 1) asm volatile("cp.async.wait_group 1;" ::: "memory");
        else             asm volatile("cp.async.wait_group 0;" ::: "memory");
        __syncthreads();
        if (it + 2 < nK) {
            uint32_t nb = su + (uint32_t)(((it + 2) % 3) * STAGE_B);
            cpa_tile<128>(nb, A, arow0, alim, astr, (it + 2) * 64, tid);
            if (!TRANSB) cpa_tile<256>(nb + 16384, Bp, brow0, blim, bstr, (it + 2) * 64, tid);
            else         cpa_tile_tr (nb + 16384, Bp, (it + 2) * 64, blim, bstr, tid);
            CPA_COMMIT();
        }
        uint32_t base = su + (uint32_t)((it % 3) * STAGE_B);
        mma_compute<TRANSB>(base, base + 16384, lane, warpM, warpN, acc);
    }
    __syncthreads();
}

// ---------------- GEMM1: y = lk(tok @ npf^T), transposed out (+ npc/ct) --------
__global__ __launch_bounds__(256, 1) void k_mma1() {
    extern __shared__ char smem[];
    uint32_t su = s2u(smem);
    int tid = threadIdx.x, lane = tid & 31, wid = tid >> 5;
    int warpM = wid & 1, warpN = wid >> 1;
    int bx = blockIdx.x, by = blockIdx.y, bz = blockIdx.z;

    const __half *A, *Bp;
    float* CoutF = 0;
    size_t cstr = 0; int M, m0, n0, Nlim = 0, blim; bool isS;
    if (bz < Bn) {
        A = g_tok + (size_t)bz * Ln * Dn;
        Bp = g_npf + (size_t)bx * 256 * Dn;
        M = Ln; m0 = by * 128; n0 = bx * 256; blim = 256; isS = true;
    } else if (by == 0) {
        A = g_img; Bp = g_npf + (size_t)bx * 256 * Dn;
        CoutF = g_npc; cstr = NPn; M = Bn; m0 = 0; n0 = bx * 256;
        Nlim = NPn; blim = 256; isS = false;
    } else if (by == 1 && bx == 0) {
        A = g_img; Bp = g_txt;
        CoutF = g_ct; cstr = Bn; M = Bn; m0 = 0; n0 = 0;
        Nlim = Bn; blim = 128; isS = false;
    } else return;

    uint32_t acc[4][8][2];
#pragma unroll
    for (int i = 0; i < 4; i++)
#pragma unroll
        for (int j = 0; j < 8; j++) { acc[i][j][0] = 0u; acc[i][j][1] = 0u; }

    mma_mainloop<false>(su, A, m0, M, (size_t)Dn, Bp, 0, blim, (size_t)Dn,
                        12, tid, lane, warpM, warpN, acc);

    if (isS) {
        __half* st = (__half*)smem;   // [256][132]
#pragma unroll
        for (int mb = 0; mb < 4; mb++) {
#pragma unroll
            for (int h = 0; h < 2; h++) {
                int ml = warpM * 64 + mb * 16 + (lane >> 2) + h * 8;
                int gr = m0 + ml;
                float ps = 0.f;
#pragma unroll
                for (int nb = 0; nb < 8; nb++) {
                    __half2 hv = *(__half2*)&acc[mb][nb][h];
                    float lx = lk(__half2float(hv.x));
                    float ly = lk(__half2float(hv.y));
                    ps += lx * lx + ly * ly;
                    int nl = warpN * 64 + nb * 8 + (lane & 3) * 2;
                    st[nl * 132 + ml]       = __float2half_rn(lx);
                    st[(nl + 1) * 132 + ml] = __float2half_rn(ly);
                }
                ps += __shfl_xor_sync(0xffffffffu, ps, 1);
                ps += __shfl_xor_sync(0xffffffffu, ps, 2);
                if ((lane & 3) == 0 && gr < M)
                    atomicAdd(&g_norm2[(size_t)bz * Ln + gr], ps);
            }
        }
        __syncthreads();
        int valid = M - m0; if (valid > 128) valid = 128;
#pragma unroll 4
        for (int c = tid; c < 256 * 32; c += 256) {
            int r = c >> 5, ch = c & 31;
            int l = ch * 4;
            __half* dst = g_Yt + ((size_t)bz * NPn + n0 + r) * LP + m0 + l;
            const __half* srcp = st + r * 132 + l;
            if (l + 4 <= valid) {
                *(uint2*)dst = *(const uint2*)srcp;
            } else {
                for (int j = 0; j < 4; j++)
                    if (l + j < valid) dst[j] = srcp[j];
            }
        }
    } else {
#pragma unroll
        for (int mb = 0; mb < 4; mb++) {
#pragma unroll
            for (int h = 0; h < 2; h++) {
                int gr = m0 + warpM * 64 + mb * 16 + (lane >> 2) + h * 8;
                if (gr >= M) continue;
#pragma unroll
                for (int nb = 0; nb < 8; nb++) {
                    int gn = n0 + warpN * 64 + nb * 8 + (lane & 3) * 2;
                    if (gn < Nlim) {
                        __half2 hv = *(__half2*)&acc[mb][nb][h];
                        float2 v;
                        v.x = __half2float(hv.x); v.y = __half2float(hv.y);
                        *(float2*)(CoutF + (size_t)gr * cstr + gn) = v;
                    }
                }
            }
        }
    }
}

// ---------------- GEMM2: w_hat = e @ tok (B via ldmatrix.trans); ||w||^2 -------
__global__ __launch_bounds__(256, 1) void k_mma2() {
    extern __shared__ char smem[];
    uint32_t su = s2u(smem);
    int tid = threadIdx.x, lane = tid & 31, wid = tid >> 5;
    int warpM = wid & 1, warpN = wid >> 1;
    int bx = blockIdx.x, by = blockIdx.y, bz = blockIdx.z;

    const __half* A  = g_Pt + (size_t)bz * NPn * LP;
    const __half* Bp = g_tok + (size_t)bz * Ln * Dn + bx * 256;  // pre-offset d0
    int m0 = by * 128;

    uint32_t acc[4][8][2];
#pragma unroll
    for (int i = 0; i < 4; i++)
#pragma unroll
        for (int j = 0; j < 8; j++) { acc[i][j][0] = 0u; acc[i][j][1] = 0u; }

    mma_mainloop<true>(su, A, m0, NPn, (size_t)LP, Bp, 0, Ln, (size_t)Dn,
                       10, tid, lane, warpM, warpN, acc);

#pragma unroll
    for (int mb = 0; mb < 4; mb++) {
#pragma unroll
        for (int h = 0; h < 2; h++) {
            int gr = m0 + warpM * 64 + mb * 16 + (lane >> 2) + h * 8;
            float s = 0.f;
#pragma unroll
            for (int nb = 0; nb < 8; nb++) {
                __half2 hv = *(__half2*)&acc[mb][nb][h];
                float x = __half2float(hv.x), y = __half2float(hv.y);
                s += x * x + y * y;
            }
            s += __shfl_xor_sync(0xffffffffu, s, 1);
            s += __shfl_xor_sync(0xffffffffu, s, 2);
            if ((lane & 3) == 0)
                atomicAdd(&g_wn2[(size_t)bz * NPn + gr], s);
        }
    }
}

// ---------------- e-pass: warp per (b,n) row; e = schraudolph; num = sum e*raw --
__global__ __launch_bounds__(256) void k_epass() {
    int warp = (blockIdx.x << 3) + (threadIdx.x >> 5);   // 0 .. 131071
    int lane = threadIdx.x & 31;
    int b = warp >> 10, n = warp & 1023;
    const uint2* Y  = (const uint2*)(g_Yt + ((size_t)b * NPn + n) * LP);
    uint2*       P  = (uint2*)(g_Pt + ((size_t)b * NPn + n) * LP);
    const uint2* C  = (const uint2*)(g_ch + (size_t)b * LP);
    const uint2* A2 = (const uint2*)g_ca;
    float num = 0.f;
#pragma unroll
    for (int k = 0; k < 5; k++) {
        int idx = lane + (k << 5);
        uint2 y = Y[idx], c = C[idx], a = A2[idx], r;
        asm("fma.rn.f16x2 %0,%1,%2,%3;" : "=r"(r.x) : "r"(y.x), "r"(c.x), "r"(a.x));
        asm("fma.rn.f16x2 %0,%1,%2,%3;" : "=r"(r.y) : "r"(y.y), "r"(c.y), "r"(a.y));
        P[idx] = r;
        __half2 yv0 = *(__half2*)&y.x, yv1 = *(__half2*)&y.y;
        __half2 ev0 = *(__half2*)&r.x, ev1 = *(__half2*)&r.y;
        float y0 = __half2float(yv0.x), y1 = __half2float(yv0.y);
        float y2 = __half2float(yv1.x), y3 = __half2float(yv1.y);
        float r0 = (y0 < 0.f) ? 10.f * y0 : y0;
        float r1 = (y1 < 0.f) ? 10.f * y1 : y1;
        float r2 = (y2 < 0.f) ? 10.f * y2 : y2;
        float r3 = (y3 < 0.f) ? 10.f * y3 : y3;
        num += __half2float(ev0.x) * r0 + __half2float(ev0.y) * r1
             + __half2float(ev1.x) * r2 + __half2float(ev1.y) * r3;
    }
#pragma unroll
    for (int o = 16; o > 0; o >>= 1)
        num += __shfl_xor_sync(0xffffffffu, num, o);
    if (lane == 0) g_num[(size_t)b * NPn + n] = num;
}

// ---------------- init ----------------------------------------------------------
__global__ void k_init(const int* __restrict__ idxr) {
    int gid = blockIdx.x * 256 + threadIdx.x;
    if (gid < Bn * NPn) g_wn2[gid] = 0.f;
    if (gid < Bn * Ln)  g_norm2[gid] = 0.f;
    if (gid < LP) g_ca[gid] = __ushort_as_half(gid < Ln ? (unsigned short)0x7380
                                                        : (unsigned short)0);
    if (gid == 0) {
        g_acc = 0.f;
        int any = 0;
        for (int i = 1; i < 1024; i += 2) any |= idxr[i];
        g_idx64 = (any == 0) ? 1 : 0;
    }
}
__device__ __forceinline__ int get_idx(const int* __restrict__ r, int n) {
    return g_idx64 ? r[2 * n] : r[n];
}

// ---------------- convert npf (+ fused q-norm) ----------------------------------
__global__ __launch_bounds__(256) void k_cvt_np(const float* __restrict__ npf) {
    int n = blockIdx.x, t = threadIdx.x;
    const float* src = npf + (size_t)n * Dn;
    __half* dst = g_npf + (size_t)n * Dn;
    float s = 0.f;
#pragma unroll
    for (int i = 0; i < 3; i++) {
        float v = src[t + i * 256];
        dst[t + i * 256] = __float2half(v);
        s += v * v;
    }
    __shared__ float sh[256];
    sh[t] = s; __syncthreads();
    for (int o = 128; o > 0; o >>= 1) {
        if (t < o) sh[t] += sh[t + o];
        __syncthreads();
    }
    if (t == 0) g_qn[n] = sqrtf(sh[0]);
}

// ---------------- convert img/txt -----------------------------------------------
__global__ void k_cvt_it(const float* __restrict__ img, const float* __restrict__ txt) {
    int i = (blockIdx.x * 256 + threadIdx.x) * 4;
    const float* src; __half* dst; int off;
    if (i < Bn * Dn)          { src = img; dst = g_img; off = i; }
    else if (i < 2 * Bn * Dn) { src = txt; dst = g_txt; off = i - Bn * Dn; }
    else return;
    float4 v = *(const float4*)(src + off);
    dst[off] = __float2half(v.x); dst[off + 1] = __float2half(v.y);
    dst[off + 2] = __float2half(v.z); dst[off + 3] = __float2half(v.w);
}

// ---------------- pure streaming convert of tokens -------------------------------
__global__ __launch_bounds__(256) void k_cvt_tok(const float* __restrict__ tok) {
    size_t i = ((size_t)blockIdx.x * 256 + threadIdx.x) * 8;
    float4 v0 = *(const float4*)(tok + i);
    float4 v1 = *(const float4*)(tok + i + 4);
    __half h[8];
    h[0] = __float2half(v0.x); h[1] = __float2half(v0.y);
    h[2] = __float2half(v0.z); h[3] = __float2half(v0.w);
    h[4] = __float2half(v1.x); h[5] = __float2half(v1.y);
    h[6] = __float2half(v1.z); h[7] = __float2half(v1.w);
    *(uint4*)(g_tok + i) = *(uint4*)h;
}

// ---------------- inv norm -> fp16 scale ----------------------------------------
__global__ void k_inv() {
    int i = blockIdx.x * 256 + threadIdx.x;
    if (i < Bn * Ln) {
        int b = i / Ln, l = i - b * Ln;
        float inv = 1.f / fmaxf(sqrtf(g_norm2[i]), EPSF);
        float cf = fminf(inv * 5909.2788f, 60000.f);   // 4*log2(e)*1024
        g_ch[b * LP + l] = __float2half_rn(cf);
    }
}

// ---------------- merged loss reduction -----------------------------------------
__global__ void k_loss(const float* sc, const float* bi, const int* __restrict__ idxr) {
    int gid = blockIdx.x * 256 + threadIdx.x;
    float t = 0.f;
    if (gid < Bn * Bn) {
        int i = gid >> 7, j = gid & 127;
        float lg = g_ct[gid] * sc[0] + bi[0];
        float lab = (i == j) ? 1.f : -1.f;
        t = -logsig(lab * lg) * (1.0f / Bn);
    } else if (gid < Bn * Bn + Bn * NPn) {
        int g2 = gid - Bn * Bn;
        int b = g2 >> 10, n = g2 & 1023;
        float lab = (get_idx(idxr, n) == b) ? 1.f : -1.f;
        float lg = g_npc[g2] * sc[0] + bi[0];
        t = -logsig(lab * lg) * (1.0f / NPn);
    } else if (gid < Bn * Bn + 2 * Bn * NPn) {
        int g2 = gid - Bn * Bn - Bn * NPn;
        int b = g2 >> 10, n = g2 & 1023;
        float wn = sqrtf(g_wn2[g2]);
        float den = fmaxf(g_qn[n] * wn, EPSF);
        float sim = g_num[g2] / den;
        float lg = sim * sc[0] + bi[0];
        float lab = (get_idx(idxr, n) == b) ? 1.f : -1.f;
        t = -logsig(lab * lg) * (0.01f / NPn);
    }
    __shared__ float sh[256];
    sh[threadIdx.x] = t; __syncthreads();
    for (int o = 128; o > 0; o >>= 1) {
        if (threadIdx.x < o) sh[threadIdx.x] += sh[threadIdx.x + o];
        __syncthreads();
    }
    if (threadIdx.x == 0) atomicAdd(&g_acc, sh[0]);
}

__global__ void k_final(float* out) { out[0] = g_acc; }

// ---------------- launch ---------------------------------------------------------
extern "C" void kernel_launch(void* const* d_in, const int* in_sizes, int n_in,
                              void* d_out, int out_size) {
    const float* img = (const float*)d_in[0];
    const float* txt = (const float*)d_in[1];
    const float* sc  = (const float*)d_in[2];
    const float* bi  = (const float*)d_in[3];
    const float* npf = (const float*)d_in[4];
    const int*   idx = (const int*)d_in[5];
    const float* tok = (const float*)d_in[6];
    float* out = (float*)d_out;

    cudaFuncSetAttribute(k_mma1, cudaFuncAttributeMaxDynamicSharedMemorySize, SMEM_DYN);
    cudaFuncSetAttribute(k_mma2, cudaFuncAttributeMaxDynamicSharedMemorySize, SMEM_DYN);

    k_init<<<512, 256>>>(idx);
    k_cvt_np<<<NPn, 256>>>(npf);
    k_cvt_it<<<192, 256>>>(img, txt);
    k_cvt_tok<<<27696, 256>>>(tok);   // 128*577*768 / (256*8)

    k_mma1<<<dim3(4, 5, 129), 256, SMEM_DYN>>>();
    k_inv<<<289, 256>>>();
    k_epass<<<16384, 256>>>();
    k_mma2<<<dim3(3, 8, 128), 256, SMEM_DYN>>>();

    k_loss<<<1088, 256>>>(sc, bi, idx);
    k_final<<<1, 1>>>(out);
}

// round 8
// speedup vs baseline: 12.8075x; 1.1025x over previous
#include <cuda_runtime.h>
#include <cuda_fp16.h>
#include <math.h>
#include <stdint.h>

#define Bn  128
#define Ln  577
#define LP  640
#define Dn  768
#define NPn 1024
#define EPSF 1e-8f
#define STAGE_B 49152
#define SMEM_DYN (2 * STAGE_B)

// ---------------- device scratch ----------------
__device__ __half g_Yt [(size_t)Bn*NPn*LP];   // y = leaky(S), [b][n][l]
__device__ __half g_Pt [(size_t)Bn*NPn*LP];   // e (unnormalized), [b][n][l]
__device__ __half g_tok[(size_t)Bn*Ln*Dn];    // tokens fp16, [b][l][d]
__device__ __half g_npf[NPn*Dn];
__device__ __half g_img[Bn*Dn];
__device__ __half g_txt[Bn*Dn];
__device__ float  g_norm2[Bn*Ln];
__device__ __half g_ch [Bn*LP];     // per-(b,l) scale c, pad=0
__device__ __half g_ca [LP];        // addend 15360.0 valid l, 0 pad
__device__ float  g_qn  [NPn];
__device__ float  g_num [Bn*NPn];   // sum e*raw
__device__ float  g_wn2 [Bn*NPn];   // ||w_hat||^2
__device__ float  g_ct  [Bn*Bn];
__device__ float  g_npc [Bn*NPn];
__device__ float  g_acc;
__device__ int    g_idx64;

__device__ __forceinline__ float lk(float x) { return x >= 0.f ? x : 0.1f * x; }
__device__ __forceinline__ float logsig(float x) {
    return fminf(x, 0.f) - log1pf(expf(-fabsf(x)));
}
__device__ __forceinline__ uint32_t s2u(const void* p) {
    uint32_t a;
    asm("{ .reg .u64 t; cvta.to.shared.u64 t, %1; cvt.u32.u64 %0, t; }" : "=r"(a) : "l"(p));
    return a;
}

// -------- cp.async K-major tile: ROWS x 64 halfs, SW128 swizzle ---------------
template<int ROWS>
__device__ __forceinline__ void cpa_tile(uint32_t dst, const __half* __restrict__ src,
                                         int row0, int row_lim, size_t stride, int k0, int tid) {
#pragma unroll
    for (int i = 0; i < ROWS / 32; i++) {
        int e = tid + (i << 8);
        int r = e >> 3, c = e & 7;
        int gr = row0 + r;
        int sz = 16;
        if (gr >= row_lim) { gr = row_lim - 1; sz = 0; }
        const void* gp = (const void*)(src + (size_t)gr * stride + k0 + (c << 3));
        uint32_t off = (uint32_t)((r << 7) + (c << 4));
        off ^= (off >> 3) & 0x70;
        asm volatile("cp.async.cg.shared.global [%0], [%1], 16, %2;"
                     :: "r"(dst + off), "l"(gp), "r"(sz) : "memory");
    }
}
// -------- cp.async MN-major tile: 64 rows(l) x 256 halfs(d), per-row XOR ------
__device__ __forceinline__ void cpa_tile_tr(uint32_t dst, const __half* __restrict__ src,
                                            int row0, int row_lim, size_t stride, int tid) {
#pragma unroll
    for (int i = 0; i < 8; i++) {
        int e = tid + (i << 8);
        int r = e >> 5, c = e & 31;
        int gr = row0 + r;
        int sz = 16;
        if (gr >= row_lim) { gr = row_lim - 1; sz = 0; }
        const void* gp = (const void*)(src + (size_t)gr * stride + (c << 3));
        uint32_t phys = (uint32_t)(r << 9) + ((uint32_t)(c << 4) ^ ((uint32_t)(r & 7) << 4));
        asm volatile("cp.async.cg.shared.global [%0], [%1], 16, %2;"
                     :: "r"(dst + phys), "l"(gp), "r"(sz) : "memory");
    }
}
#define CPA_COMMIT() asm volatile("cp.async.commit_group;" ::: "memory")

// ---------------- warp MMA (f16 acc) over one 128x256x64 SMEM chunk ------------
template<bool TRANSB>
__device__ __forceinline__ void mma_compute(uint32_t aBase, uint32_t bBase,
                                            int lane, int warpM, int warpN,
                                            uint32_t (&acc)[4][8][2]) {
#pragma unroll
    for (int ks = 0; ks < 4; ks++) {
        uint32_t a[4][4];
#pragma unroll
        for (int mb = 0; mb < 4; mb++) {
            int row = warpM * 64 + mb * 16 + (lane & 15);
            uint32_t byte = (uint32_t)(ks * 32 + ((lane >> 4) << 4));
            uint32_t off = (uint32_t)(row << 7) + byte;
            off ^= (off >> 3) & 0x70;
            asm volatile("ldmatrix.sync.aligned.m8n8.x4.shared.b16 {%0,%1,%2,%3}, [%4];"
                         : "=r"(a[mb][0]), "=r"(a[mb][1]), "=r"(a[mb][2]), "=r"(a[mb][3])
                         : "r"(aBase + off));
        }
        uint32_t b[8][2];
        if (!TRANSB) {
#pragma unroll
            for (int g = 0; g < 4; g++) {
                int row = warpN * 64 + g * 16 + (lane & 7) + ((lane >> 4) << 3);
                uint32_t byte = (uint32_t)(ks * 32 + ((lane & 8) ? 16 : 0));
                uint32_t off = (uint32_t)(row << 7) + byte;
                off ^= (off >> 3) & 0x70;
                uint32_t r0, r1, r2, r3;
                asm volatile("ldmatrix.sync.aligned.m8n8.x4.shared.b16 {%0,%1,%2,%3}, [%4];"
                             : "=r"(r0), "=r"(r1), "=r"(r2), "=r"(r3)
                             : "r"(bBase + off));
                b[g * 2][0] = r0; b[g * 2][1] = r1;
                b[g * 2 + 1][0] = r2; b[g * 2 + 1][1] = r3;
            }
        } else {
#pragma unroll
            for (int g = 0; g < 4; g++) {
                int row = ks * 16 + (lane & 15);                       // l row
                uint32_t bir = (uint32_t)(warpN * 128 + g * 32 + ((lane >> 4) << 4));
                uint32_t phys = (uint32_t)(row << 9) + (bir ^ ((uint32_t)(row & 7) << 4));
                uint32_t r0, r1, r2, r3;
                asm volatile("ldmatrix.sync.aligned.m8n8.x4.trans.shared.b16 {%0,%1,%2,%3}, [%4];"
                             : "=r"(r0), "=r"(r1), "=r"(r2), "=r"(r3)
                             : "r"(bBase + phys));
                b[g * 2][0] = r0; b[g * 2][1] = r1;
                b[g * 2 + 1][0] = r2; b[g * 2 + 1][1] = r3;
            }
        }
#pragma unroll
        for (int mb = 0; mb < 4; mb++)
#pragma unroll
            for (int nb = 0; nb < 8; nb++)
                asm volatile(
                    "mma.sync.aligned.m16n8k16.row.col.f16.f16.f16.f16 "
                    "{%0,%1},{%2,%3,%4,%5},{%6,%7},{%0,%1};"
                    : "+r"(acc[mb][nb][0]), "+r"(acc[mb][nb][1])
                    : "r"(a[mb][0]), "r"(a[mb][1]), "r"(a[mb][2]), "r"(a[mb][3]),
                      "r"(b[nb][0]), "r"(b[nb][1]));
    }
}

// ---------------- 2-stage pipelined mainloop (2 CTAs/SM) -----------------------
// prefetch(it+1) is issued AFTER the full drain + sync, so the buffer being
// overwritten is never concurrently read; compute(it) overlaps load(it+1).
template<bool TRANSB>
__device__ __forceinline__ void mma_mainloop(uint32_t su,
    const __half* A, int arow0, int alim, size_t astr,
    const __half* Bp, int brow0, int blim, size_t bstr,
    int nK, int tid, int lane, int warpM, int warpN, uint32_t (&acc)[4][8][2]) {
    cpa_tile<128>(su, A, arow0, alim, astr, 0, tid);
    if (!TRANSB) cpa_tile<256>(su + 16384, Bp, brow0, blim, bstr, 0, tid);
    else         cpa_tile_tr (su + 16384, Bp, 0, blim, bstr, tid);
    CPA_COMMIT();
    for (int it = 0; it < nK; ++it) {
        asm volatile("cp.async.wait_group 0;" ::: "memory");
        __syncthreads();
        if (it + 1 < nK) {
            uint32_t nb = su + (uint32_t)(((it + 1) & 1) * STAGE_B);
            cpa_tile<128>(nb, A, arow0, alim, astr, (it + 1) * 64, tid);
            if (!TRANSB) cpa_tile<256>(nb + 16384, Bp, brow0, blim, bstr, (it + 1) * 64, tid);
            else         cpa_tile_tr (nb + 16384, Bp, (it + 1) * 64, blim, bstr, tid);
            CPA_COMMIT();
        }
        uint32_t base = su + (uint32_t)((it & 1) * STAGE_B);
        mma_compute<TRANSB>(base, base + 16384, lane, warpM, warpN, acc);
    }
    __syncthreads();
}

// ---------------- GEMM1: y = lk(tok @ npf^T), transposed out (+ npc/ct) --------
__global__ __launch_bounds__(256, 2) void k_mma1() {
    extern __shared__ char smem[];
    uint32_t su = s2u(smem);
    int tid = threadIdx.x, lane = tid & 31, wid = tid >> 5;
    int warpM = wid & 1, warpN = wid >> 1;
    int bx = blockIdx.x, by = blockIdx.y, bz = blockIdx.z;

    const __half *A, *Bp;
    float* CoutF = 0;
    size_t cstr = 0; int M, m0, n0, Nlim = 0, blim; bool isS;
    if (bz < Bn) {
        A = g_tok + (size_t)bz * Ln * Dn;
        Bp = g_npf + (size_t)bx * 256 * Dn;
        M = Ln; m0 = by * 128; n0 = bx * 256; blim = 256; isS = true;
    } else if (by == 0) {
        A = g_img; Bp = g_npf + (size_t)bx * 256 * Dn;
        CoutF = g_npc; cstr = NPn; M = Bn; m0 = 0; n0 = bx * 256;
        Nlim = NPn; blim = 256; isS = false;
    } else if (by == 1 && bx == 0) {
        A = g_img; Bp = g_txt;
        CoutF = g_ct; cstr = Bn; M = Bn; m0 = 0; n0 = 0;
        Nlim = Bn; blim = 128; isS = false;
    } else return;

    uint32_t acc[4][8][2];
#pragma unroll
    for (int i = 0; i < 4; i++)
#pragma unroll
        for (int j = 0; j < 8; j++) { acc[i][j][0] = 0u; acc[i][j][1] = 0u; }

    mma_mainloop<false>(su, A, m0, M, (size_t)Dn, Bp, 0, blim, (size_t)Dn,
                        12, tid, lane, warpM, warpN, acc);

    if (isS) {
        __half* st = (__half*)smem;   // [256][132]
#pragma unroll
        for (int mb = 0; mb < 4; mb++) {
#pragma unroll
            for (int h = 0; h < 2; h++) {
                int ml = warpM * 64 + mb * 16 + (lane >> 2) + h * 8;
                int gr = m0 + ml;
                float ps = 0.f;
#pragma unroll
                for (int nb = 0; nb < 8; nb++) {
                    __half2 hv = *(__half2*)&acc[mb][nb][h];
                    float lx = lk(__half2float(hv.x));
                    float ly = lk(__half2float(hv.y));
                    ps += lx * lx + ly * ly;
                    int nl = warpN * 64 + nb * 8 + (lane & 3) * 2;
                    st[nl * 132 + ml]       = __float2half_rn(lx);
                    st[(nl + 1) * 132 + ml] = __float2half_rn(ly);
                }
                ps += __shfl_xor_sync(0xffffffffu, ps, 1);
                ps += __shfl_xor_sync(0xffffffffu, ps, 2);
                if ((lane & 3) == 0 && gr < M)
                    atomicAdd(&g_norm2[(size_t)bz * Ln + gr], ps);
            }
        }
        __syncthreads();
        int valid = M - m0; if (valid > 128) valid = 128;
#pragma unroll 4
        for (int c = tid; c < 256 * 32; c += 256) {
            int r = c >> 5, ch = c & 31;
            int l = ch * 4;
            __half* dst = g_Yt + ((size_t)bz * NPn + n0 + r) * LP + m0 + l;
            const __half* srcp = st + r * 132 + l;
            if (l + 4 <= valid) {
                *(uint2*)dst = *(const uint2*)srcp;
            } else {
                for (int j = 0; j < 4; j++)
                    if (l + j < valid) dst[j] = srcp[j];
            }
        }
    } else {
#pragma unroll
        for (int mb = 0; mb < 4; mb++) {
#pragma unroll
            for (int h = 0; h < 2; h++) {
                int gr = m0 + warpM * 64 + mb * 16 + (lane >> 2) + h * 8;
                if (gr >= M) continue;
#pragma unroll
                for (int nb = 0; nb < 8; nb++) {
                    int gn = n0 + warpN * 64 + nb * 8 + (lane & 3) * 2;
                    if (gn < Nlim) {
                        __half2 hv = *(__half2*)&acc[mb][nb][h];
                        float2 v;
                        v.x = __half2float(hv.x); v.y = __half2float(hv.y);
                        *(float2*)(CoutF + (size_t)gr * cstr + gn) = v;
                    }
                }
            }
        }
    }
}

// ---------------- GEMM2: w_hat = e @ tok (B via ldmatrix.trans); ||w||^2 -------
__global__ __launch_bounds__(256, 2) void k_mma2() {
    extern __shared__ char smem[];
    uint32_t su = s2u(smem);
    int tid = threadIdx.x, lane = tid & 31, wid = tid >> 5;
    int warpM = wid & 1, warpN = wid >> 1;
    int bx = blockIdx.x, by = blockIdx.y, bz = blockIdx.z;

    const __half* A  = g_Pt + (size_t)bz * NPn * LP;
    const __half* Bp = g_tok + (size_t)bz * Ln * Dn + bx * 256;  // pre-offset d0
    int m0 = by * 128;

    uint32_t acc[4][8][2];
#pragma unroll
    for (int i = 0; i < 4; i++)
#pragma unroll
        for (int j = 0; j < 8; j++) { acc[i][j][0] = 0u; acc[i][j][1] = 0u; }

    mma_mainloop<true>(su, A, m0, NPn, (size_t)LP, Bp, 0, Ln, (size_t)Dn,
                       10, tid, lane, warpM, warpN, acc);

#pragma unroll
    for (int mb = 0; mb < 4; mb++) {
#pragma unroll
        for (int h = 0; h < 2; h++) {
            int gr = m0 + warpM * 64 + mb * 16 + (lane >> 2) + h * 8;
            float s = 0.f;
#pragma unroll
            for (int nb = 0; nb < 8; nb++) {
                __half2 hv = *(__half2*)&acc[mb][nb][h];
                float x = __half2float(hv.x), y = __half2float(hv.y);
                s += x * x + y * y;
            }
            s += __shfl_xor_sync(0xffffffffu, s, 1);
            s += __shfl_xor_sync(0xffffffffu, s, 2);
            if ((lane & 3) == 0)
                atomicAdd(&g_wn2[(size_t)bz * NPn + gr], s);
        }
    }
}

// ---------------- e-pass: warp per (b,n) row; e = schraudolph; num = sum e*raw --
__global__ __launch_bounds__(256) void k_epass() {
    int warp = (blockIdx.x << 3) + (threadIdx.x >> 5);   // 0 .. 131071
    int lane = threadIdx.x & 31;
    int b = warp >> 10, n = warp & 1023;
    const uint2* Y  = (const uint2*)(g_Yt + ((size_t)b * NPn + n) * LP);
    uint2*       P  = (uint2*)(g_Pt + ((size_t)b * NPn + n) * LP);
    const uint2* C  = (const uint2*)(g_ch + (size_t)b * LP);
    const uint2* A2 = (const uint2*)g_ca;
    float num = 0.f;
#pragma unroll
    for (int k = 0; k < 5; k++) {
        int idx = lane + (k << 5);
        uint2 y = Y[idx], c = C[idx], a = A2[idx], r;
        asm("fma.rn.f16x2 %0,%1,%2,%3;" : "=r"(r.x) : "r"(y.x), "r"(c.x), "r"(a.x));
        asm("fma.rn.f16x2 %0,%1,%2,%3;" : "=r"(r.y) : "r"(y.y), "r"(c.y), "r"(a.y));
        P[idx] = r;
        __half2 yv0 = *(__half2*)&y.x, yv1 = *(__half2*)&y.y;
        __half2 ev0 = *(__half2*)&r.x, ev1 = *(__half2*)&r.y;
        float y0 = __half2float(yv0.x), y1 = __half2float(yv0.y);
        float y2 = __half2float(yv1.x), y3 = __half2float(yv1.y);
        float r0 = (y0 < 0.f) ? 10.f * y0 : y0;
        float r1 = (y1 < 0.f) ? 10.f * y1 : y1;
        float r2 = (y2 < 0.f) ? 10.f * y2 : y2;
        float r3 = (y3 < 0.f) ? 10.f * y3 : y3;
        num += __half2float(ev0.x) * r0 + __half2float(ev0.y) * r1
             + __half2float(ev1.x) * r2 + __half2float(ev1.y) * r3;
    }
#pragma unroll
    for (int o = 16; o > 0; o >>= 1)
        num += __shfl_xor_sync(0xffffffffu, num, o);
    if (lane == 0) g_num[(size_t)b * NPn + n] = num;
}

// ---------------- init ----------------------------------------------------------
__global__ void k_init(const int* __restrict__ idxr) {
    int gid = blockIdx.x * 256 + threadIdx.x;
    if (gid < Bn * NPn) g_wn2[gid] = 0.f;
    if (gid < Bn * Ln)  g_norm2[gid] = 0.f;
    if (gid < LP) g_ca[gid] = __ushort_as_half(gid < Ln ? (unsigned short)0x7380
                                                        : (unsigned short)0);
    if (gid == 0) {
        g_acc = 0.f;
        int any = 0;
        for (int i = 1; i < 1024; i += 2) any |= idxr[i];
        g_idx64 = (any == 0) ? 1 : 0;
    }
}
__device__ __forceinline__ int get_idx(const int* __restrict__ r, int n) {
    return g_idx64 ? r[2 * n] : r[n];
}

// ---------------- convert npf (+ fused q-norm) ----------------------------------
__global__ __launch_bounds__(256) void k_cvt_np(const float* __restrict__ npf) {
    int n = blockIdx.x, t = threadIdx.x;
    const float* src = npf + (size_t)n * Dn;
    __half* dst = g_npf + (size_t)n * Dn;
    float s = 0.f;
#pragma unroll
    for (int i = 0; i < 3; i++) {
        float v = src[t + i * 256];
        dst[t + i * 256] = __float2half(v);
        s += v * v;
    }
    __shared__ float sh[256];
    sh[t] = s; __syncthreads();
    for (int o = 128; o > 0; o >>= 1) {
        if (t < o) sh[t] += sh[t + o];
        __syncthreads();
    }
    if (t == 0) g_qn[n] = sqrtf(sh[0]);
}

// ---------------- convert img/txt -----------------------------------------------
__global__ void k_cvt_it(const float* __restrict__ img, const float* __restrict__ txt) {
    int i = (blockIdx.x * 256 + threadIdx.x) * 4;
    const float* src; __half* dst; int off;
    if (i < Bn * Dn)          { src = img; dst = g_img; off = i; }
    else if (i < 2 * Bn * Dn) { src = txt; dst = g_txt; off = i - Bn * Dn; }
    else return;
    float4 v = *(const float4*)(src + off);
    dst[off] = __float2half(v.x); dst[off + 1] = __float2half(v.y);
    dst[off + 2] = __float2half(v.z); dst[off + 3] = __float2half(v.w);
}

// ---------------- pure streaming convert of tokens -------------------------------
__global__ __launch_bounds__(256) void k_cvt_tok(const float* __restrict__ tok) {
    size_t i = ((size_t)blockIdx.x * 256 + threadIdx.x) * 8;
    float4 v0 = *(const float4*)(tok + i);
    float4 v1 = *(const float4*)(tok + i + 4);
    __half h[8];
    h[0] = __float2half(v0.x); h[1] = __float2half(v0.y);
    h[2] = __float2half(v0.z); h[3] = __float2half(v0.w);
    h[4] = __float2half(v1.x); h[5] = __float2half(v1.y);
    h[6] = __float2half(v1.z); h[7] = __float2half(v1.w);
    *(uint4*)(g_tok + i) = *(uint4*)h;
}

// ---------------- inv norm -> fp16 scale ----------------------------------------
__global__ void k_inv() {
    int i = blockIdx.x * 256 + threadIdx.x;
    if (i < Bn * Ln) {
        int b = i / Ln, l = i - b * Ln;
        float inv = 1.f / fmaxf(sqrtf(g_norm2[i]), EPSF);
        float cf = fminf(inv * 5909.2788f, 60000.f);   // 4*log2(e)*1024
        g_ch[b * LP + l] = __float2half_rn(cf);
    }
}

// ---------------- merged loss reduction -----------------------------------------
__global__ void k_loss(const float* sc, const float* bi, const int* __restrict__ idxr) {
    int gid = blockIdx.x * 256 + threadIdx.x;
    float t = 0.f;
    if (gid < Bn * Bn) {
        int i = gid >> 7, j = gid & 127;
        float lg = g_ct[gid] * sc[0] + bi[0];
        float lab = (i == j) ? 1.f : -1.f;
        t = -logsig(lab * lg) * (1.0f / Bn);
    } else if (gid < Bn * Bn + Bn * NPn) {
        int g2 = gid - Bn * Bn;
        int b = g2 >> 10, n = g2 & 1023;
        float lab = (get_idx(idxr, n) == b) ? 1.f : -1.f;
        float lg = g_npc[g2] * sc[0] + bi[0];
        t = -logsig(lab * lg) * (1.0f / NPn);
    } else if (gid < Bn * Bn + 2 * Bn * NPn) {
        int g2 = gid - Bn * Bn - Bn * NPn;
        int b = g2 >> 10, n = g2 & 1023;
        float wn = sqrtf(g_wn2[g2]);
        float den = fmaxf(g_qn[n] * wn, EPSF);
        float sim = g_num[g2] / den;
        float lg = sim * sc[0] + bi[0];
        float lab = (get_idx(idxr, n) == b) ? 1.f : -1.f;
        t = -logsig(lab * lg) * (0.01f / NPn);
    }
    __shared__ float sh[256];
    sh[threadIdx.x] = t; __syncthreads();
    for (int o = 128; o > 0; o >>= 1) {
        if (threadIdx.x < o) sh[threadIdx.x] += sh[threadIdx.x + o];
        __syncthreads();
    }
    if (threadIdx.x == 0) atomicAdd(&g_acc, sh[0]);
}

__global__ void k_final(float* out) { out[0] = g_acc; }

// ---------------- launch ---------------------------------------------------------
extern "C" void kernel_launch(void* const* d_in, const int* in_sizes, int n_in,
                              void* d_out, int out_size) {
    const float* img = (const float*)d_in[0];
    const float* txt = (const float*)d_in[1];
    const float* sc  = (const float*)d_in[2];
    const float* bi  = (const float*)d_in[3];
    const float* npf = (const float*)d_in[4];
    const int*   idx = (const int*)d_in[5];
    const float* tok = (const float*)d_in[6];
    float* out = (float*)d_out;

    cudaFuncSetAttribute(k_mma1, cudaFuncAttributeMaxDynamicSharedMemorySize, SMEM_DYN);
    cudaFuncSetAttribute(k_mma2, cudaFuncAttributeMaxDynamicSharedMemorySize, SMEM_DYN);

    k_init<<<512, 256>>>(idx);
    k_cvt_np<<<NPn, 256>>>(npf);
    k_cvt_it<<<192, 256>>>(img, txt);
    k_cvt_tok<<<27696, 256>>>(tok);   // 128*577*768 / (256*8)

    k_mma1<<<dim3(4, 5, 129), 256, SMEM_DYN>>>();
    k_inv<<<289, 256>>>();
    k_epass<<<16384, 256>>>();
    k_mma2<<<dim3(3, 8, 128), 256, SMEM_DYN>>>();

    k_loss<<<1088, 256>>>(sc, bi, idx);
    k_final<<<1, 1>>>(out);
}

// round 10
// speedup vs baseline: 13.0116x; 1.0159x over previous
#include <cuda_runtime.h>
#include <cuda_fp16.h>
#include <math.h>
#include <stdint.h>

#define Bn  128
#define Ln  577
#define LP  640
#define Dn  768
#define NPn 1024
#define EPSF 1e-8f
#define STAGE_B 49152
#define SMEM_MMA1 (2 * STAGE_B)
#define SMEM_MMA2 (2 * STAGE_B + 2560)

// ---------------- device scratch ----------------
__device__ __half g_Yt [(size_t)Bn*NPn*LP];   // y = leaky(S), [b][n][l]; pads stay 0
__device__ __half g_tok[(size_t)Bn*Ln*Dn];    // tokens fp16, [b][l][d]
__device__ __half g_npf[NPn*Dn];
__device__ __half g_img[Bn*Dn];
__device__ __half g_txt[Bn*Dn];
__device__ float  g_norm2[Bn*Ln];
__device__ __half g_ch [Bn*LP];     // per-(b,l) scale c, pad=0 (zero-init, never written)
__device__ __half g_ca [LP];        // addend 15360.0 valid l, 0 pad
__device__ float  g_qn  [NPn];
__device__ float  g_num [Bn*NPn];   // sum e*raw  (written by k_mma2 bx==0)
__device__ float  g_wn2 [Bn*NPn];   // ||w_hat||^2
__device__ float  g_ct  [Bn*Bn];
__device__ float  g_npc [Bn*NPn];
__device__ float  g_acc;
__device__ int    g_idx64;

__device__ __forceinline__ float lk(float x) { return x >= 0.f ? x : 0.1f * x; }
__device__ __forceinline__ float logsig(float x) {
    return fminf(x, 0.f) - log1pf(expf(-fabsf(x)));
}
__device__ __forceinline__ uint32_t s2u(const void* p) {
    uint32_t a;
    asm("{ .reg .u64 t; cvta.to.shared.u64 t, %1; cvt.u32.u64 %0, t; }" : "=r"(a) : "l"(p));
    return a;
}

// -------- cp.async K-major tile: ROWS x 64 halfs, SW128 swizzle ---------------
template<int ROWS>
__device__ __forceinline__ void cpa_tile(uint32_t dst, const __half* __restrict__ src,
                                         int row0, int row_lim, size_t stride, int k0, int tid) {
#pragma unroll
    for (int i = 0; i < ROWS / 32; i++) {
        int e = tid + (i << 8);
        int r = e >> 3, c = e & 7;
        int gr = row0 + r;
        int sz = 16;
        if (gr >= row_lim) { gr = row_lim - 1; sz = 0; }
        const void* gp = (const void*)(src + (size_t)gr * stride + k0 + (c << 3));
        uint32_t off = (uint32_t)((r << 7) + (c << 4));
        off ^= (off >> 3) & 0x70;
        asm volatile("cp.async.cg.shared.global [%0], [%1], 16, %2;"
                     :: "r"(dst + off), "l"(gp), "r"(sz) : "memory");
    }
}
// -------- cp.async MN-major tile: 64 rows(l) x 256 halfs(d), per-row XOR ------
__device__ __forceinline__ void cpa_tile_tr(uint32_t dst, const __half* __restrict__ src,
                                            int row0, int row_lim, size_t stride, int tid) {
#pragma unroll
    for (int i = 0; i < 8; i++) {
        int e = tid + (i << 8);
        int r = e >> 5, c = e & 31;
        int gr = row0 + r;
        int sz = 16;
        if (gr >= row_lim) { gr = row_lim - 1; sz = 0; }
        const void* gp = (const void*)(src + (size_t)gr * stride + (c << 3));
        uint32_t phys = (uint32_t)(r << 9) + ((uint32_t)(c << 4) ^ ((uint32_t)(r & 7) << 4));
        asm volatile("cp.async.cg.shared.global [%0], [%1], 16, %2;"
                     :: "r"(dst + phys), "l"(gp), "r"(sz) : "memory");
    }
}
#define CPA_COMMIT() asm volatile("cp.async.commit_group;" ::: "memory")

// ---------------- warp MMA (f16 acc) over one 128x256x64 SMEM chunk ------------
template<bool TRANSB>
__device__ __forceinline__ void mma_compute(uint32_t aBase, uint32_t bBase,
                                            int lane, int warpM, int warpN,
                                            uint32_t (&acc)[4][8][2]) {
#pragma unroll
    for (int ks = 0; ks < 4; ks++) {
        uint32_t a[4][4];
#pragma unroll
        for (int mb = 0; mb < 4; mb++) {
            int row = warpM * 64 + mb * 16 + (lane & 15);
            uint32_t byte = (uint32_t)(ks * 32 + ((lane >> 4) << 4));
            uint32_t off = (uint32_t)(row << 7) + byte;
            off ^= (off >> 3) & 0x70;
            asm volatile("ldmatrix.sync.aligned.m8n8.x4.shared.b16 {%0,%1,%2,%3}, [%4];"
                         : "=r"(a[mb][0]), "=r"(a[mb][1]), "=r"(a[mb][2]), "=r"(a[mb][3])
                         : "r"(aBase + off));
        }
        uint32_t b[8][2];
        if (!TRANSB) {
#pragma unroll
            for (int g = 0; g < 4; g++) {
                int row = warpN * 64 + g * 16 + (lane & 7) + ((lane >> 4) << 3);
                uint32_t byte = (uint32_t)(ks * 32 + ((lane & 8) ? 16 : 0));
                uint32_t off = (uint32_t)(row << 7) + byte;
                off ^= (off >> 3) & 0x70;
                uint32_t r0, r1, r2, r3;
                asm volatile("ldmatrix.sync.aligned.m8n8.x4.shared.b16 {%0,%1,%2,%3}, [%4];"
                             : "=r"(r0), "=r"(r1), "=r"(r2), "=r"(r3)
                             : "r"(bBase + off));
                b[g * 2][0] = r0; b[g * 2][1] = r1;
                b[g * 2 + 1][0] = r2; b[g * 2 + 1][1] = r3;
            }
        } else {
#pragma unroll
            for (int g = 0; g < 4; g++) {
                int row = ks * 16 + (lane & 15);                       // l row
                uint32_t bir = (uint32_t)(warpN * 128 + g * 32 + ((lane >> 4) << 4));
                uint32_t phys = (uint32_t)(row << 9) + (bir ^ ((uint32_t)(row & 7) << 4));
                uint32_t r0, r1, r2, r3;
                asm volatile("ldmatrix.sync.aligned.m8n8.x4.trans.shared.b16 {%0,%1,%2,%3}, [%4];"
                             : "=r"(r0), "=r"(r1), "=r"(r2), "=r"(r3)
                             : "r"(bBase + phys));
                b[g * 2][0] = r0; b[g * 2][1] = r1;
                b[g * 2 + 1][0] = r2; b[g * 2 + 1][1] = r3;
            }
        }
#pragma unroll
        for (int mb = 0; mb < 4; mb++)
#pragma unroll
            for (int nb = 0; nb < 8; nb++)
                asm volatile(
                    "mma.sync.aligned.m16n8k16.row.col.f16.f16.f16.f16 "
                    "{%0,%1},{%2,%3,%4,%5},{%6,%7},{%0,%1};"
                    : "+r"(acc[mb][nb][0]), "+r"(acc[mb][nb][1])
                    : "r"(a[mb][0]), "r"(a[mb][1]), "r"(a[mb][2]), "r"(a[mb][3]),
                      "r"(b[nb][0]), "r"(b[nb][1]));
    }
}

// ---------------- 2-stage pipelined mainloop (GEMM1) ---------------------------
__device__ __forceinline__ void mma_mainloop1(uint32_t su,
    const __half* A, int arow0, int alim, size_t astr,
    const __half* Bp, int blim, size_t bstr,
    int nK, int tid, int lane, int warpM, int warpN, uint32_t (&acc)[4][8][2]) {
    cpa_tile<128>(su, A, arow0, alim, astr, 0, tid);
    cpa_tile<256>(su + 16384, Bp, 0, blim, bstr, 0, tid);
    CPA_COMMIT();
    for (int it = 0; it < nK; ++it) {
        asm volatile("cp.async.wait_group 0;" ::: "memory");
        __syncthreads();
        if (it + 1 < nK) {
            uint32_t nb = su + (uint32_t)(((it + 1) & 1) * STAGE_B);
            cpa_tile<128>(nb, A, arow0, alim, astr, (it + 1) * 64, tid);
            cpa_tile<256>(nb + 16384, Bp, 0, blim, bstr, (it + 1) * 64, tid);
            CPA_COMMIT();
        }
        uint32_t base = su + (uint32_t)((it & 1) * STAGE_B);
        mma_compute<false>(base, base + 16384, lane, warpM, warpN, acc);
    }
    __syncthreads();
}

// ---------------- GEMM1: y = lk(tok @ npf^T), transposed out (+ npc/ct) --------
__global__ __launch_bounds__(256, 2) void k_mma1() {
    extern __shared__ char smem[];
    uint32_t su = s2u(smem);
    int tid = threadIdx.x, lane = tid & 31, wid = tid >> 5;
    int warpM = wid & 1, warpN = wid >> 1;
    int bx = blockIdx.x, by = blockIdx.y, bz = blockIdx.z;

    const __half *A, *Bp;
    float* CoutF = 0;
    size_t cstr = 0; int M, m0, n0, Nlim = 0, blim; bool isS;
    if (bz < Bn) {
        A = g_tok + (size_t)bz * Ln * Dn;
        Bp = g_npf + (size_t)bx * 256 * Dn;
        M = Ln; m0 = by * 128; n0 = bx * 256; blim = 256; isS = true;
    } else if (by == 0) {
        A = g_img; Bp = g_npf + (size_t)bx * 256 * Dn;
        CoutF = g_npc; cstr = NPn; M = Bn; m0 = 0; n0 = bx * 256;
        Nlim = NPn; blim = 256; isS = false;
    } else if (by == 1 && bx == 0) {
        A = g_img; Bp = g_txt;
        CoutF = g_ct; cstr = Bn; M = Bn; m0 = 0; n0 = 0;
        Nlim = Bn; blim = 128; isS = false;
    } else return;

    uint32_t acc[4][8][2];
#pragma unroll
    for (int i = 0; i < 4; i++)
#pragma unroll
        for (int j = 0; j < 8; j++) { acc[i][j][0] = 0u; acc[i][j][1] = 0u; }

    mma_mainloop1(su, A, m0, M, (size_t)Dn, Bp, blim, (size_t)Dn,
                  12, tid, lane, warpM, warpN, acc);

    if (isS) {
        __half* st = (__half*)smem;   // [256][132]
#pragma unroll
        for (int mb = 0; mb < 4; mb++) {
#pragma unroll
            for (int h = 0; h < 2; h++) {
                int ml = warpM * 64 + mb * 16 + (lane >> 2) + h * 8;
                int gr = m0 + ml;
                float ps = 0.f;
#pragma unroll
                for (int nb = 0; nb < 8; nb++) {
                    __half2 hv = *(__half2*)&acc[mb][nb][h];
                    float lx = lk(__half2float(hv.x));
                    float ly = lk(__half2float(hv.y));
                    ps += lx * lx + ly * ly;
                    int nl = warpN * 64 + nb * 8 + (lane & 3) * 2;
                    st[nl * 132 + ml]       = __float2half_rn(lx);
                    st[(nl + 1) * 132 + ml] = __float2half_rn(ly);
                }
                ps += __shfl_xor_sync(0xffffffffu, ps, 1);
                ps += __shfl_xor_sync(0xffffffffu, ps, 2);
                if ((lane & 3) == 0 && gr < M)
                    atomicAdd(&g_norm2[(size_t)bz * Ln + gr], ps);
            }
        }
        __syncthreads();
        int valid = M - m0; if (valid > 128) valid = 128;
#pragma unroll 4
        for (int c = tid; c < 256 * 32; c += 256) {
            int r = c >> 5, ch = c & 31;
            int l = ch * 4;
            __half* dst = g_Yt + ((size_t)bz * NPn + n0 + r) * LP + m0 + l;
            const __half* srcp = st + r * 132 + l;
            if (l + 4 <= valid) {
                *(uint2*)dst = *(const uint2*)srcp;
            } else {
                for (int j = 0; j < 4; j++)
                    if (l + j < valid) dst[j] = srcp[j];
            }
        }
    } else {
#pragma unroll
        for (int mb = 0; mb < 4; mb++) {
#pragma unroll
            for (int h = 0; h < 2; h++) {
                int gr = m0 + warpM * 64 + mb * 16 + (lane >> 2) + h * 8;
                if (gr >= M) continue;
#pragma unroll
                for (int nb = 0; nb < 8; nb++) {
                    int gn = n0 + warpN * 64 + nb * 8 + (lane & 3) * 2;
                    if (gn < Nlim) {
                        __half2 hv = *(__half2*)&acc[mb][nb][h];
                        float2 v;
                        v.x = __half2float(hv.x); v.y = __half2float(hv.y);
                        *(float2*)(CoutF + (size_t)gr * cstr + gn) = v;
                    }
                }
            }
        }
    }
}

// ---------------- GEMM2: e built in-SMEM from y; w_hat = e @ tok ---------------
__global__ __launch_bounds__(256, 2) void k_mma2() {
    extern __shared__ char smem[];
    uint32_t su = s2u(smem);
    int tid = threadIdx.x, lane = tid & 31, wid = tid >> 5;
    int warpM = wid & 1, warpN = wid >> 1;
    int bx = blockIdx.x, by = blockIdx.y, bz = blockIdx.z;

    const __half* A  = g_Yt + (size_t)bz * NPn * LP;
    const __half* Bp = g_tok + (size_t)bz * Ln * Dn + bx * 256;  // pre-offset d0
    int m0 = by * 128;
    bool doNum = (bx == 0);

    // preload per-l scales (c, a) as packed u32 pairs — 320 u32 each, 256 threads
    uint32_t* sch = (uint32_t*)(smem + 2 * STAGE_B);
    uint32_t* sca = (uint32_t*)(smem + 2 * STAGE_B + 1280);
    for (int i = tid; i < 320; i += 256) {
        sch[i] = ((const uint32_t*)(g_ch + (size_t)bz * LP))[i];
        sca[i] = ((const uint32_t*)g_ca)[i];
    }

    uint32_t acc[4][8][2];
#pragma unroll
    for (int i = 0; i < 4; i++)
#pragma unroll
        for (int j = 0; j < 8; j++) { acc[i][j][0] = 0u; acc[i][j][1] = 0u; }
    float nacc[4] = {0.f, 0.f, 0.f, 0.f};

    cpa_tile<128>(su, A, m0, NPn, (size_t)LP, 0, tid);
    cpa_tile_tr(su + 16384, Bp, 0, Ln, (size_t)Dn, tid);
    CPA_COMMIT();

    const int rR = tid >> 3, cC = tid & 7;
    for (int it = 0; it < 10; ++it) {
        asm volatile("cp.async.wait_group 0;" ::: "memory");
        __syncthreads();
        if (it + 1 < 10) {
            uint32_t nb = su + (uint32_t)(((it + 1) & 1) * STAGE_B);
            cpa_tile<128>(nb, A, m0, NPn, (size_t)LP, (it + 1) * 64, tid);
            cpa_tile_tr(nb + 16384, Bp, (it + 1) * 64, Ln, (size_t)Dn, tid);
            CPA_COMMIT();
        }
        // in-place e-transform of A tile (current buffer)
        char* bufc = smem + (it & 1) * STAGE_B;
        int sidx = it * 32 + cC * 4;
#pragma unroll
        for (int i = 0; i < 4; i++) {
            int rr = rR + (i << 5);
            uint32_t off = ((uint32_t)(rr << 7)) + ((uint32_t)(cC << 4));
            off ^= (off >> 3) & 0x70;
            uint4 y4 = *(uint4*)(bufc + off);
            uint32_t yv[4] = {y4.x, y4.y, y4.z, y4.w};
            uint32_t ev[4];
#pragma unroll
            for (int j = 0; j < 4; j++) {
                asm("fma.rn.f16x2 %0,%1,%2,%3;"
                    : "=r"(ev[j]) : "r"(yv[j]), "r"(sch[sidx + j]), "r"(sca[sidx + j]));
                if (doNum) {
                    __half2 yh = *(__half2*)&yv[j];
                    __half2 eh = *(__half2*)&ev[j];
                    float a0 = __half2float(yh.x), a1 = __half2float(yh.y);
                    float rw0 = (a0 < 0.f) ? 10.f * a0 : a0;
                    float rw1 = (a1 < 0.f) ? 10.f * a1 : a1;
                    nacc[i] += __half2float(eh.x) * rw0 + __half2float(eh.y) * rw1;
                }
            }
            uint4 e4; e4.x = ev[0]; e4.y = ev[1]; e4.z = ev[2]; e4.w = ev[3];
            *(uint4*)(bufc + off) = e4;
        }
        __syncthreads();
        uint32_t base = su + (uint32_t)((it & 1) * STAGE_B);
        mma_compute<true>(base, base + 16384, lane, warpM, warpN, acc);
    }
    __syncthreads();

    if (doNum) {
#pragma unroll
        for (int i = 0; i < 4; i++) {
            nacc[i] += __shfl_xor_sync(0xffffffffu, nacc[i], 1);
            nacc[i] += __shfl_xor_sync(0xffffffffu, nacc[i], 2);
            nacc[i] += __shfl_xor_sync(0xffffffffu, nacc[i], 4);
        }
        if ((lane & 7) == 0) {
#pragma unroll
            for (int i = 0; i < 4; i++)
                g_num[(size_t)bz * NPn + m0 + rR + (i << 5)] = nacc[i];
        }
    }

#pragma unroll
    for (int mb = 0; mb < 4; mb++) {
#pragma unroll
        for (int h = 0; h < 2; h++) {
            int gr = m0 + warpM * 64 + mb * 16 + (lane >> 2) + h * 8;
            float s = 0.f;
#pragma unroll
            for (int nb = 0; nb < 8; nb++) {
                __half2 hv = *(__half2*)&acc[mb][nb][h];
                float x = __half2float(hv.x), y = __half2float(hv.y);
                s += x * x + y * y;
            }
            s += __shfl_xor_sync(0xffffffffu, s, 1);
            s += __shfl_xor_sync(0xffffffffu, s, 2);
            if ((lane & 3) == 0)
                atomicAdd(&g_wn2[(size_t)bz * NPn + gr], s);
        }
    }
}

// ---------------- init ----------------------------------------------------------
__global__ void k_init(const int* __restrict__ idxr) {
    int gid = blockIdx.x * 256 + threadIdx.x;
    if (gid < Bn * NPn) g_wn2[gid] = 0.f;
    if (gid < Bn * Ln)  g_norm2[gid] = 0.f;
    if (gid < LP) g_ca[gid] = __ushort_as_half(gid < Ln ? (unsigned short)0x7380
                                                        : (unsigned short)0);
    if (gid == 0) {
        g_acc = 0.f;
        int any = 0;
        for (int i = 1; i < 1024; i += 2) any |= idxr[i];
        g_idx64 = (any == 0) ? 1 : 0;
    }
}
__device__ __forceinline__ int get_idx(const int* __restrict__ r, int n) {
    return g_idx64 ? r[2 * n] : r[n];
}

// ---------------- convert npf (+ fused q-norm) ----------------------------------
__global__ __launch_bounds__(256) void k_cvt_np(const float* __restrict__ npf) {
    int n = blockIdx.x, t = threadIdx.x;
    const float* src = npf + (size_t)n * Dn;
    __half* dst = g_npf + (size_t)n * Dn;
    float s = 0.f;
#pragma unroll
    for (int i = 0; i < 3; i++) {
        float v = src[t + i * 256];
        dst[t + i * 256] = __float2half(v);
        s += v * v;
    }
    __shared__ float sh[256];
    sh[t] = s; __syncthreads();
    for (int o = 128; o > 0; o >>= 1) {
        if (t < o) sh[t] += sh[t + o];
        __syncthreads();
    }
    if (t == 0) g_qn[n] = sqrtf(sh[0]);
}

// ---------------- convert img/txt -----------------------------------------------
__global__ void k_cvt_it(const float* __restrict__ img, const float* __restrict__ txt) {
    int i = (blockIdx.x * 256 + threadIdx.x) * 4;
    const float* src; __half* dst; int off;
    if (i < Bn * Dn)          { src = img; dst = g_img; off = i; }
    else if (i < 2 * Bn * Dn) { src = txt; dst = g_txt; off = i - Bn * Dn; }
    else return;
    float4 v = *(const float4*)(src + off);
    dst[off] = __float2half(v.x); dst[off + 1] = __float2half(v.y);
    dst[off + 2] = __float2half(v.z); dst[off + 3] = __float2half(v.w);
}

// ---------------- pure streaming convert of tokens -------------------------------
__global__ __launch_bounds__(256) void k_cvt_tok(const float* __restrict__ tok) {
    size_t i = ((size_t)blockIdx.x * 256 + threadIdx.x) * 8;
    float4 v0 = *(const float4*)(tok + i);
    float4 v1 = *(const float4*)(tok + i + 4);
    __half h[8];
    h[0] = __float2half(v0.x); h[1] = __float2half(v0.y);
    h[2] = __float2half(v0.z); h[3] = __float2half(v0.w);
    h[4] = __float2half(v1.x); h[5] = __float2half(v1.y);
    h[6] = __float2half(v1.z); h[7] = __float2half(v1.w);
    *(uint4*)(g_tok + i) = *(uint4*)h;
}

// ---------------- inv norm -> fp16 scale ----------------------------------------
__global__ void k_inv() {
    int i = blockIdx.x * 256 + threadIdx.x;
    if (i < Bn * Ln) {
        int b = i / Ln, l = i - b * Ln;
        float inv = 1.f / fmaxf(sqrtf(g_norm2[i]), EPSF);
        float cf = fminf(inv * 5909.2788f, 60000.f);   // 4*log2(e)*1024
        g_ch[b * LP + l] = __float2half_rn(cf);
    }
}

// ---------------- merged loss reduction -----------------------------------------
__global__ void k_loss(const float* sc, const float* bi, const int* __restrict__ idxr) {
    int gid = blockIdx.x * 256 + threadIdx.x;
    float t = 0.f;
    if (gid < Bn * Bn) {
        int i = gid >> 7, j = gid & 127;
        float lg = g_ct[gid] * sc[0] + bi[0];
        float lab = (i == j) ? 1.f : -1.f;
        t = -logsig(lab * lg) * (1.0f / Bn);
    } else if (gid < Bn * Bn + Bn * NPn) {
        int g2 = gid - Bn * Bn;
        int b = g2 >> 10, n = g2 & 1023;
        float lab = (get_idx(idxr, n) == b) ? 1.f : -1.f;
        float lg = g_npc[g2] * sc[0] + bi[0];
        t = -logsig(lab * lg) * (1.0f / NPn);
    } else if (gid < Bn * Bn + 2 * Bn * NPn) {
        int g2 = gid - Bn * Bn - Bn * NPn;
        int b = g2 >> 10, n = g2 & 1023;
        float wn = sqrtf(g_wn2[g2]);
        float den = fmaxf(g_qn[n] * wn, EPSF);
        float sim = g_num[g2] / den;
        float lg = sim * sc[0] + bi[0];
        float lab = (get_idx(idxr, n) == b) ? 1.f : -1.f;
        t = -logsig(lab * lg) * (0.01f / NPn);
    }
    __shared__ float sh[256];
    sh[threadIdx.x] = t; __syncthreads();
    for (int o = 128; o > 0; o >>= 1) {
        if (threadIdx.x < o) sh[threadIdx.x] += sh[threadIdx.x + o];
        __syncthreads();
    }
    if (threadIdx.x == 0) atomicAdd(&g_acc, sh[0]);
}

__global__ void k_final(float* out) { out[0] = g_acc; }

// ---------------- launch ---------------------------------------------------------
extern "C" void kernel_launch(void* const* d_in, const int* in_sizes, int n_in,
                              void* d_out, int out_size) {
    const float* img = (const float*)d_in[0];
    const float* txt = (const float*)d_in[1];
    const float* sc  = (const float*)d_in[2];
    const float* bi  = (const float*)d_in[3];
    const float* npf = (const float*)d_in[4];
    const int*   idx = (const int*)d_in[5];
    const float* tok = (const float*)d_in[6];
    float* out = (float*)d_out;

    cudaFuncSetAttribute(k_mma1, cudaFuncAttributeMaxDynamicSharedMemorySize, SMEM_MMA1);
    cudaFuncSetAttribute(k_mma2, cudaFuncAttributeMaxDynamicSharedMemorySize, SMEM_MMA2);

    k_init<<<512, 256>>>(idx);
    k_cvt_np<<<NPn, 256>>>(npf);
    k_cvt_it<<<192, 256>>>(img, txt);
    k_cvt_tok<<<27696, 256>>>(tok);   // 128*577*768 / (256*8)

    k_mma1<<<dim3(4, 5, 129), 256, SMEM_MMA1>>>();
    k_inv<<<289, 256>>>();
    k_mma2<<<dim3(3, 8, 128), 256, SMEM_MMA2>>>();

    k_loss<<<1088, 256>>>(sc, bi, idx);
    k_final<<<1, 1>>>(out);
}

// round 11
// speedup vs baseline: 13.0851x; 1.0056x over previous
#include <cuda_runtime.h>
#include <cuda_fp16.h>
#include <math.h>
#include <stdint.h>

#define Bn  128
#define Ln  577
#define LP  640
#define Dn  768
#define NPn 1024
#define EPSF 1e-8f
#define STAGE_B 49152
#define SMEM_MMA1 (2 * STAGE_B)
#define SMEM_MMA2 (2 * STAGE_B + 2560)

// ---------------- device scratch ----------------
__device__ __half g_Yt [(size_t)Bn*NPn*LP];   // y = leaky(S), [b][n][l]
__device__ __half g_tok[(size_t)Bn*Ln*Dn];    // tokens fp16, [b][l][d]
__device__ __half g_npf[NPn*Dn];
__device__ __half g_img[Bn*Dn];
__device__ __half g_txt[Bn*Dn];
__device__ float  g_norm2[Bn*Ln];
__device__ float  g_qn  [NPn];
__device__ float  g_num [Bn*NPn];   // sum e*raw  (written by k_mma2 bx==0)
__device__ float  g_wn2 [Bn*NPn];   // ||w_hat||^2
__device__ float  g_ct  [Bn*Bn];
__device__ float  g_npc [Bn*NPn];
__device__ float  g_acc;
__device__ int    g_idx64;

__device__ __forceinline__ float lk(float x) { return x >= 0.f ? x : 0.1f * x; }
__device__ __forceinline__ float logsig(float x) {
    return fminf(x, 0.f) - log1pf(expf(-fabsf(x)));
}
__device__ __forceinline__ uint32_t s2u(const void* p) {
    uint32_t a;
    asm("{ .reg .u64 t; cvta.to.shared.u64 t, %1; cvt.u32.u64 %0, t; }" : "=r"(a) : "l"(p));
    return a;
}

// -------- cp.async K-major tile: ROWS x 64 halfs, SW128 swizzle ---------------
template<int ROWS>
__device__ __forceinline__ void cpa_tile(uint32_t dst, const __half* __restrict__ src,
                                         int row0, int row_lim, size_t stride, int k0, int tid) {
#pragma unroll
    for (int i = 0; i < ROWS / 32; i++) {
        int e = tid + (i << 8);
        int r = e >> 3, c = e & 7;
        int gr = row0 + r;
        int sz = 16;
        if (gr >= row_lim) { gr = row_lim - 1; sz = 0; }
        const void* gp = (const void*)(src + (size_t)gr * stride + k0 + (c << 3));
        uint32_t off = (uint32_t)((r << 7) + (c << 4));
        off ^= (off >> 3) & 0x70;
        asm volatile("cp.async.cg.shared.global [%0], [%1], 16, %2;"
                     :: "r"(dst + off), "l"(gp), "r"(sz) : "memory");
    }
}
// -------- cp.async MN-major tile: 64 rows(l) x 256 halfs(d), per-row XOR ------
__device__ __forceinline__ void cpa_tile_tr(uint32_t dst, const __half* __restrict__ src,
                                            int row0, int row_lim, size_t stride, int tid) {
#pragma unroll
    for (int i = 0; i < 8; i++) {
        int e = tid + (i << 8);
        int r = e >> 5, c = e & 31;
        int gr = row0 + r;
        int sz = 16;
        if (gr >= row_lim) { gr = row_lim - 1; sz = 0; }
        const void* gp = (const void*)(src + (size_t)gr * stride + (c << 3));
        uint32_t phys = (uint32_t)(r << 9) + ((uint32_t)(c << 4) ^ ((uint32_t)(r & 7) << 4));
        asm volatile("cp.async.cg.shared.global [%0], [%1], 16, %2;"
                     :: "r"(dst + phys), "l"(gp), "r"(sz) : "memory");
    }
}
#define CPA_COMMIT() asm volatile("cp.async.commit_group;" ::: "memory")

// ---------------- warp MMA (f16 acc) over one 128x256x64 SMEM chunk ------------
template<bool TRANSB>
__device__ __forceinline__ void mma_compute(uint32_t aBase, uint32_t bBase,
                                            int lane, int warpM, int warpN,
                                            uint32_t (&acc)[4][8][2]) {
#pragma unroll
    for (int ks = 0; ks < 4; ks++) {
        uint32_t a[4][4];
#pragma unroll
        for (int mb = 0; mb < 4; mb++) {
            int row = warpM * 64 + mb * 16 + (lane & 15);
            uint32_t byte = (uint32_t)(ks * 32 + ((lane >> 4) << 4));
            uint32_t off = (uint32_t)(row << 7) + byte;
            off ^= (off >> 3) & 0x70;
            asm volatile("ldmatrix.sync.aligned.m8n8.x4.shared.b16 {%0,%1,%2,%3}, [%4];"
                         : "=r"(a[mb][0]), "=r"(a[mb][1]), "=r"(a[mb][2]), "=r"(a[mb][3])
                         : "r"(aBase + off));
        }
        uint32_t b[8][2];
        if (!TRANSB) {
#pragma unroll
            for (int g = 0; g < 4; g++) {
                int row = warpN * 64 + g * 16 + (lane & 7) + ((lane >> 4) << 3);
                uint32_t byte = (uint32_t)(ks * 32 + ((lane & 8) ? 16 : 0));
                uint32_t off = (uint32_t)(row << 7) + byte;
                off ^= (off >> 3) & 0x70;
                uint32_t r0, r1, r2, r3;
                asm volatile("ldmatrix.sync.aligned.m8n8.x4.shared.b16 {%0,%1,%2,%3}, [%4];"
                             : "=r"(r0), "=r"(r1), "=r"(r2), "=r"(r3)
                             : "r"(bBase + off));
                b[g * 2][0] = r0; b[g * 2][1] = r1;
                b[g * 2 + 1][0] = r2; b[g * 2 + 1][1] = r3;
            }
        } else {
#pragma unroll
            for (int g = 0; g < 4; g++) {
                int row = ks * 16 + (lane & 15);                       // l row
                uint32_t bir = (uint32_t)(warpN * 128 + g * 32 + ((lane >> 4) << 4));
                uint32_t phys = (uint32_t)(row << 9) + (bir ^ ((uint32_t)(row & 7) << 4));
                uint32_t r0, r1, r2, r3;
                asm volatile("ldmatrix.sync.aligned.m8n8.x4.trans.shared.b16 {%0,%1,%2,%3}, [%4];"
                             : "=r"(r0), "=r"(r1), "=r"(r2), "=r"(r3)
                             : "r"(bBase + phys));
                b[g * 2][0] = r0; b[g * 2][1] = r1;
                b[g * 2 + 1][0] = r2; b[g * 2 + 1][1] = r3;
            }
        }
#pragma unroll
        for (int mb = 0; mb < 4; mb++)
#pragma unroll
            for (int nb = 0; nb < 8; nb++)
                asm volatile(
                    "mma.sync.aligned.m16n8k16.row.col.f16.f16.f16.f16 "
                    "{%0,%1},{%2,%3,%4,%5},{%6,%7},{%0,%1};"
                    : "+r"(acc[mb][nb][0]), "+r"(acc[mb][nb][1])
                    : "r"(a[mb][0]), "r"(a[mb][1]), "r"(a[mb][2]), "r"(a[mb][3]),
                      "r"(b[nb][0]), "r"(b[nb][1]));
    }
}

// ---------------- 2-stage pipelined mainloop (GEMM1) ---------------------------
__device__ __forceinline__ void mma_mainloop1(uint32_t su,
    const __half* A, int arow0, int alim, size_t astr,
    const __half* Bp, int blim, size_t bstr,
    int nK, int tid, int lane, int warpM, int warpN, uint32_t (&acc)[4][8][2]) {
    cpa_tile<128>(su, A, arow0, alim, astr, 0, tid);
    cpa_tile<256>(su + 16384, Bp, 0, blim, bstr, 0, tid);
    CPA_COMMIT();
    for (int it = 0; it < nK; ++it) {
        asm volatile("cp.async.wait_group 0;" ::: "memory");
        __syncthreads();
        if (it + 1 < nK) {
            uint32_t nb = su + (uint32_t)(((it + 1) & 1) * STAGE_B);
            cpa_tile<128>(nb, A, arow0, alim, astr, (it + 1) * 64, tid);
            cpa_tile<256>(nb + 16384, Bp, 0, blim, bstr, (it + 1) * 64, tid);
            CPA_COMMIT();
        }
        uint32_t base = su + (uint32_t)((it & 1) * STAGE_B);
        mma_compute<false>(base, base + 16384, lane, warpM, warpN, acc);
    }
    __syncthreads();
}

// ---------------- GEMM1: y = lk(tok @ npf^T), transposed out (+ npc/ct) --------
__global__ __launch_bounds__(256, 2) void k_mma1() {
    extern __shared__ char smem[];
    uint32_t su = s2u(smem);
    int tid = threadIdx.x, lane = tid & 31, wid = tid >> 5;
    int warpM = wid & 1, warpN = wid >> 1;
    int bx = blockIdx.x, by = blockIdx.y, bz = blockIdx.z;

    const __half *A, *Bp;
    float* CoutF = 0;
    size_t cstr = 0; int M, m0, n0, Nlim = 0, blim; bool isS;
    if (bz < Bn) {
        A = g_tok + (size_t)bz * Ln * Dn;
        Bp = g_npf + (size_t)bx * 256 * Dn;
        M = Ln; m0 = by * 128; n0 = bx * 256; blim = 256; isS = true;
    } else if (by == 0) {
        A = g_img; Bp = g_npf + (size_t)bx * 256 * Dn;
        CoutF = g_npc; cstr = NPn; M = Bn; m0 = 0; n0 = bx * 256;
        Nlim = NPn; blim = 256; isS = false;
    } else if (by == 1 && bx == 0) {
        A = g_img; Bp = g_txt;
        CoutF = g_ct; cstr = Bn; M = Bn; m0 = 0; n0 = 0;
        Nlim = Bn; blim = 128; isS = false;
    } else return;

    uint32_t acc[4][8][2];
#pragma unroll
    for (int i = 0; i < 4; i++)
#pragma unroll
        for (int j = 0; j < 8; j++) { acc[i][j][0] = 0u; acc[i][j][1] = 0u; }

    mma_mainloop1(su, A, m0, M, (size_t)Dn, Bp, blim, (size_t)Dn,
                  12, tid, lane, warpM, warpN, acc);

    if (isS) {
        __half* st = (__half*)smem;   // [256][132]
#pragma unroll
        for (int mb = 0; mb < 4; mb++) {
#pragma unroll
            for (int h = 0; h < 2; h++) {
                int ml = warpM * 64 + mb * 16 + (lane >> 2) + h * 8;
                int gr = m0 + ml;
                float ps = 0.f;
#pragma unroll
                for (int nb = 0; nb < 8; nb++) {
                    __half2 hv = *(__half2*)&acc[mb][nb][h];
                    float lx = lk(__half2float(hv.x));
                    float ly = lk(__half2float(hv.y));
                    ps += lx * lx + ly * ly;
                    int nl = warpN * 64 + nb * 8 + (lane & 3) * 2;
                    st[nl * 132 + ml]       = __float2half_rn(lx);
                    st[(nl + 1) * 132 + ml] = __float2half_rn(ly);
                }
                ps += __shfl_xor_sync(0xffffffffu, ps, 1);
                ps += __shfl_xor_sync(0xffffffffu, ps, 2);
                if ((lane & 3) == 0 && gr < M)
                    atomicAdd(&g_norm2[(size_t)bz * Ln + gr], ps);
            }
        }
        __syncthreads();
        // pad columns (l >= 577) may carry garbage y; e=fma(y,0,0)=0 kills them.
#pragma unroll 4
        for (int c = tid; c < 256 * 32; c += 256) {
            int r = c >> 5, ch = c & 31;
            int l = ch * 4;
            __half* dst = g_Yt + ((size_t)bz * NPn + n0 + r) * LP + m0 + l;
            *(uint2*)dst = *(const uint2*)(st + r * 132 + l);
        }
    } else {
#pragma unroll
        for (int mb = 0; mb < 4; mb++) {
#pragma unroll
            for (int h = 0; h < 2; h++) {
                int gr = m0 + warpM * 64 + mb * 16 + (lane >> 2) + h * 8;
                if (gr >= M) continue;
#pragma unroll
                for (int nb = 0; nb < 8; nb++) {
                    int gn = n0 + warpN * 64 + nb * 8 + (lane & 3) * 2;
                    if (gn < Nlim) {
                        __half2 hv = *(__half2*)&acc[mb][nb][h];
                        float2 v;
                        v.x = __half2float(hv.x); v.y = __half2float(hv.y);
                        *(float2*)(CoutF + (size_t)gr * cstr + gn) = v;
                    }
                }
            }
        }
    }
}

// ---------------- GEMM2: e built in-SMEM from y; w_hat = e @ tok ---------------
// Scales computed in-CTA from g_norm2 (no k_inv kernel, no g_ch/g_ca globals).
__global__ __launch_bounds__(256, 2) void k_mma2() {
    extern __shared__ char smem[];
    uint32_t su = s2u(smem);
    int tid = threadIdx.x, lane = tid & 31, wid = tid >> 5;
    int warpM = wid & 1, warpN = wid >> 1;
    int bx = blockIdx.x, by = blockIdx.y, bz = blockIdx.z;

    const __half* A  = g_Yt + (size_t)bz * NPn * LP;
    const __half* Bp = g_tok + (size_t)bz * Ln * Dn + bx * 256;  // pre-offset d0
    int m0 = by * 128;
    bool doNum = (bx == 0);

    // compute per-l packed (c, a): c = min(rsqrt(norm2)*4*log2e*1024, 60000) for
    // valid l, 0 for pad; a = 15360 (0x3c00<<?? = 0x7380 bits) valid, 0 pad.
    uint32_t* sch = (uint32_t*)(smem + 2 * STAGE_B);
    uint32_t* sca = sch + 320;
    const float* n2b = g_norm2 + (size_t)bz * Ln;
    for (int i = tid; i < 320; i += 256) {
        int l0 = 2 * i, l1 = 2 * i + 1;
        unsigned short c0 = 0, c1 = 0, a0 = 0, a1 = 0;
        if (l0 < Ln) {
            float cf = fminf(rsqrtf(fmaxf(n2b[l0], 1e-16f)) * 5909.2788f, 60000.f);
            c0 = __half_as_ushort(__float2half_rn(cf)); a0 = 0x7380;
        }
        if (l1 < Ln) {
            float cf = fminf(rsqrtf(fmaxf(n2b[l1], 1e-16f)) * 5909.2788f, 60000.f);
            c1 = __half_as_ushort(__float2half_rn(cf)); a1 = 0x7380;
        }
        sch[i] = (uint32_t)c0 | ((uint32_t)c1 << 16);
        sca[i] = (uint32_t)a0 | ((uint32_t)a1 << 16);
    }

    uint32_t acc[4][8][2];
#pragma unroll
    for (int i = 0; i < 4; i++)
#pragma unroll
        for (int j = 0; j < 8; j++) { acc[i][j][0] = 0u; acc[i][j][1] = 0u; }
    float nacc[4] = {0.f, 0.f, 0.f, 0.f};

    cpa_tile<128>(su, A, m0, NPn, (size_t)LP, 0, tid);
    cpa_tile_tr(su + 16384, Bp, 0, Ln, (size_t)Dn, tid);
    CPA_COMMIT();

    const int rR = tid >> 3, cC = tid & 7;
    for (int it = 0; it < 10; ++it) {
        asm volatile("cp.async.wait_group 0;" ::: "memory");
        __syncthreads();
        if (it + 1 < 10) {
            uint32_t nb = su + (uint32_t)(((it + 1) & 1) * STAGE_B);
            cpa_tile<128>(nb, A, m0, NPn, (size_t)LP, (it + 1) * 64, tid);
            cpa_tile_tr(nb + 16384, Bp, (it + 1) * 64, Ln, (size_t)Dn, tid);
            CPA_COMMIT();
        }
        // in-place e-transform of A tile (current buffer)
        char* bufc = smem + (it & 1) * STAGE_B;
        int sidx = it * 32 + cC * 4;
#pragma unroll
        for (int i = 0; i < 4; i++) {
            int rr = rR + (i << 5);
            uint32_t off = ((uint32_t)(rr << 7)) + ((uint32_t)(cC << 4));
            off ^= (off >> 3) & 0x70;
            uint4 y4 = *(uint4*)(bufc + off);
            uint32_t yv[4] = {y4.x, y4.y, y4.z, y4.w};
            uint32_t ev[4];
#pragma unroll
            for (int j = 0; j < 4; j++) {
                asm("fma.rn.f16x2 %0,%1,%2,%3;"
                    : "=r"(ev[j]) : "r"(yv[j]), "r"(sch[sidx + j]), "r"(sca[sidx + j]));
                if (doNum) {
                    __half2 yh = *(__half2*)&yv[j];
                    __half2 eh = *(__half2*)&ev[j];
                    float a0 = __half2float(yh.x), a1 = __half2float(yh.y);
                    float rw0 = (a0 < 0.f) ? 10.f * a0 : a0;
                    float rw1 = (a1 < 0.f) ? 10.f * a1 : a1;
                    nacc[i] += __half2float(eh.x) * rw0 + __half2float(eh.y) * rw1;
                }
            }
            uint4 e4; e4.x = ev[0]; e4.y = ev[1]; e4.z = ev[2]; e4.w = ev[3];
            *(uint4*)(bufc + off) = e4;
        }
        __syncthreads();
        uint32_t base = su + (uint32_t)((it & 1) * STAGE_B);
        mma_compute<true>(base, base + 16384, lane, warpM, warpN, acc);
    }
    __syncthreads();

    if (doNum) {
#pragma unroll
        for (int i = 0; i < 4; i++) {
            nacc[i] += __shfl_xor_sync(0xffffffffu, nacc[i], 1);
            nacc[i] += __shfl_xor_sync(0xffffffffu, nacc[i], 2);
            nacc[i] += __shfl_xor_sync(0xffffffffu, nacc[i], 4);
        }
        if ((lane & 7) == 0) {
#pragma unroll
            for (int i = 0; i < 4; i++)
                g_num[(size_t)bz * NPn + m0 + rR + (i << 5)] = nacc[i];
        }
    }

#pragma unroll
    for (int mb = 0; mb < 4; mb++) {
#pragma unroll
        for (int h = 0; h < 2; h++) {
            int gr = m0 + warpM * 64 + mb * 16 + (lane >> 2) + h * 8;
            float s = 0.f;
#pragma unroll
            for (int nb = 0; nb < 8; nb++) {
                __half2 hv = *(__half2*)&acc[mb][nb][h];
                float x = __half2float(hv.x), y = __half2float(hv.y);
                s += x * x + y * y;
            }
            s += __shfl_xor_sync(0xffffffffu, s, 1);
            s += __shfl_xor_sync(0xffffffffu, s, 2);
            if ((lane & 3) == 0)
                atomicAdd(&g_wn2[(size_t)bz * NPn + gr], s);
        }
    }
}

// ---------------- fused pre-pass: cvt_tok + cvt_np(+qnorm) + cvt_it + init -----
#define PRE_TOK 27696
#define PRE_NP  (PRE_TOK + NPn)
#define PRE_IT  (PRE_NP + 192)
#define PRE_END (PRE_IT + 512)
__global__ __launch_bounds__(256) void k_pre(const float* __restrict__ npf,
                                             const float* __restrict__ img,
                                             const float* __restrict__ txt,
                                             const float* __restrict__ tok,
                                             const int* __restrict__ idxr) {
    int bb = blockIdx.x, t = threadIdx.x;
    if (bb < PRE_TOK) {
        size_t i = ((size_t)bb * 256 + t) * 8;
        float4 v0 = *(const float4*)(tok + i);
        float4 v1 = *(const float4*)(tok + i + 4);
        __half h[8];
        h[0] = __float2half(v0.x); h[1] = __float2half(v0.y);
        h[2] = __float2half(v0.z); h[3] = __float2half(v0.w);
        h[4] = __float2half(v1.x); h[5] = __float2half(v1.y);
        h[6] = __float2half(v1.z); h[7] = __float2half(v1.w);
        *(uint4*)(g_tok + i) = *(uint4*)h;
    } else if (bb < PRE_NP) {
        int n = bb - PRE_TOK;
        const float* src = npf + (size_t)n * Dn;
        __half* dst = g_npf + (size_t)n * Dn;
        float s = 0.f;
#pragma unroll
        for (int i = 0; i < 3; i++) {
            float v = src[t + i * 256];
            dst[t + i * 256] = __float2half(v);
            s += v * v;
        }
        __shared__ float sh[256];
        sh[t] = s; __syncthreads();
        for (int o = 128; o > 0; o >>= 1) {
            if (t < o) sh[t] += sh[t + o];
            __syncthreads();
        }
        if (t == 0) g_qn[n] = sqrtf(sh[0]);
    } else if (bb < PRE_IT) {
        int i = ((bb - PRE_NP) * 256 + t) * 4;
        const float* src; __half* dst; int off;
        if (i < Bn * Dn)          { src = img; dst = g_img; off = i; }
        else if (i < 2 * Bn * Dn) { src = txt; dst = g_txt; off = i - Bn * Dn; }
        else return;
        float4 v = *(const float4*)(src + off);
        dst[off] = __float2half(v.x); dst[off + 1] = __float2half(v.y);
        dst[off + 2] = __float2half(v.z); dst[off + 3] = __float2half(v.w);
    } else {
        int gid = (bb - PRE_IT) * 256 + t;
        if (gid < Bn * NPn) g_wn2[gid] = 0.f;
        if (gid < Bn * Ln)  g_norm2[gid] = 0.f;
        if (gid == 0) {
            g_acc = 0.f;
            int any = 0;
            for (int i = 1; i < 1024; i += 2) any |= idxr[i];
            g_idx64 = (any == 0) ? 1 : 0;
        }
    }
}
__device__ __forceinline__ int get_idx(const int* __restrict__ r, int n) {
    return g_idx64 ? r[2 * n] : r[n];
}

// ---------------- merged loss reduction -----------------------------------------
__global__ void k_loss(const float* sc, const float* bi, const int* __restrict__ idxr) {
    int gid = blockIdx.x * 256 + threadIdx.x;
    float t = 0.f;
    if (gid < Bn * Bn) {
        int i = gid >> 7, j = gid & 127;
        float lg = g_ct[gid] * sc[0] + bi[0];
        float lab = (i == j) ? 1.f : -1.f;
        t = -logsig(lab * lg) * (1.0f / Bn);
    } else if (gid < Bn * Bn + Bn * NPn) {
        int g2 = gid - Bn * Bn;
        int b = g2 >> 10, n = g2 & 1023;
        float lab = (get_idx(idxr, n) == b) ? 1.f : -1.f;
        float lg = g_npc[g2] * sc[0] + bi[0];
        t = -logsig(lab * lg) * (1.0f / NPn);
    } else if (gid < Bn * Bn + 2 * Bn * NPn) {
        int g2 = gid - Bn * Bn - Bn * NPn;
        int b = g2 >> 10, n = g2 & 1023;
        float wn = sqrtf(g_wn2[g2]);
        float den = fmaxf(g_qn[n] * wn, EPSF);
        float sim = g_num[g2] / den;
        float lg = sim * sc[0] + bi[0];
        float lab = (get_idx(idxr, n) == b) ? 1.f : -1.f;
        t = -logsig(lab * lg) * (0.01f / NPn);
    }
    __shared__ float sh[256];
    sh[threadIdx.x] = t; __syncthreads();
    for (int o = 128; o > 0; o >>= 1) {
        if (threadIdx.x < o) sh[threadIdx.x] += sh[threadIdx.x + o];
        __syncthreads();
    }
    if (threadIdx.x == 0) atomicAdd(&g_acc, sh[0]);
}

__global__ void k_final(float* out) { out[0] = g_acc; }

// ---------------- launch ---------------------------------------------------------
extern "C" void kernel_launch(void* const* d_in, const int* in_sizes, int n_in,
                              void* d_out, int out_size) {
    const float* img = (const float*)d_in[0];
    const float* txt = (const float*)d_in[1];
    const float* sc  = (const float*)d_in[2];
    const float* bi  = (const float*)d_in[3];
    const float* npf = (const float*)d_in[4];
    const int*   idx = (const int*)d_in[5];
    const float* tok = (const float*)d_in[6];
    float* out = (float*)d_out;

    cudaFuncSetAttribute(k_mma1, cudaFuncAttributeMaxDynamicSharedMemorySize, SMEM_MMA1);
    cudaFuncSetAttribute(k_mma2, cudaFuncAttributeMaxDynamicSharedMemorySize, SMEM_MMA2);

    k_pre<<<PRE_END, 256>>>(npf, img, txt, tok, idx);
    k_mma1<<<dim3(4, 5, 129), 256, SMEM_MMA1>>>();
    k_mma2<<<dim3(3, 8, 128), 256, SMEM_MMA2>>>();
    k_loss<<<1088, 256>>>(sc, bi, idx);
    k_final<<<1, 1>>>(out);
}